// round 7
// baseline (speedup 1.0000x reference)
#include <cuda_runtime.h>
#include <cuda_fp16.h>
#include <math.h>
#include <stdint.h>

// ---------------------------------------------------------------------------
// DyHead-style MultiAttentionBlock. FP16 tensor-core mdconv + offconv,
// ldmatrix fragments, fp16 NHWC inputs, coalesced bilinear gather.
// B=2, C=256, levels H = {128, 64, 32}, GN groups = 16.
// ---------------------------------------------------------------------------

constexpr int BN = 2;
constexpr int C  = 256;

// ---- scratch layout (float units; X buffers are half, occupy half the slot) ----
constexpr size_t OFF_X0N   = 0;
constexpr size_t OFF_X1N   = OFF_X0N  + (size_t)BN*128*128*C;
constexpr size_t OFF_X2N   = OFF_X1N  + (size_t)BN*64*64*C;
constexpr size_t OFF_OFFB  = OFF_X2N  + (size_t)BN*32*32*C;
constexpr size_t OFF_YMID  = OFF_OFFB + (size_t)BN*128*128*27;
constexpr size_t OFF_YLOW  = OFF_YMID + (size_t)BN*C*128*128;
constexpr size_t OFF_YHIGH = OFF_YLOW + (size_t)BN*C*64*64;
constexpr size_t OFF_SUMF  = OFF_YHIGH+ (size_t)BN*C*64*64;
constexpr size_t OFF_W3MID = OFF_SUMF + (size_t)BN*C*128*128;   // half[9*256*256]
constexpr size_t OFF_W3LOW = OFF_W3MID + (size_t)9*256*256;
constexpr size_t OFF_W3HIGH= OFF_W3LOW + (size_t)9*256*256;
constexpr size_t OFF_W3OFF = OFF_W3HIGH+ (size_t)9*256*256;     // half[9*32*256]
constexpr size_t OFF_STAT  = OFF_W3OFF + (size_t)9*256*32;      // 3 sets x (512 sum + 512 sq)
constexpr size_t OFF_GNM   = OFF_STAT  + 3072;
constexpr size_t OFF_GNR   = OFF_GNM   + 96;
constexpr size_t OFF_SV    = OFF_GNR   + 96;
constexpr size_t OFF_P2    = OFF_SV    + 8;
constexpr size_t OFF_COEF  = OFF_P2    + 512;
constexpr size_t SCRATCH_TOTAL = OFF_COEF + 2048;

__device__ __align__(256) float g_scratch[SCRATCH_TOTAL];

// mdconv dynamic smem (bytes):
//   Ash : half [2][128*40]  at 0      (20480 B)
//   Bsh : half [2][256*40]  at 20480  (40960 B)
//   swt9: float[9*512]      at 61440  (18432 B)
//   sb9 : int  [9*512]      at 79872  (18432 B)
constexpr int MD_SMEM_BYTES = 98304;

__device__ __forceinline__ void mma_f16(float* d, const uint32_t* a, uint32_t b0, uint32_t b1) {
    asm volatile(
        "mma.sync.aligned.m16n8k16.row.col.f32.f16.f16.f32 "
        "{%0,%1,%2,%3},{%4,%5,%6,%7},{%8,%9},{%0,%1,%2,%3};\n"
        : "+f"(d[0]), "+f"(d[1]), "+f"(d[2]), "+f"(d[3])
        : "r"(a[0]), "r"(a[1]), "r"(a[2]), "r"(a[3]), "r"(b0), "r"(b1));
}

__device__ __forceinline__ void ldsm_x4(uint32_t* r, const half* p) {
    uint32_t a = (uint32_t)__cvta_generic_to_shared(p);
    asm volatile("ldmatrix.sync.aligned.m8n8.x4.shared.b16 {%0,%1,%2,%3}, [%4];"
        : "=r"(r[0]), "=r"(r[1]), "=r"(r[2]), "=r"(r[3]) : "r"(a));
}

__device__ __forceinline__ void cp_async16(uint32_t daddr, const void* src) {
    asm volatile("cp.async.cg.shared.global [%0], [%1], 16;\n" :: "r"(daddr), "l"(src));
}

// ---------------------------------------------------------------------------
// prep: w_mid -> half [k][o][c], w_off -> half [k][o32][c], zero stat buffers.
// ---------------------------------------------------------------------------
__global__ void prep_kernel(const float* __restrict__ w_mid, const float* __restrict__ w_off) {
    int bidx = blockIdx.x;
    if (bidx < 2304) {
        int idx = bidx * 256 + threadIdx.x;           // < 9*256*256
        int k = idx >> 16, o = (idx >> 8) & 255, c = idx & 255;
        ((half*)(g_scratch + OFF_W3MID))[idx] = __float2half(w_mid[(o * 256 + c) * 9 + k]);
    } else if (bidx < 2592) {
        int idx = (bidx - 2304) * 256 + threadIdx.x;  // < 9*32*256
        int k = idx >> 13, o = (idx >> 8) & 31, c = idx & 255;
        ((half*)(g_scratch + OFF_W3OFF))[idx] =
            __float2half(o < 27 ? w_off[(o * 256 + c) * 9 + k] : 0.f);
    } else {
        int idx = (bidx - 2592) * 256 + threadIdx.x;
        if (idx < 3072) g_scratch[OFF_STAT + idx] = 0.f;
    }
}

__global__ void reorder_w_half_kernel(const float* __restrict__ w, size_t out_o) {
    int idx = blockIdx.x * 256 + threadIdx.x;         // < 9*256*256
    int k = idx >> 16, o = (idx >> 8) & 255, c = idx & 255;
    ((half*)(g_scratch + out_o))[idx] = __float2half(w[(o * 256 + c) * 9 + k]);
}

// ---------------------------------------------------------------------------
// NCHW fp32 -> NHWC fp16 transpose.
// ---------------------------------------------------------------------------
__global__ void transpose_kernel(const float* __restrict__ in, size_t out_o, int HW) {
    __shared__ float t[32][33];
    int b = blockIdx.z;
    int hw0 = blockIdx.x * 32, c0 = blockIdx.y * 32;
    int tx = threadIdx.x, ty = threadIdx.y;  // 32 x 8
    #pragma unroll
    for (int i = 0; i < 32; i += 8)
        t[ty + i][tx] = in[((size_t)b * C + c0 + ty + i) * HW + hw0 + tx];
    __syncthreads();
    half* xh = (half*)(g_scratch + out_o);
    #pragma unroll
    for (int i = 0; i < 32; i += 8)
        xh[((size_t)b * HW + hw0 + ty + i) * C + c0 + tx] = __float2half(t[tx][ty + i]);
}

// ---------------------------------------------------------------------------
// Offset conv via fp16 MMA + ldmatrix. 3x3, 256 -> 27 (padded 32).
// Block: 128 px x 32 o, 256 threads (8 warps = 4M x 2N).
// ---------------------------------------------------------------------------
__global__ __launch_bounds__(256) void offconv_mma_kernel(
    size_t xn_o, int H, int W,
    const float* __restrict__ bias, size_t out_o)
{
    __shared__ half Ash[2][128 * 40];
    __shared__ half Bsh[2][32 * 40];

    int b = blockIdx.y, tile = blockIdx.x, tid = threadIdx.x;
    int lane = tid & 31, warp = tid >> 5;
    int warpM = warp >> 1, warpN = warp & 1;
    const half* xn = (const half*)(g_scratch + xn_o);
    const half* wh = (const half*)(g_scratch + OFF_W3OFF);

    float acc[2][2][4];
    #pragma unroll
    for (int mt = 0; mt < 2; ++mt)
        #pragma unroll
        for (int nt = 0; nt < 2; ++nt)
            #pragma unroll
            for (int r = 0; r < 4; ++r) acc[mt][nt][r] = 0.f;

    int tpx = tid >> 1, tseg = tid & 1;
    int p = tile * 128 + tpx;
    int ph = p / W, pw = p - ph * W;

    uint32_t bs_saddr = (uint32_t)__cvta_generic_to_shared(&Bsh[0][0]);

    uint4 gr[2];
    auto gather_ldg = [&](int s) {
        int k = s >> 3, c0 = (s & 7) << 5;
        int dy = k / 3 - 1, dx = k % 3 - 1;
        int y = ph + dy, x = pw + dx;
        bool valid = (y >= 0 && y < H && x >= 0 && x < W);
        const half* src = xn + ((size_t)(b * H + y) * W + x) * 256 + c0 + tseg * 16;
        #pragma unroll
        for (int i = 0; i < 2; ++i)
            gr[i] = valid ? *(const uint4*)(src + i * 8) : make_uint4(0, 0, 0, 0);
    };
    auto sts_a = [&](int buf) {
        half* dst = &Ash[buf][tpx * 40 + tseg * 16];
        *(uint4*)&dst[0] = gr[0];
        *(uint4*)&dst[8] = gr[1];
    };
    auto cpasync_b = [&](int s, int buf) {
        int k = s >> 3, c0 = (s & 7) << 5;
        if (tid < 128) {
            int o = tid >> 2, seg = tid & 3;
            cp_async16(bs_saddr + (uint32_t)(buf * 2560 + o * 80 + seg * 16),
                       wh + ((size_t)(k * 32 + o) << 8) + c0 + seg * 8);
        }
        asm volatile("cp.async.commit_group;\n");
    };

    gather_ldg(0);
    cpasync_b(0, 0);

    int lg = lane >> 3, lr = lane & 7;

    for (int s = 0; s < 72; ++s) {
        int cb = s & 1;
        sts_a(cb);
        if (s < 71) gather_ldg(s + 1);
        asm volatile("cp.async.wait_group 0;\n");
        __syncthreads();
        if (s < 71) cpasync_b(s + 1, cb ^ 1);

        const half* Ab = Ash[cb];
        const half* Bb = Bsh[cb];
        #pragma unroll
        for (int ks = 0; ks < 2; ++ks) {
            int kb = ks * 16 + (lg >> 1) * 8;
            uint32_t a[2][4];
            #pragma unroll
            for (int mt = 0; mt < 2; ++mt)
                ldsm_x4(a[mt], Ab + (warpM * 32 + mt * 16 + (lg & 1) * 8 + lr) * 40 + kb);
            uint32_t bf[4];
            ldsm_x4(bf, Bb + (warpN * 16 + (lg & 1) * 8 + lr) * 40 + kb);
            mma_f16(acc[0][0], a[0], bf[0], bf[2]);
            mma_f16(acc[1][0], a[1], bf[0], bf[2]);
            mma_f16(acc[0][1], a[0], bf[1], bf[3]);
            mma_f16(acc[1][1], a[1], bf[1], bf[3]);
        }
        __syncthreads();
    }

    // epilogue: [b][px][27]
    int HWl = H * W;
    int pxb = tile * 128 + warpM * 32 + (lane >> 2);
    #pragma unroll
    for (int nt = 0; nt < 2; ++nt) {
        int o = warpN * 16 + nt * 8 + 2 * (lane & 3);
        float bv0 = (o < 27) ? bias[o] : 0.f;
        float bv1 = (o + 1 < 27) ? bias[o + 1] : 0.f;
        #pragma unroll
        for (int mt = 0; mt < 2; ++mt) {
            #pragma unroll
            for (int rr = 0; rr < 2; ++rr) {
                int px = pxb + mt * 16 + rr * 8;
                float v0 = acc[mt][nt][rr * 2 + 0] + bv0;
                float v1 = acc[mt][nt][rr * 2 + 1] + bv1;
                size_t ob = out_o + ((size_t)b * HWl + px) * 27;
                if (o < 27) {
                    if (o >= 18) v0 = 1.f / (1.f + expf(-v0));
                    g_scratch[ob + o] = v0;
                }
                if (o + 1 < 27) {
                    if (o + 1 >= 18) v1 = 1.f / (1.f + expf(-v1));
                    g_scratch[ob + o + 1] = v1;
                }
            }
        }
    }
}

// ---------------------------------------------------------------------------
// Modulated deformable conv: fused bilinear gather (coalesced lanes) + FP16
// MMA with ldmatrix fragments, pipelined, fused per-(b,c) stats.
// Block: 128 px x 256 o, 512 threads (16 warps = 4M x 4N). 72 chunks of 32 c.
// ---------------------------------------------------------------------------
__global__ __launch_bounds__(512) void mdconv_mma_kernel(
    size_t xn_o, int Hi, int Wi,
    size_t off_o, int offH, int offW, int offmul,
    int stride, size_t w3_o,
    size_t y_o, int HWo, int Wo, size_t stat_o)
{
    extern __shared__ char smraw[];
    half*  Ash  = (half*)smraw;               // [2][128*40]
    half*  Bsh  = (half*)(smraw + 20480);     // [2][256*40]
    float* swt9 = (float*)(smraw + 61440);    // [9*512]
    int*   sb9  = (int*)(smraw + 79872);      // [9*512]

    int b = blockIdx.y, tile = blockIdx.x, tid = threadIdx.x;
    int lane = tid & 31, warp = tid >> 5;
    int warpM = warp & 3, warpN = warp >> 2;

    const half* xn = (const half*)(g_scratch + xn_o);
    const half* w3h = (const half*)(g_scratch + w3_o);

    // precompute gather tables for all 9 taps (9*128 px entries)
    for (int it = tid; it < 1152; it += 512) {
        int k = it >> 7, p = it & 127;
        int pg = tile * 128 + p;
        int h = pg / Wo, w = pg - h * Wo;
        size_t ob = off_o + ((size_t)(b * offH + h * offmul) * offW + w * offmul) * 27;
        float oy = g_scratch[ob + 2 * k];
        float ox = g_scratch[ob + 2 * k + 1];
        float m  = g_scratch[ob + 18 + k];
        float py  = (float)(h * stride - 1 + k / 3) + oy;
        float pxx = (float)(w * stride - 1 + k % 3) + ox;
        float fy = floorf(py), fx = floorf(pxx);
        int y0 = (int)fy, x0 = (int)fx;
        float wy = py - fy, wx = pxx - fx;
        int y1 = y0 + 1, x1 = x0 + 1;
        float vy0 = (y0 >= 0 && y0 < Hi) ? 1.f : 0.f;
        float vy1 = (y1 >= 0 && y1 < Hi) ? 1.f : 0.f;
        float vx0 = (x0 >= 0 && x0 < Wi) ? 1.f : 0.f;
        float vx1 = (x1 >= 0 && x1 < Wi) ? 1.f : 0.f;
        int y0c = min(max(y0, 0), Hi - 1), y1c = min(max(y1, 0), Hi - 1);
        int x0c = min(max(x0, 0), Wi - 1), x1c = min(max(x1, 0), Wi - 1);
        int kb = k * 512 + p;
        swt9[kb]       = (1.f - wy) * (1.f - wx) * m * vy0 * vx0;
        swt9[kb + 128] = (1.f - wy) * wx * m * vy0 * vx1;
        swt9[kb + 256] = wy * (1.f - wx) * m * vy1 * vx0;
        swt9[kb + 384] = wy * wx * m * vy1 * vx1;
        sb9[kb]       = ((b * Hi + y0c) * Wi + x0c) * 256;
        sb9[kb + 128] = ((b * Hi + y0c) * Wi + x1c) * 256;
        sb9[kb + 256] = ((b * Hi + y1c) * Wi + x0c) * 256;
        sb9[kb + 384] = ((b * Hi + y1c) * Wi + x1c) * 256;
    }
    __syncthreads();

    float acc[2][8][4];
    #pragma unroll
    for (int mt = 0; mt < 2; ++mt)
        #pragma unroll
        for (int nt = 0; nt < 8; ++nt)
            #pragma unroll
            for (int r = 0; r < 4; ++r) acc[mt][nt][r] = 0.f;

    // coalesced gather mapping: 4 consecutive lanes = 4 segments of one px
    int gpx = tid >> 2;   // 0..127
    int gcq = tid & 3;    // 16B segment

    uint32_t bs_saddr = (uint32_t)__cvta_generic_to_shared(Bsh);

    float gw0, gw1, gw2, gw3;
    uint4 gv[4];

    auto gather_ldg = [&](int s) {
        int kk = s >> 3, c0n = (s & 7) << 5;
        int kb = kk * 512 + gpx;
        gw0 = swt9[kb]; gw1 = swt9[kb + 128]; gw2 = swt9[kb + 256]; gw3 = swt9[kb + 384];
        int b00 = sb9[kb], b01 = sb9[kb + 128], b10 = sb9[kb + 256], b11 = sb9[kb + 384];
        int cofs = c0n + gcq * 8;
        gv[0] = *(const uint4*)(xn + b00 + cofs);
        gv[1] = *(const uint4*)(xn + b01 + cofs);
        gv[2] = *(const uint4*)(xn + b10 + cofs);
        gv[3] = *(const uint4*)(xn + b11 + cofs);
    };
    auto combine_sts = [&](int buf) {
        uint4 outv;
        half2* po = (half2*)&outv;
        #pragma unroll
        for (int j = 0; j < 4; ++j) {
            float2 f00 = __half22float2(((const half2*)&gv[0])[j]);
            float2 f01 = __half22float2(((const half2*)&gv[1])[j]);
            float2 f10 = __half22float2(((const half2*)&gv[2])[j]);
            float2 f11 = __half22float2(((const half2*)&gv[3])[j]);
            float rx = gw0 * f00.x + gw1 * f01.x + gw2 * f10.x + gw3 * f11.x;
            float ry = gw0 * f00.y + gw1 * f01.y + gw2 * f10.y + gw3 * f11.y;
            po[j] = __floats2half2_rn(rx, ry);
        }
        *(uint4*)&Ash[buf * 5120 + gpx * 40 + gcq * 8] = outv;
    };
    auto cpasync_b = [&](int s, int buf) {
        int kk = s >> 3, c0n = (s & 7) << 5;
        const half* wsrc = w3h + ((size_t)kk << 16) + c0n;   // [k][o][c], row = 256 halves
        #pragma unroll
        for (int it = 0; it < 2; ++it) {
            int e = it * 512 + tid;
            int o = e >> 2, seg = e & 3;
            cp_async16(bs_saddr + (uint32_t)(buf * 20480 + o * 80 + seg * 16),
                       wsrc + o * 256 + seg * 8);
        }
        asm volatile("cp.async.commit_group;\n");
    };

    gather_ldg(0);
    cpasync_b(0, 0);

    int lg = lane >> 3, lr = lane & 7;

    for (int s = 0; s < 72; ++s) {
        int cb = s & 1;
        combine_sts(cb);
        if (s < 71) gather_ldg(s + 1);
        asm volatile("cp.async.wait_group 0;\n");
        __syncthreads();
        if (s < 71) cpasync_b(s + 1, cb ^ 1);

        const half* Ab = Ash + cb * 5120;
        const half* Bb = Bsh + cb * 10240;
        #pragma unroll
        for (int ks = 0; ks < 2; ++ks) {
            int kb = ks * 16 + (lg >> 1) * 8;
            uint32_t a[2][4];
            #pragma unroll
            for (int mt = 0; mt < 2; ++mt)
                ldsm_x4(a[mt], Ab + (warpM * 32 + mt * 16 + (lg & 1) * 8 + lr) * 40 + kb);
            #pragma unroll
            for (int j = 0; j < 4; ++j) {
                uint32_t bf[4];
                ldsm_x4(bf, Bb + (warpN * 64 + j * 16 + (lg & 1) * 8 + lr) * 40 + kb);
                mma_f16(acc[0][2 * j],     a[0], bf[0], bf[2]);
                mma_f16(acc[1][2 * j],     a[1], bf[0], bf[2]);
                mma_f16(acc[0][2 * j + 1], a[0], bf[1], bf[3]);
                mma_f16(acc[1][2 * j + 1], a[1], bf[1], bf[3]);
            }
        }
        __syncthreads();
    }

    // epilogue: Y [b][o][HWo] + fused stats
    float* yp = g_scratch + y_o + (size_t)b * 256 * HWo;
    float* st_sum = g_scratch + stat_o + b * 256;
    float* st_sq  = g_scratch + stat_o + 512 + b * 256;
    int px0 = tile * 128 + warpM * 32 + (lane >> 2);
    #pragma unroll
    for (int nt = 0; nt < 8; ++nt) {
        int o = warpN * 64 + nt * 8 + 2 * (lane & 3);
        float s0 = 0.f, s1 = 0.f, q0 = 0.f, q1 = 0.f;
        #pragma unroll
        for (int mt = 0; mt < 2; ++mt) {
            int px = px0 + mt * 16;
            float v0 = acc[mt][nt][0], v1 = acc[mt][nt][1];
            float v2 = acc[mt][nt][2], v3 = acc[mt][nt][3];
            yp[(size_t)o * HWo + px]           = v0;
            yp[(size_t)(o + 1) * HWo + px]     = v1;
            yp[(size_t)o * HWo + px + 8]       = v2;
            yp[(size_t)(o + 1) * HWo + px + 8] = v3;
            s0 += v0 + v2; s1 += v1 + v3;
            q0 += v0 * v0 + v2 * v2; q1 += v1 * v1 + v3 * v3;
        }
        #pragma unroll
        for (int off = 16; off >= 4; off >>= 1) {
            s0 += __shfl_down_sync(0xffffffffu, s0, off);
            s1 += __shfl_down_sync(0xffffffffu, s1, off);
            q0 += __shfl_down_sync(0xffffffffu, q0, off);
            q1 += __shfl_down_sync(0xffffffffu, q1, off);
        }
        if (lane < 4) {
            atomicAdd(&st_sum[o], s0);
            atomicAdd(&st_sum[o + 1], s1);
            atomicAdd(&st_sq[o], q0);
            atomicAdd(&st_sq[o + 1], q1);
        }
    }
}

// ---------------------------------------------------------------------------
// GN finalize + scale-attn scalar (analytic pooled value).
// ---------------------------------------------------------------------------
__global__ void gn_finalize_kernel(
    size_t sum_o, size_t sq_o,
    const float* __restrict__ gamma, const float* __restrict__ beta,
    const float* __restrict__ w_sa, const float* __restrict__ b_sa,
    float inv_hw, float inv_cnt,
    size_t gnm_o, size_t gnr_o, size_t sv_o)
{
    int b = blockIdx.x, t = threadIdx.x;  // 256
    __shared__ float ss[256], qq[256], gm[16], gr[16], red[256];
    ss[t] = g_scratch[sum_o + b * 256 + t];
    qq[t] = g_scratch[sq_o + b * 256 + t];
    __syncthreads();
    if (t < 16) {
        float S = 0.f, Q = 0.f;
        #pragma unroll
        for (int j = 0; j < 16; ++j) { S += ss[t * 16 + j]; Q += qq[t * 16 + j]; }
        float mean = S * inv_cnt;
        float var = Q * inv_cnt - mean * mean;
        float r = rsqrtf(var + 1e-5f);
        gm[t] = mean; gr[t] = r;
        g_scratch[gnm_o + b * 16 + t] = mean;
        g_scratch[gnr_o + b * 16 + t] = r;
    }
    __syncthreads();
    int g = t >> 4;
    float p = gamma[t] * (ss[t] * inv_hw - gm[g]) * gr[g] + beta[t];
    red[t] = p * w_sa[t];
    __syncthreads();
    for (int off = 128; off; off >>= 1) {
        if (t < off) red[t] += red[t + off];
        __syncthreads();
    }
    if (t == 0) {
        float x = fmaxf(red[0] + b_sa[0], 0.f);
        g_scratch[sv_o + b] = fminf(x + 3.f, 6.f) * (1.f / 6.f);
    }
}

__global__ void zero_kernel(size_t o, int n) {
    int i = blockIdx.x * 256 + threadIdx.x;
    if (i < n) g_scratch[o + i] = 0.f;
}

// ---------------------------------------------------------------------------
// Combine branches + pooled sums.
// ---------------------------------------------------------------------------
__global__ void combine_kernel(
    size_t ymid_o, size_t ylow_o, size_t yhigh_o,
    int hasLow, int hasHigh, int W, int HW, int Hh, int Wh, float ry, float rx,
    size_t gnm_o, size_t gnr_o, size_t sv_o,
    const float* __restrict__ gw_mid, const float* __restrict__ gb_mid,
    const float* __restrict__ gw_low, const float* __restrict__ gb_low,
    const float* __restrict__ gw_high, const float* __restrict__ gb_high,
    float inv_n, size_t sumf_o, size_t p2_o)
{
    int b = blockIdx.z, c = blockIdx.y;
    int px = blockIdx.x * 256 + threadIdx.x;
    int g = c >> 4;
    int gi = b * 16 + g;
    size_t base = ((size_t)(b * 256 + c)) * HW;

    float v = g_scratch[sv_o + b] *
              (gw_mid[c] * (g_scratch[ymid_o + base + px] - g_scratch[gnm_o + gi]) * g_scratch[gnr_o + gi] + gb_mid[c]);
    if (hasLow)
        v += g_scratch[sv_o + 2 + b] *
             (gw_low[c] * (g_scratch[ylow_o + base + px] - g_scratch[gnm_o + 32 + gi]) * g_scratch[gnr_o + 32 + gi] + gb_low[c]);
    if (hasHigh) {
        int h = px / W, w = px - h * W;
        float sy = h * ry, sx = w * rx;
        int yl = (int)sy; int yh2 = min(yl + 1, Hh - 1);
        int xl = (int)sx; int xh = min(xl + 1, Wh - 1);
        float wy = sy - (float)yl, wx = sx - (float)xl;
        const float* hp = g_scratch + yhigh_o + ((size_t)(b * 256 + c)) * Hh * Wh;
        float t0 = hp[yl * Wh + xl] * (1.f - wx) + hp[yl * Wh + xh] * wx;
        float t1 = hp[yh2 * Wh + xl] * (1.f - wx) + hp[yh2 * Wh + xh] * wx;
        float raw = t0 * (1.f - wy) + t1 * wy;
        v += g_scratch[sv_o + 4 + b] *
             (gw_high[c] * (raw - g_scratch[gnm_o + 64 + gi]) * g_scratch[gnr_o + 64 + gi] + gb_high[c]);
    }
    v *= inv_n;
    g_scratch[sumf_o + base + px] = v;

    float r = v;
    #pragma unroll
    for (int o = 16; o; o >>= 1) r += __shfl_down_sync(0xffffffffu, r, o);
    __shared__ float wsum[8];
    if ((threadIdx.x & 31) == 0) wsum[threadIdx.x >> 5] = r;
    __syncthreads();
    if (threadIdx.x == 0) {
        float tt = 0.f;
        #pragma unroll
        for (int i = 0; i < 8; ++i) tt += wsum[i];
        atomicAdd(&g_scratch[p2_o + b * 256 + c], tt);
    }
}

// ---------------------------------------------------------------------------
// DyReLU coefficients.
// ---------------------------------------------------------------------------
__global__ void dycoef_kernel(size_t p2_o, float inv_hw,
    const float* __restrict__ w1, const float* __restrict__ b1,
    const float* __restrict__ w2, const float* __restrict__ b2,
    size_t coef_o)
{
    int b = blockIdx.x, t = threadIdx.x;  // 1024
    __shared__ float pm[256], hb[64];
    if (t < 256) pm[t] = g_scratch[p2_o + b * 256 + t] * inv_hw;
    __syncthreads();
    if (t < 64) {
        float a = b1[t];
        for (int cx = 0; cx < 256; ++cx) a += pm[cx] * w1[t * 256 + cx];
        hb[t] = fmaxf(a, 0.f);
    }
    __syncthreads();
    float a = b2[t];
    #pragma unroll
    for (int i = 0; i < 64; ++i) a += hb[i] * w2[t * 64 + i];
    float hs = fminf(fmaxf(a + 3.f, 0.f), 6.f) * (1.f / 6.f);
    g_scratch[coef_o + b * 1024 + t] = hs - 0.5f;
}

// ---------------------------------------------------------------------------
// Apply DyReLU, write final output.
// ---------------------------------------------------------------------------
__global__ void dyrelu_kernel(size_t sumf_o, size_t coef_o, int HW, float* __restrict__ outp, int CHW) {
    int idx = blockIdx.x * 256 + threadIdx.x;
    int b = idx / CHW;
    int c = (idx - b * CHW) / HW;
    const float* cf = g_scratch + coef_o + b * 1024;
    float x = g_scratch[sumf_o + idx];
    float a1 = cf[c] * 2.f + 1.f, bb1 = cf[256 + c];
    float a2 = cf[512 + c] * 2.f, bb2 = cf[768 + c];
    outp[idx] = fmaxf(x * a1 + bb1, x * a2 + bb2);
}

// ---------------------------------------------------------------------------
// Host orchestration
// ---------------------------------------------------------------------------
extern "C" void kernel_launch(void* const* d_in, const int* in_sizes, int n_in,
                              void* d_out, int out_size) {
    (void)in_sizes; (void)n_in; (void)out_size;
    const float* x0     = (const float*)d_in[0];
    const float* x1     = (const float*)d_in[1];
    const float* x2     = (const float*)d_in[2];
    const float* w_off  = (const float*)d_in[3];
    const float* b_off  = (const float*)d_in[4];
    const float* w_mid  = (const float*)d_in[5];
    const float* g_mid  = (const float*)d_in[6];
    const float* be_mid = (const float*)d_in[7];
    const float* w_low  = (const float*)d_in[8];
    const float* g_low  = (const float*)d_in[9];
    const float* be_low = (const float*)d_in[10];
    const float* w_high = (const float*)d_in[11];
    const float* g_high = (const float*)d_in[12];
    const float* be_high= (const float*)d_in[13];
    const float* w_sa   = (const float*)d_in[14];
    const float* b_sa   = (const float*)d_in[15];
    const float* w_dy1  = (const float*)d_in[16];
    const float* b_dy1  = (const float*)d_in[17];
    const float* w_dy2  = (const float*)d_in[18];
    const float* b_dy2  = (const float*)d_in[19];
    float* out = (float*)d_out;

    static bool attr_set = false;
    if (!attr_set) {
        cudaFuncSetAttribute(mdconv_mma_kernel,
                             cudaFuncAttributeMaxDynamicSharedMemorySize, MD_SMEM_BYTES);
        attr_set = true;
    }

    dim3 tblk(32, 8);
    const int Hs[3] = {128, 64, 32};
    const size_t xn_offs[3] = {OFF_X0N, OFF_X1N, OFF_X2N};

    // Launch order: slot 4 = mdconv mid L0 for the ncu window.
    transpose_kernel<<<dim3(128 * 128 / 32, 8, 2), tblk>>>(x0, OFF_X0N, 128 * 128);   // 1
    prep_kernel<<<2604, 256>>>(w_mid, w_off);                                          // 2
    offconv_mma_kernel<<<dim3(128 * 128 / 128, 2), 256>>>(OFF_X0N, 128, 128, b_off, OFF_OFFB); // 3
    mdconv_mma_kernel<<<dim3(128 * 128 / 128, 2), 512, MD_SMEM_BYTES>>>(               // 4
        OFF_X0N, 128, 128, OFF_OFFB, 128, 128, 1, 1, OFF_W3MID, OFF_YMID, 128 * 128, 128, OFF_STAT);
    reorder_w_half_kernel<<<2304, 256>>>(w_low,  OFF_W3LOW);                           // 5
    reorder_w_half_kernel<<<2304, 256>>>(w_high, OFF_W3HIGH);                          // 6
    transpose_kernel<<<dim3(64 * 64 / 32, 8, 2), tblk>>>(x1, OFF_X1N, 64 * 64);        // 7
    transpose_kernel<<<dim3(32 * 32 / 32, 8, 2), tblk>>>(x2, OFF_X2N, 32 * 32);        // 8

    size_t outoff = 0;
    for (int l = 0; l < 3; ++l) {
        int H = Hs[l], HW = H * H;
        int hasLow = (l > 0), hasHigh = (l < 2);
        int nbr = 1 + hasLow + hasHigh;
        int Hh = H / 2, HWh = Hh * Hh;

        if (l > 0) {
            zero_kernel<<<12, 256>>>(OFF_STAT, 3072);
            offconv_mma_kernel<<<dim3(HW / 128, 2), 256>>>(xn_offs[l], H, H, b_off, OFF_OFFB);
            mdconv_mma_kernel<<<dim3(HW / 128, 2), 512, MD_SMEM_BYTES>>>(
                xn_offs[l], H, H, OFF_OFFB, H, H, 1, 1, OFF_W3MID, OFF_YMID, HW, H, OFF_STAT);
        }
        gn_finalize_kernel<<<2, 256>>>(OFF_STAT, OFF_STAT + 512, g_mid, be_mid, w_sa, b_sa,
                                       1.f / HW, 1.f / (16.f * HW),
                                       OFF_GNM, OFF_GNR, OFF_SV);
        if (hasLow) {
            int Hi = Hs[l - 1];
            mdconv_mma_kernel<<<dim3(HW / 128, 2), 512, MD_SMEM_BYTES>>>(
                xn_offs[l - 1], Hi, Hi, OFF_OFFB, H, H, 1, 2, OFF_W3LOW, OFF_YLOW, HW, H,
                OFF_STAT + 1024);
            gn_finalize_kernel<<<2, 256>>>(OFF_STAT + 1024, OFF_STAT + 1536, g_low, be_low, w_sa, b_sa,
                                           1.f / HW, 1.f / (16.f * HW),
                                           OFF_GNM + 32, OFF_GNR + 32, OFF_SV + 2);
        }
        if (hasHigh) {
            mdconv_mma_kernel<<<dim3(HWh / 128, 2), 512, MD_SMEM_BYTES>>>(
                xn_offs[l + 1], Hh, Hh, OFF_OFFB, H, H, 2, 1, OFF_W3HIGH, OFF_YHIGH, HWh, Hh,
                OFF_STAT + 2048);
            gn_finalize_kernel<<<2, 256>>>(OFF_STAT + 2048, OFF_STAT + 2560, g_high, be_high, w_sa, b_sa,
                                           1.f / HWh, 1.f / (16.f * HWh),
                                           OFF_GNM + 64, OFF_GNR + 64, OFF_SV + 4);
        }

        zero_kernel<<<2, 256>>>(OFF_P2, 512);
        float ry = (float)(Hh - 1) / (float)(H - 1);
        combine_kernel<<<dim3(HW / 256, 256, 2), 256>>>(
            OFF_YMID, OFF_YLOW, OFF_YHIGH, hasLow, hasHigh,
            H, HW, Hh, Hh, ry, ry,
            OFF_GNM, OFF_GNR, OFF_SV,
            g_mid, be_mid, g_low, be_low, g_high, be_high,
            1.f / (float)nbr, OFF_SUMF, OFF_P2);

        dycoef_kernel<<<2, 1024>>>(OFF_P2, 1.f / HW, w_dy1, b_dy1, w_dy2, b_dy2, OFF_COEF);

        int total = 2 * 256 * HW;
        dyrelu_kernel<<<total / 256, 256>>>(OFF_SUMF, OFF_COEF, HW, out + outoff, 256 * HW);
        outoff += (size_t)total;
    }
}

// round 8
// speedup vs baseline: 1.2404x; 1.2404x over previous
#include <cuda_runtime.h>
#include <cuda_fp16.h>
#include <math.h>
#include <stdint.h>

// ---------------------------------------------------------------------------
// DyHead-style MultiAttentionBlock. FP16 tensor-core mdconv + offconv,
// ldmatrix fragments, fp16 NHWC inputs, coalesced bilinear gather,
// per-level tile size (PX=128 for L0, PX=64 for smaller levels).
// B=2, C=256, levels H = {128, 64, 32}, GN groups = 16.
// ---------------------------------------------------------------------------

constexpr int BN = 2;
constexpr int C  = 256;

// ---- scratch layout (float units; X buffers are half, occupy half the slot) ----
constexpr size_t OFF_X0N   = 0;
constexpr size_t OFF_X1N   = OFF_X0N  + (size_t)BN*128*128*C;
constexpr size_t OFF_X2N   = OFF_X1N  + (size_t)BN*64*64*C;
constexpr size_t OFF_OFFB  = OFF_X2N  + (size_t)BN*32*32*C;
constexpr size_t OFF_YMID  = OFF_OFFB + (size_t)BN*128*128*27;
constexpr size_t OFF_YLOW  = OFF_YMID + (size_t)BN*C*128*128;
constexpr size_t OFF_YHIGH = OFF_YLOW + (size_t)BN*C*64*64;
constexpr size_t OFF_SUMF  = OFF_YHIGH+ (size_t)BN*C*64*64;
constexpr size_t OFF_W3MID = OFF_SUMF + (size_t)BN*C*128*128;   // half[9*256*256]
constexpr size_t OFF_W3LOW = OFF_W3MID + (size_t)9*256*256;
constexpr size_t OFF_W3HIGH= OFF_W3LOW + (size_t)9*256*256;
constexpr size_t OFF_W3OFF = OFF_W3HIGH+ (size_t)9*256*256;     // half[9*32*256]
constexpr size_t OFF_STAT  = OFF_W3OFF + (size_t)9*256*32;      // 3 sets x (512 sum + 512 sq)
constexpr size_t OFF_GNM   = OFF_STAT  + 3072;
constexpr size_t OFF_GNR   = OFF_GNM   + 96;
constexpr size_t OFF_SV    = OFF_GNR   + 96;
constexpr size_t OFF_P2    = OFF_SV    + 8;
constexpr size_t OFF_COEF  = OFF_P2    + 512;
constexpr size_t SCRATCH_TOTAL = OFF_COEF + 2048;

__device__ __align__(256) float g_scratch[SCRATCH_TOTAL];

// mdconv dynamic smem bytes for tile PX: Ash 2*PX*40*2 + Bsh 40960 + swt/sb 2*144*PX
constexpr int md_smem_bytes(int PX) { return 40960 + 448 * PX; }

__device__ __forceinline__ void mma_f16(float* d, const uint32_t* a, uint32_t b0, uint32_t b1) {
    asm volatile(
        "mma.sync.aligned.m16n8k16.row.col.f32.f16.f16.f32 "
        "{%0,%1,%2,%3},{%4,%5,%6,%7},{%8,%9},{%0,%1,%2,%3};\n"
        : "+f"(d[0]), "+f"(d[1]), "+f"(d[2]), "+f"(d[3])
        : "r"(a[0]), "r"(a[1]), "r"(a[2]), "r"(a[3]), "r"(b0), "r"(b1));
}

__device__ __forceinline__ void ldsm_x4(uint32_t* r, const half* p) {
    uint32_t a = (uint32_t)__cvta_generic_to_shared(p);
    asm volatile("ldmatrix.sync.aligned.m8n8.x4.shared.b16 {%0,%1,%2,%3}, [%4];"
        : "=r"(r[0]), "=r"(r[1]), "=r"(r[2]), "=r"(r[3]) : "r"(a));
}

__device__ __forceinline__ void cp_async16(uint32_t daddr, const void* src) {
    asm volatile("cp.async.cg.shared.global [%0], [%1], 16;\n" :: "r"(daddr), "l"(src));
}

// ---------------------------------------------------------------------------
// prep: w_mid -> half [k][o][c], w_off -> half [k][o32][c], zero stat buffers.
// ---------------------------------------------------------------------------
__global__ void prep_kernel(const float* __restrict__ w_mid, const float* __restrict__ w_off) {
    int bidx = blockIdx.x;
    if (bidx < 2304) {
        int idx = bidx * 256 + threadIdx.x;           // < 9*256*256
        int k = idx >> 16, o = (idx >> 8) & 255, c = idx & 255;
        ((half*)(g_scratch + OFF_W3MID))[idx] = __float2half(w_mid[(o * 256 + c) * 9 + k]);
    } else if (bidx < 2592) {
        int idx = (bidx - 2304) * 256 + threadIdx.x;  // < 9*32*256
        int k = idx >> 13, o = (idx >> 8) & 31, c = idx & 255;
        ((half*)(g_scratch + OFF_W3OFF))[idx] =
            __float2half(o < 27 ? w_off[(o * 256 + c) * 9 + k] : 0.f);
    } else {
        int idx = (bidx - 2592) * 256 + threadIdx.x;
        if (idx < 3072) g_scratch[OFF_STAT + idx] = 0.f;
    }
}

__global__ void reorder_w_half_kernel(const float* __restrict__ w, size_t out_o) {
    int idx = blockIdx.x * 256 + threadIdx.x;         // < 9*256*256
    int k = idx >> 16, o = (idx >> 8) & 255, c = idx & 255;
    ((half*)(g_scratch + out_o))[idx] = __float2half(w[(o * 256 + c) * 9 + k]);
}

// ---------------------------------------------------------------------------
// NCHW fp32 -> NHWC fp16 transpose.
// ---------------------------------------------------------------------------
__global__ void transpose_kernel(const float* __restrict__ in, size_t out_o, int HW) {
    __shared__ float t[32][33];
    int b = blockIdx.z;
    int hw0 = blockIdx.x * 32, c0 = blockIdx.y * 32;
    int tx = threadIdx.x, ty = threadIdx.y;  // 32 x 8
    #pragma unroll
    for (int i = 0; i < 32; i += 8)
        t[ty + i][tx] = in[((size_t)b * C + c0 + ty + i) * HW + hw0 + tx];
    __syncthreads();
    half* xh = (half*)(g_scratch + out_o);
    #pragma unroll
    for (int i = 0; i < 32; i += 8)
        xh[((size_t)b * HW + hw0 + ty + i) * C + c0 + tx] = __float2half(t[tx][ty + i]);
}

// ---------------------------------------------------------------------------
// Offset conv via fp16 MMA + ldmatrix. 3x3, 256 -> 27 (padded 32).
// Block: 128 px x 32 o, 256 threads (8 warps = 4M x 2N).
// ---------------------------------------------------------------------------
__global__ __launch_bounds__(256) void offconv_mma_kernel(
    size_t xn_o, int H, int W,
    const float* __restrict__ bias, size_t out_o)
{
    __shared__ half Ash[2][128 * 40];
    __shared__ half Bsh[2][32 * 40];

    int b = blockIdx.y, tile = blockIdx.x, tid = threadIdx.x;
    int lane = tid & 31, warp = tid >> 5;
    int warpM = warp >> 1, warpN = warp & 1;
    const half* xn = (const half*)(g_scratch + xn_o);
    const half* wh = (const half*)(g_scratch + OFF_W3OFF);

    float acc[2][2][4];
    #pragma unroll
    for (int mt = 0; mt < 2; ++mt)
        #pragma unroll
        for (int nt = 0; nt < 2; ++nt)
            #pragma unroll
            for (int r = 0; r < 4; ++r) acc[mt][nt][r] = 0.f;

    int tpx = tid >> 1, tseg = tid & 1;
    int p = tile * 128 + tpx;
    int ph = p / W, pw = p - ph * W;

    uint32_t bs_saddr = (uint32_t)__cvta_generic_to_shared(&Bsh[0][0]);

    uint4 gr[2];
    auto gather_ldg = [&](int s) {
        int k = s >> 3, c0 = (s & 7) << 5;
        int dy = k / 3 - 1, dx = k % 3 - 1;
        int y = ph + dy, x = pw + dx;
        bool valid = (y >= 0 && y < H && x >= 0 && x < W);
        const half* src = xn + ((size_t)(b * H + y) * W + x) * 256 + c0 + tseg * 16;
        #pragma unroll
        for (int i = 0; i < 2; ++i)
            gr[i] = valid ? *(const uint4*)(src + i * 8) : make_uint4(0, 0, 0, 0);
    };
    auto sts_a = [&](int buf) {
        half* dst = &Ash[buf][tpx * 40 + tseg * 16];
        *(uint4*)&dst[0] = gr[0];
        *(uint4*)&dst[8] = gr[1];
    };
    auto cpasync_b = [&](int s, int buf) {
        int k = s >> 3, c0 = (s & 7) << 5;
        if (tid < 128) {
            int o = tid >> 2, seg = tid & 3;
            cp_async16(bs_saddr + (uint32_t)(buf * 2560 + o * 80 + seg * 16),
                       wh + ((size_t)(k * 32 + o) << 8) + c0 + seg * 8);
        }
        asm volatile("cp.async.commit_group;\n");
    };

    gather_ldg(0);
    cpasync_b(0, 0);

    int lg = lane >> 3, lr = lane & 7;

    for (int s = 0; s < 72; ++s) {
        int cb = s & 1;
        sts_a(cb);
        if (s < 71) gather_ldg(s + 1);
        asm volatile("cp.async.wait_group 0;\n");
        __syncthreads();
        if (s < 71) cpasync_b(s + 1, cb ^ 1);

        const half* Ab = Ash[cb];
        const half* Bb = Bsh[cb];
        #pragma unroll
        for (int ks = 0; ks < 2; ++ks) {
            int kb = ks * 16 + (lg >> 1) * 8;
            uint32_t a[2][4];
            #pragma unroll
            for (int mt = 0; mt < 2; ++mt)
                ldsm_x4(a[mt], Ab + (warpM * 32 + mt * 16 + (lg & 1) * 8 + lr) * 40 + kb);
            uint32_t bf[4];
            ldsm_x4(bf, Bb + (warpN * 16 + (lg & 1) * 8 + lr) * 40 + kb);
            mma_f16(acc[0][0], a[0], bf[0], bf[2]);
            mma_f16(acc[1][0], a[1], bf[0], bf[2]);
            mma_f16(acc[0][1], a[0], bf[1], bf[3]);
            mma_f16(acc[1][1], a[1], bf[1], bf[3]);
        }
        __syncthreads();
    }

    // epilogue: [b][px][27]
    int HWl = H * W;
    int pxb = tile * 128 + warpM * 32 + (lane >> 2);
    #pragma unroll
    for (int nt = 0; nt < 2; ++nt) {
        int o = warpN * 16 + nt * 8 + 2 * (lane & 3);
        float bv0 = (o < 27) ? bias[o] : 0.f;
        float bv1 = (o + 1 < 27) ? bias[o + 1] : 0.f;
        #pragma unroll
        for (int mt = 0; mt < 2; ++mt) {
            #pragma unroll
            for (int rr = 0; rr < 2; ++rr) {
                int px = pxb + mt * 16 + rr * 8;
                float v0 = acc[mt][nt][rr * 2 + 0] + bv0;
                float v1 = acc[mt][nt][rr * 2 + 1] + bv1;
                size_t ob = out_o + ((size_t)b * HWl + px) * 27;
                if (o < 27) {
                    if (o >= 18) v0 = 1.f / (1.f + expf(-v0));
                    g_scratch[ob + o] = v0;
                }
                if (o + 1 < 27) {
                    if (o + 1 >= 18) v1 = 1.f / (1.f + expf(-v1));
                    g_scratch[ob + o + 1] = v1;
                }
            }
        }
    }
}

// ---------------------------------------------------------------------------
// Modulated deformable conv: fused bilinear gather (coalesced lanes) + FP16
// MMA with ldmatrix fragments, pipelined, fused per-(b,c) stats.
// Template PX px per block, PX*4 threads (PX/32 M-warps x 4 N-warps).
// ---------------------------------------------------------------------------
template<int PX>
__global__ __launch_bounds__(PX * 4) void mdconv_mma_kernel(
    size_t xn_o, int Hi, int Wi,
    size_t off_o, int offH, int offW, int offmul,
    int stride, size_t w3_o,
    size_t y_o, int HWo, int Wo, size_t stat_o)
{
    constexpr int THREADS = PX * 4;
    constexpr int WM = PX / 32;
    constexpr int ASH_HALF = PX * 40;          // per buffer
    constexpr int ASH_BYTES = 2 * ASH_HALF * 2;

    extern __shared__ char smraw[];
    half*  Ash  = (half*)smraw;                         // [2][PX*40]
    half*  Bsh  = (half*)(smraw + ASH_BYTES);           // [2][256*40]
    float* swt9 = (float*)(smraw + ASH_BYTES + 40960);  // [9][4*PX]
    int*   sb9  = (int*)(smraw + ASH_BYTES + 40960 + 144 * PX);

    int b = blockIdx.y, tile = blockIdx.x, tid = threadIdx.x;
    int lane = tid & 31, warp = tid >> 5;
    int warpM = warp % WM, warpN = warp / WM;

    const half* xn = (const half*)(g_scratch + xn_o);
    const half* w3h = (const half*)(g_scratch + w3_o);

    // precompute gather tables for all 9 taps (9*PX entries)
    for (int it = tid; it < 9 * PX; it += THREADS) {
        int k = it / PX, p = it % PX;
        int pg = tile * PX + p;
        int h = pg / Wo, w = pg - h * Wo;
        size_t ob = off_o + ((size_t)(b * offH + h * offmul) * offW + w * offmul) * 27;
        float oy = g_scratch[ob + 2 * k];
        float ox = g_scratch[ob + 2 * k + 1];
        float m  = g_scratch[ob + 18 + k];
        float py  = (float)(h * stride - 1 + k / 3) + oy;
        float pxx = (float)(w * stride - 1 + k % 3) + ox;
        float fy = floorf(py), fx = floorf(pxx);
        int y0 = (int)fy, x0 = (int)fx;
        float wy = py - fy, wx = pxx - fx;
        int y1 = y0 + 1, x1 = x0 + 1;
        float vy0 = (y0 >= 0 && y0 < Hi) ? 1.f : 0.f;
        float vy1 = (y1 >= 0 && y1 < Hi) ? 1.f : 0.f;
        float vx0 = (x0 >= 0 && x0 < Wi) ? 1.f : 0.f;
        float vx1 = (x1 >= 0 && x1 < Wi) ? 1.f : 0.f;
        int y0c = min(max(y0, 0), Hi - 1), y1c = min(max(y1, 0), Hi - 1);
        int x0c = min(max(x0, 0), Wi - 1), x1c = min(max(x1, 0), Wi - 1);
        int kb = k * 4 * PX + p;
        swt9[kb]          = (1.f - wy) * (1.f - wx) * m * vy0 * vx0;
        swt9[kb + PX]     = (1.f - wy) * wx * m * vy0 * vx1;
        swt9[kb + 2 * PX] = wy * (1.f - wx) * m * vy1 * vx0;
        swt9[kb + 3 * PX] = wy * wx * m * vy1 * vx1;
        sb9[kb]          = ((b * Hi + y0c) * Wi + x0c) * 256;
        sb9[kb + PX]     = ((b * Hi + y0c) * Wi + x1c) * 256;
        sb9[kb + 2 * PX] = ((b * Hi + y1c) * Wi + x0c) * 256;
        sb9[kb + 3 * PX] = ((b * Hi + y1c) * Wi + x1c) * 256;
    }
    __syncthreads();

    float acc[2][8][4];
    #pragma unroll
    for (int mt = 0; mt < 2; ++mt)
        #pragma unroll
        for (int nt = 0; nt < 8; ++nt)
            #pragma unroll
            for (int r = 0; r < 4; ++r) acc[mt][nt][r] = 0.f;

    // coalesced gather mapping: 4 consecutive lanes = 4 segments of one px
    int gpx = tid >> 2;   // 0..PX-1
    int gcq = tid & 3;    // 16B segment

    uint32_t bs_saddr = (uint32_t)__cvta_generic_to_shared(Bsh);

    float gw0, gw1, gw2, gw3;
    uint4 gv[4];

    auto gather_ldg = [&](int s) {
        int kk = s >> 3, c0n = (s & 7) << 5;
        int kb = kk * 4 * PX + gpx;
        gw0 = swt9[kb]; gw1 = swt9[kb + PX]; gw2 = swt9[kb + 2 * PX]; gw3 = swt9[kb + 3 * PX];
        int b00 = sb9[kb], b01 = sb9[kb + PX], b10 = sb9[kb + 2 * PX], b11 = sb9[kb + 3 * PX];
        int cofs = c0n + gcq * 8;
        gv[0] = *(const uint4*)(xn + b00 + cofs);
        gv[1] = *(const uint4*)(xn + b01 + cofs);
        gv[2] = *(const uint4*)(xn + b10 + cofs);
        gv[3] = *(const uint4*)(xn + b11 + cofs);
    };
    auto combine_sts = [&](int buf) {
        uint4 outv;
        half2* po = (half2*)&outv;
        #pragma unroll
        for (int j = 0; j < 4; ++j) {
            float2 f00 = __half22float2(((const half2*)&gv[0])[j]);
            float2 f01 = __half22float2(((const half2*)&gv[1])[j]);
            float2 f10 = __half22float2(((const half2*)&gv[2])[j]);
            float2 f11 = __half22float2(((const half2*)&gv[3])[j]);
            float rx = gw0 * f00.x + gw1 * f01.x + gw2 * f10.x + gw3 * f11.x;
            float ry = gw0 * f00.y + gw1 * f01.y + gw2 * f10.y + gw3 * f11.y;
            po[j] = __floats2half2_rn(rx, ry);
        }
        *(uint4*)&Ash[buf * ASH_HALF + gpx * 40 + gcq * 8] = outv;
    };
    auto cpasync_b = [&](int s, int buf) {
        int kk = s >> 3, c0n = (s & 7) << 5;
        const half* wsrc = w3h + ((size_t)kk << 16) + c0n;   // [k][o][c], row = 256 halves
        #pragma unroll
        for (int it = 0; it < 1024 / THREADS; ++it) {
            int e = it * THREADS + tid;
            int o = e >> 2, seg = e & 3;
            cp_async16(bs_saddr + (uint32_t)(buf * 20480 + o * 80 + seg * 16),
                       wsrc + o * 256 + seg * 8);
        }
        asm volatile("cp.async.commit_group;\n");
    };

    gather_ldg(0);
    cpasync_b(0, 0);

    int lg = lane >> 3, lr = lane & 7;

    for (int s = 0; s < 72; ++s) {
        int cb = s & 1;
        combine_sts(cb);
        if (s < 71) gather_ldg(s + 1);
        asm volatile("cp.async.wait_group 0;\n");
        __syncthreads();
        if (s < 71) cpasync_b(s + 1, cb ^ 1);

        const half* Ab = Ash + cb * ASH_HALF;
        const half* Bb = Bsh + cb * 10240;
        #pragma unroll
        for (int ks = 0; ks < 2; ++ks) {
            int kb = ks * 16 + (lg >> 1) * 8;
            uint32_t a[2][4];
            #pragma unroll
            for (int mt = 0; mt < 2; ++mt)
                ldsm_x4(a[mt], Ab + (warpM * 32 + mt * 16 + (lg & 1) * 8 + lr) * 40 + kb);
            #pragma unroll
            for (int j = 0; j < 4; ++j) {
                uint32_t bf[4];
                ldsm_x4(bf, Bb + (warpN * 64 + j * 16 + (lg & 1) * 8 + lr) * 40 + kb);
                mma_f16(acc[0][2 * j],     a[0], bf[0], bf[2]);
                mma_f16(acc[1][2 * j],     a[1], bf[0], bf[2]);
                mma_f16(acc[0][2 * j + 1], a[0], bf[1], bf[3]);
                mma_f16(acc[1][2 * j + 1], a[1], bf[1], bf[3]);
            }
        }
        __syncthreads();
    }

    // epilogue: Y [b][o][HWo] + fused stats
    float* yp = g_scratch + y_o + (size_t)b * 256 * HWo;
    float* st_sum = g_scratch + stat_o + b * 256;
    float* st_sq  = g_scratch + stat_o + 512 + b * 256;
    int px0 = tile * PX + warpM * 32 + (lane >> 2);
    #pragma unroll
    for (int nt = 0; nt < 8; ++nt) {
        int o = warpN * 64 + nt * 8 + 2 * (lane & 3);
        float s0 = 0.f, s1 = 0.f, q0 = 0.f, q1 = 0.f;
        #pragma unroll
        for (int mt = 0; mt < 2; ++mt) {
            int px = px0 + mt * 16;
            float v0 = acc[mt][nt][0], v1 = acc[mt][nt][1];
            float v2 = acc[mt][nt][2], v3 = acc[mt][nt][3];
            yp[(size_t)o * HWo + px]           = v0;
            yp[(size_t)(o + 1) * HWo + px]     = v1;
            yp[(size_t)o * HWo + px + 8]       = v2;
            yp[(size_t)(o + 1) * HWo + px + 8] = v3;
            s0 += v0 + v2; s1 += v1 + v3;
            q0 += v0 * v0 + v2 * v2; q1 += v1 * v1 + v3 * v3;
        }
        #pragma unroll
        for (int off = 16; off >= 4; off >>= 1) {
            s0 += __shfl_down_sync(0xffffffffu, s0, off);
            s1 += __shfl_down_sync(0xffffffffu, s1, off);
            q0 += __shfl_down_sync(0xffffffffu, q0, off);
            q1 += __shfl_down_sync(0xffffffffu, q1, off);
        }
        if (lane < 4) {
            atomicAdd(&st_sum[o], s0);
            atomicAdd(&st_sum[o + 1], s1);
            atomicAdd(&st_sq[o], q0);
            atomicAdd(&st_sq[o + 1], q1);
        }
    }
}

// ---------------------------------------------------------------------------
// GN finalize + scale-attn scalar (analytic pooled value).
// ---------------------------------------------------------------------------
__global__ void gn_finalize_kernel(
    size_t sum_o, size_t sq_o,
    const float* __restrict__ gamma, const float* __restrict__ beta,
    const float* __restrict__ w_sa, const float* __restrict__ b_sa,
    float inv_hw, float inv_cnt,
    size_t gnm_o, size_t gnr_o, size_t sv_o)
{
    int b = blockIdx.x, t = threadIdx.x;  // 256
    __shared__ float ss[256], qq[256], gm[16], gr[16], red[256];
    ss[t] = g_scratch[sum_o + b * 256 + t];
    qq[t] = g_scratch[sq_o + b * 256 + t];
    __syncthreads();
    if (t < 16) {
        float S = 0.f, Q = 0.f;
        #pragma unroll
        for (int j = 0; j < 16; ++j) { S += ss[t * 16 + j]; Q += qq[t * 16 + j]; }
        float mean = S * inv_cnt;
        float var = Q * inv_cnt - mean * mean;
        float r = rsqrtf(var + 1e-5f);
        gm[t] = mean; gr[t] = r;
        g_scratch[gnm_o + b * 16 + t] = mean;
        g_scratch[gnr_o + b * 16 + t] = r;
    }
    __syncthreads();
    int g = t >> 4;
    float p = gamma[t] * (ss[t] * inv_hw - gm[g]) * gr[g] + beta[t];
    red[t] = p * w_sa[t];
    __syncthreads();
    for (int off = 128; off; off >>= 1) {
        if (t < off) red[t] += red[t + off];
        __syncthreads();
    }
    if (t == 0) {
        float x = fmaxf(red[0] + b_sa[0], 0.f);
        g_scratch[sv_o + b] = fminf(x + 3.f, 6.f) * (1.f / 6.f);
    }
}

__global__ void zero_kernel(size_t o, int n) {
    int i = blockIdx.x * 256 + threadIdx.x;
    if (i < n) g_scratch[o + i] = 0.f;
}

// ---------------------------------------------------------------------------
// Combine branches + pooled sums.
// ---------------------------------------------------------------------------
__global__ void combine_kernel(
    size_t ymid_o, size_t ylow_o, size_t yhigh_o,
    int hasLow, int hasHigh, int W, int HW, int Hh, int Wh, float ry, float rx,
    size_t gnm_o, size_t gnr_o, size_t sv_o,
    const float* __restrict__ gw_mid, const float* __restrict__ gb_mid,
    const float* __restrict__ gw_low, const float* __restrict__ gb_low,
    const float* __restrict__ gw_high, const float* __restrict__ gb_high,
    float inv_n, size_t sumf_o, size_t p2_o)
{
    int b = blockIdx.z, c = blockIdx.y;
    int px = blockIdx.x * 256 + threadIdx.x;
    int g = c >> 4;
    int gi = b * 16 + g;
    size_t base = ((size_t)(b * 256 + c)) * HW;

    float v = g_scratch[sv_o + b] *
              (gw_mid[c] * (g_scratch[ymid_o + base + px] - g_scratch[gnm_o + gi]) * g_scratch[gnr_o + gi] + gb_mid[c]);
    if (hasLow)
        v += g_scratch[sv_o + 2 + b] *
             (gw_low[c] * (g_scratch[ylow_o + base + px] - g_scratch[gnm_o + 32 + gi]) * g_scratch[gnr_o + 32 + gi] + gb_low[c]);
    if (hasHigh) {
        int h = px / W, w = px - h * W;
        float sy = h * ry, sx = w * rx;
        int yl = (int)sy; int yh2 = min(yl + 1, Hh - 1);
        int xl = (int)sx; int xh = min(xl + 1, Wh - 1);
        float wy = sy - (float)yl, wx = sx - (float)xl;
        const float* hp = g_scratch + yhigh_o + ((size_t)(b * 256 + c)) * Hh * Wh;
        float t0 = hp[yl * Wh + xl] * (1.f - wx) + hp[yl * Wh + xh] * wx;
        float t1 = hp[yh2 * Wh + xl] * (1.f - wx) + hp[yh2 * Wh + xh] * wx;
        float raw = t0 * (1.f - wy) + t1 * wy;
        v += g_scratch[sv_o + 4 + b] *
             (gw_high[c] * (raw - g_scratch[gnm_o + 64 + gi]) * g_scratch[gnr_o + 64 + gi] + gb_high[c]);
    }
    v *= inv_n;
    g_scratch[sumf_o + base + px] = v;

    float r = v;
    #pragma unroll
    for (int o = 16; o; o >>= 1) r += __shfl_down_sync(0xffffffffu, r, o);
    __shared__ float wsum[8];
    if ((threadIdx.x & 31) == 0) wsum[threadIdx.x >> 5] = r;
    __syncthreads();
    if (threadIdx.x == 0) {
        float tt = 0.f;
        #pragma unroll
        for (int i = 0; i < 8; ++i) tt += wsum[i];
        atomicAdd(&g_scratch[p2_o + b * 256 + c], tt);
    }
}

// ---------------------------------------------------------------------------
// DyReLU coefficients.
// ---------------------------------------------------------------------------
__global__ void dycoef_kernel(size_t p2_o, float inv_hw,
    const float* __restrict__ w1, const float* __restrict__ b1,
    const float* __restrict__ w2, const float* __restrict__ b2,
    size_t coef_o)
{
    int b = blockIdx.x, t = threadIdx.x;  // 1024
    __shared__ float pm[256], hb[64];
    if (t < 256) pm[t] = g_scratch[p2_o + b * 256 + t] * inv_hw;
    __syncthreads();
    if (t < 64) {
        float a = b1[t];
        for (int cx = 0; cx < 256; ++cx) a += pm[cx] * w1[t * 256 + cx];
        hb[t] = fmaxf(a, 0.f);
    }
    __syncthreads();
    float a = b2[t];
    #pragma unroll
    for (int i = 0; i < 64; ++i) a += hb[i] * w2[t * 64 + i];
    float hs = fminf(fmaxf(a + 3.f, 0.f), 6.f) * (1.f / 6.f);
    g_scratch[coef_o + b * 1024 + t] = hs - 0.5f;
}

// ---------------------------------------------------------------------------
// Apply DyReLU, write final output.
// ---------------------------------------------------------------------------
__global__ void dyrelu_kernel(size_t sumf_o, size_t coef_o, int HW, float* __restrict__ outp, int CHW) {
    int idx = blockIdx.x * 256 + threadIdx.x;
    int b = idx / CHW;
    int c = (idx - b * CHW) / HW;
    const float* cf = g_scratch + coef_o + b * 1024;
    float x = g_scratch[sumf_o + idx];
    float a1 = cf[c] * 2.f + 1.f, bb1 = cf[256 + c];
    float a2 = cf[512 + c] * 2.f, bb2 = cf[768 + c];
    outp[idx] = fmaxf(x * a1 + bb1, x * a2 + bb2);
}

// ---------------------------------------------------------------------------
// Host orchestration
// ---------------------------------------------------------------------------
extern "C" void kernel_launch(void* const* d_in, const int* in_sizes, int n_in,
                              void* d_out, int out_size) {
    (void)in_sizes; (void)n_in; (void)out_size;
    const float* x0     = (const float*)d_in[0];
    const float* x1     = (const float*)d_in[1];
    const float* x2     = (const float*)d_in[2];
    const float* w_off  = (const float*)d_in[3];
    const float* b_off  = (const float*)d_in[4];
    const float* w_mid  = (const float*)d_in[5];
    const float* g_mid  = (const float*)d_in[6];
    const float* be_mid = (const float*)d_in[7];
    const float* w_low  = (const float*)d_in[8];
    const float* g_low  = (const float*)d_in[9];
    const float* be_low = (const float*)d_in[10];
    const float* w_high = (const float*)d_in[11];
    const float* g_high = (const float*)d_in[12];
    const float* be_high= (const float*)d_in[13];
    const float* w_sa   = (const float*)d_in[14];
    const float* b_sa   = (const float*)d_in[15];
    const float* w_dy1  = (const float*)d_in[16];
    const float* b_dy1  = (const float*)d_in[17];
    const float* w_dy2  = (const float*)d_in[18];
    const float* b_dy2  = (const float*)d_in[19];
    float* out = (float*)d_out;

    static bool attr_set = false;
    if (!attr_set) {
        cudaFuncSetAttribute(mdconv_mma_kernel<128>,
                             cudaFuncAttributeMaxDynamicSharedMemorySize, md_smem_bytes(128));
        cudaFuncSetAttribute(mdconv_mma_kernel<64>,
                             cudaFuncAttributeMaxDynamicSharedMemorySize, md_smem_bytes(64));
        attr_set = true;
    }

    dim3 tblk(32, 8);
    const int Hs[3] = {128, 64, 32};
    const size_t xn_offs[3] = {OFF_X0N, OFF_X1N, OFF_X2N};

    // Launch order: slot 4 = mdconv mid L0 (PX=128) for the ncu window.
    transpose_kernel<<<dim3(128 * 128 / 32, 8, 2), tblk>>>(x0, OFF_X0N, 128 * 128);   // 1
    prep_kernel<<<2604, 256>>>(w_mid, w_off);                                          // 2
    offconv_mma_kernel<<<dim3(128 * 128 / 128, 2), 256>>>(OFF_X0N, 128, 128, b_off, OFF_OFFB); // 3
    mdconv_mma_kernel<128><<<dim3(128 * 128 / 128, 2), 512, md_smem_bytes(128)>>>(     // 4
        OFF_X0N, 128, 128, OFF_OFFB, 128, 128, 1, 1, OFF_W3MID, OFF_YMID, 128 * 128, 128, OFF_STAT);
    reorder_w_half_kernel<<<2304, 256>>>(w_low,  OFF_W3LOW);                           // 5
    reorder_w_half_kernel<<<2304, 256>>>(w_high, OFF_W3HIGH);                          // 6
    transpose_kernel<<<dim3(64 * 64 / 32, 8, 2), tblk>>>(x1, OFF_X1N, 64 * 64);        // 7
    transpose_kernel<<<dim3(32 * 32 / 32, 8, 2), tblk>>>(x2, OFF_X2N, 32 * 32);        // 8

    size_t outoff = 0;
    for (int l = 0; l < 3; ++l) {
        int H = Hs[l], HW = H * H;
        int hasLow = (l > 0), hasHigh = (l < 2);
        int nbr = 1 + hasLow + hasHigh;
        int Hh = H / 2, HWh = Hh * Hh;

        if (l > 0) {
            zero_kernel<<<12, 256>>>(OFF_STAT, 3072);
            offconv_mma_kernel<<<dim3(HW / 128, 2), 256>>>(xn_offs[l], H, H, b_off, OFF_OFFB);
            mdconv_mma_kernel<64><<<dim3(HW / 64, 2), 256, md_smem_bytes(64)>>>(
                xn_offs[l], H, H, OFF_OFFB, H, H, 1, 1, OFF_W3MID, OFF_YMID, HW, H, OFF_STAT);
        }
        gn_finalize_kernel<<<2, 256>>>(OFF_STAT, OFF_STAT + 512, g_mid, be_mid, w_sa, b_sa,
                                       1.f / HW, 1.f / (16.f * HW),
                                       OFF_GNM, OFF_GNR, OFF_SV);
        if (hasLow) {
            int Hi = Hs[l - 1];
            mdconv_mma_kernel<64><<<dim3(HW / 64, 2), 256, md_smem_bytes(64)>>>(
                xn_offs[l - 1], Hi, Hi, OFF_OFFB, H, H, 1, 2, OFF_W3LOW, OFF_YLOW, HW, H,
                OFF_STAT + 1024);
            gn_finalize_kernel<<<2, 256>>>(OFF_STAT + 1024, OFF_STAT + 1536, g_low, be_low, w_sa, b_sa,
                                           1.f / HW, 1.f / (16.f * HW),
                                           OFF_GNM + 32, OFF_GNR + 32, OFF_SV + 2);
        }
        if (hasHigh) {
            mdconv_mma_kernel<64><<<dim3(HWh / 64, 2), 256, md_smem_bytes(64)>>>(
                xn_offs[l + 1], Hh, Hh, OFF_OFFB, H, H, 2, 1, OFF_W3HIGH, OFF_YHIGH, HWh, Hh,
                OFF_STAT + 2048);
            gn_finalize_kernel<<<2, 256>>>(OFF_STAT + 2048, OFF_STAT + 2560, g_high, be_high, w_sa, b_sa,
                                           1.f / HWh, 1.f / (16.f * HWh),
                                           OFF_GNM + 64, OFF_GNR + 64, OFF_SV + 4);
        }

        zero_kernel<<<2, 256>>>(OFF_P2, 512);
        float ry = (float)(Hh - 1) / (float)(H - 1);
        combine_kernel<<<dim3(HW / 256, 256, 2), 256>>>(
            OFF_YMID, OFF_YLOW, OFF_YHIGH, hasLow, hasHigh,
            H, HW, Hh, Hh, ry, ry,
            OFF_GNM, OFF_GNR, OFF_SV,
            g_mid, be_mid, g_low, be_low, g_high, be_high,
            1.f / (float)nbr, OFF_SUMF, OFF_P2);

        dycoef_kernel<<<2, 1024>>>(OFF_P2, 1.f / HW, w_dy1, b_dy1, w_dy2, b_dy2, OFF_COEF);

        int total = 2 * 256 * HW;
        dyrelu_kernel<<<total / 256, 256>>>(OFF_SUMF, OFF_COEF, HW, out + outoff, 256 * HW);
        outoff += (size_t)total;
    }
}

// round 9
// speedup vs baseline: 1.2700x; 1.0239x over previous
#include <cuda_runtime.h>
#include <cuda_fp16.h>
#include <math.h>
#include <stdint.h>

// ---------------------------------------------------------------------------
// DyHead-style MultiAttentionBlock. FP16 tensor-core mdconv + offconv,
// ldmatrix fragments, fp16 NHWC inputs, coalesced gather, PX=64 / 2 blk/SM.
// B=2, C=256, levels H = {128, 64, 32}, GN groups = 16.
// ---------------------------------------------------------------------------

constexpr int BN = 2;
constexpr int C  = 256;

// ---- scratch layout (float units; X buffers are half, occupy half the slot) ----
constexpr size_t OFF_X0N   = 0;
constexpr size_t OFF_X1N   = OFF_X0N  + (size_t)BN*128*128*C;
constexpr size_t OFF_X2N   = OFF_X1N  + (size_t)BN*64*64*C;
constexpr size_t OFF_OFFB  = OFF_X2N  + (size_t)BN*32*32*C;
constexpr size_t OFF_YMID  = OFF_OFFB + (size_t)BN*128*128*27;
constexpr size_t OFF_YLOW  = OFF_YMID + (size_t)BN*C*128*128;
constexpr size_t OFF_YHIGH = OFF_YLOW + (size_t)BN*C*64*64;
constexpr size_t OFF_SUMF  = OFF_YHIGH+ (size_t)BN*C*64*64;
constexpr size_t OFF_W3MID = OFF_SUMF + (size_t)BN*C*128*128;   // half[9*256*256]
constexpr size_t OFF_W3LOW = OFF_W3MID + (size_t)9*256*256;
constexpr size_t OFF_W3HIGH= OFF_W3LOW + (size_t)9*256*256;
constexpr size_t OFF_W3OFF = OFF_W3HIGH+ (size_t)9*256*256;     // half[9*32*256]
constexpr size_t OFF_STAT  = OFF_W3OFF + (size_t)9*256*32;      // 3 sets x (512 sum + 512 sq)
constexpr size_t OFF_GNM   = OFF_STAT  + 3072;
constexpr size_t OFF_GNR   = OFF_GNM   + 96;
constexpr size_t OFF_SV    = OFF_GNR   + 96;
constexpr size_t OFF_P2    = OFF_SV    + 8;
constexpr size_t OFF_COEF  = OFF_P2    + 512;
constexpr size_t SCRATCH_TOTAL = OFF_COEF + 2048;

__device__ __align__(256) float g_scratch[SCRATCH_TOTAL];

// mdconv (PX=64) dynamic smem layout (bytes):
//   Ash : half [2][64*40]   at 0      (10240)
//   Bsh : half [2][256*40]  at 10240  (40960)
//   swt9: float[9][256]     at 51200  (9216)
//   sb9 : int  [9][256]     at 60416  (9216)
constexpr int MD_SMEM_BYTES = 69632;

__device__ __forceinline__ void mma_f16(float* d, const uint32_t* a, uint32_t b0, uint32_t b1) {
    asm volatile(
        "mma.sync.aligned.m16n8k16.row.col.f32.f16.f16.f32 "
        "{%0,%1,%2,%3},{%4,%5,%6,%7},{%8,%9},{%0,%1,%2,%3};\n"
        : "+f"(d[0]), "+f"(d[1]), "+f"(d[2]), "+f"(d[3])
        : "r"(a[0]), "r"(a[1]), "r"(a[2]), "r"(a[3]), "r"(b0), "r"(b1));
}

__device__ __forceinline__ void ldsm_x4(uint32_t* r, const half* p) {
    uint32_t a = (uint32_t)__cvta_generic_to_shared(p);
    asm volatile("ldmatrix.sync.aligned.m8n8.x4.shared.b16 {%0,%1,%2,%3}, [%4];"
        : "=r"(r[0]), "=r"(r[1]), "=r"(r[2]), "=r"(r[3]) : "r"(a));
}

__device__ __forceinline__ void cp_async16(uint32_t daddr, const void* src) {
    asm volatile("cp.async.cg.shared.global [%0], [%1], 16;\n" :: "r"(daddr), "l"(src));
}

// ---------------------------------------------------------------------------
// prep: w_mid -> half [k][o][c], w_off -> half [k][o32][c], zero stat buffers.
// ---------------------------------------------------------------------------
__global__ void prep_kernel(const float* __restrict__ w_mid, const float* __restrict__ w_off) {
    int bidx = blockIdx.x;
    if (bidx < 2304) {
        int idx = bidx * 256 + threadIdx.x;           // < 9*256*256
        int k = idx >> 16, o = (idx >> 8) & 255, c = idx & 255;
        ((half*)(g_scratch + OFF_W3MID))[idx] = __float2half(w_mid[(o * 256 + c) * 9 + k]);
    } else if (bidx < 2592) {
        int idx = (bidx - 2304) * 256 + threadIdx.x;  // < 9*32*256
        int k = idx >> 13, o = (idx >> 8) & 31, c = idx & 255;
        ((half*)(g_scratch + OFF_W3OFF))[idx] =
            __float2half(o < 27 ? w_off[(o * 256 + c) * 9 + k] : 0.f);
    } else {
        int idx = (bidx - 2592) * 256 + threadIdx.x;
        if (idx < 3584) g_scratch[OFF_STAT + idx] = 0.f;   // stats + P2
    }
}

__global__ void reorder_w_half_kernel(const float* __restrict__ w, size_t out_o) {
    int idx = blockIdx.x * 256 + threadIdx.x;         // < 9*256*256
    int k = idx >> 16, o = (idx >> 8) & 255, c = idx & 255;
    ((half*)(g_scratch + out_o))[idx] = __float2half(w[(o * 256 + c) * 9 + k]);
}

// ---------------------------------------------------------------------------
// NCHW fp32 -> NHWC fp16 transpose.
// ---------------------------------------------------------------------------
__global__ void transpose_kernel(const float* __restrict__ in, size_t out_o, int HW) {
    __shared__ float t[32][33];
    int b = blockIdx.z;
    int hw0 = blockIdx.x * 32, c0 = blockIdx.y * 32;
    int tx = threadIdx.x, ty = threadIdx.y;  // 32 x 8
    #pragma unroll
    for (int i = 0; i < 32; i += 8)
        t[ty + i][tx] = in[((size_t)b * C + c0 + ty + i) * HW + hw0 + tx];
    __syncthreads();
    half* xh = (half*)(g_scratch + out_o);
    #pragma unroll
    for (int i = 0; i < 32; i += 8)
        xh[((size_t)b * HW + hw0 + ty + i) * C + c0 + tx] = __float2half(t[tx][ty + i]);
}

// ---------------------------------------------------------------------------
// Offset conv via fp16 MMA + ldmatrix. 3x3, 256 -> 27 (padded 32).
// Block: 128 px x 32 o, 256 threads (8 warps = 4M x 2N).
// ---------------------------------------------------------------------------
__global__ __launch_bounds__(256) void offconv_mma_kernel(
    size_t xn_o, int H, int W,
    const float* __restrict__ bias, size_t out_o)
{
    __shared__ half Ash[2][128 * 40];
    __shared__ half Bsh[2][32 * 40];

    int b = blockIdx.y, tile = blockIdx.x, tid = threadIdx.x;
    int lane = tid & 31, warp = tid >> 5;
    int warpM = warp >> 1, warpN = warp & 1;
    const half* xn = (const half*)(g_scratch + xn_o);
    const half* wh = (const half*)(g_scratch + OFF_W3OFF);

    float acc[2][2][4];
    #pragma unroll
    for (int mt = 0; mt < 2; ++mt)
        #pragma unroll
        for (int nt = 0; nt < 2; ++nt)
            #pragma unroll
            for (int r = 0; r < 4; ++r) acc[mt][nt][r] = 0.f;

    int tpx = tid >> 1, tseg = tid & 1;
    int p = tile * 128 + tpx;
    int ph = p / W, pw = p - ph * W;

    uint32_t bs_saddr = (uint32_t)__cvta_generic_to_shared(&Bsh[0][0]);

    uint4 gr[2];
    auto gather_ldg = [&](int s) {
        int k = s >> 3, c0 = (s & 7) << 5;
        int dy = k / 3 - 1, dx = k % 3 - 1;
        int y = ph + dy, x = pw + dx;
        bool valid = (y >= 0 && y < H && x >= 0 && x < W);
        const half* src = xn + ((size_t)(b * H + y) * W + x) * 256 + c0 + tseg * 16;
        #pragma unroll
        for (int i = 0; i < 2; ++i)
            gr[i] = valid ? *(const uint4*)(src + i * 8) : make_uint4(0, 0, 0, 0);
    };
    auto sts_a = [&](int buf) {
        half* dst = &Ash[buf][tpx * 40 + tseg * 16];
        *(uint4*)&dst[0] = gr[0];
        *(uint4*)&dst[8] = gr[1];
    };
    auto cpasync_b = [&](int s, int buf) {
        int k = s >> 3, c0 = (s & 7) << 5;
        if (tid < 128) {
            int o = tid >> 2, seg = tid & 3;
            cp_async16(bs_saddr + (uint32_t)(buf * 2560 + o * 80 + seg * 16),
                       wh + ((size_t)(k * 32 + o) << 8) + c0 + seg * 8);
        }
        asm volatile("cp.async.commit_group;\n");
    };

    gather_ldg(0);
    cpasync_b(0, 0);

    int lg = lane >> 3, lr = lane & 7;

    for (int s = 0; s < 72; ++s) {
        int cb = s & 1;
        sts_a(cb);
        if (s < 71) gather_ldg(s + 1);
        asm volatile("cp.async.wait_group 0;\n");
        __syncthreads();
        if (s < 71) cpasync_b(s + 1, cb ^ 1);

        const half* Ab = Ash[cb];
        const half* Bb = Bsh[cb];
        #pragma unroll
        for (int ks = 0; ks < 2; ++ks) {
            int kb = ks * 16 + (lg >> 1) * 8;
            uint32_t a[2][4];
            #pragma unroll
            for (int mt = 0; mt < 2; ++mt)
                ldsm_x4(a[mt], Ab + (warpM * 32 + mt * 16 + (lg & 1) * 8 + lr) * 40 + kb);
            uint32_t bf[4];
            ldsm_x4(bf, Bb + (warpN * 16 + (lg & 1) * 8 + lr) * 40 + kb);
            mma_f16(acc[0][0], a[0], bf[0], bf[2]);
            mma_f16(acc[1][0], a[1], bf[0], bf[2]);
            mma_f16(acc[0][1], a[0], bf[1], bf[3]);
            mma_f16(acc[1][1], a[1], bf[1], bf[3]);
        }
        __syncthreads();
    }

    // epilogue: [b][px][27]
    int HWl = H * W;
    int pxb = tile * 128 + warpM * 32 + (lane >> 2);
    #pragma unroll
    for (int nt = 0; nt < 2; ++nt) {
        int o = warpN * 16 + nt * 8 + 2 * (lane & 3);
        float bv0 = (o < 27) ? bias[o] : 0.f;
        float bv1 = (o + 1 < 27) ? bias[o + 1] : 0.f;
        #pragma unroll
        for (int mt = 0; mt < 2; ++mt) {
            #pragma unroll
            for (int rr = 0; rr < 2; ++rr) {
                int px = pxb + mt * 16 + rr * 8;
                float v0 = acc[mt][nt][rr * 2 + 0] + bv0;
                float v1 = acc[mt][nt][rr * 2 + 1] + bv1;
                size_t ob = out_o + ((size_t)b * HWl + px) * 27;
                if (o < 27) {
                    if (o >= 18) v0 = 1.f / (1.f + expf(-v0));
                    g_scratch[ob + o] = v0;
                }
                if (o + 1 < 27) {
                    if (o + 1 >= 18) v1 = 1.f / (1.f + expf(-v1));
                    g_scratch[ob + o + 1] = v1;
                }
            }
        }
    }
}

// ---------------------------------------------------------------------------
// Modulated deformable conv: fused bilinear gather (coalesced lanes) + FP16
// MMA, pipelined, per-k register-resident gather table, fused stats.
// Block: 64 px x 256 o, 256 threads (8 warps = 2M x 4N), 2 blocks/SM.
// ---------------------------------------------------------------------------
__global__ __launch_bounds__(256, 2) void mdconv_mma_kernel(
    size_t xn_o, int Hi, int Wi,
    size_t off_o, int offH, int offW, int offmul,
    int stride, size_t w3_o,
    size_t y_o, int HWo, int Wo, size_t stat_o)
{
    constexpr int PX = 64;
    constexpr int ASH_HALF = PX * 40;

    extern __shared__ char smraw[];
    half*  Ash  = (half*)smraw;               // [2][64*40]
    half*  Bsh  = (half*)(smraw + 10240);     // [2][256*40]
    float* swt9 = (float*)(smraw + 51200);    // [9][4*64]
    int*   sb9  = (int*)(smraw + 60416);      // [9][4*64]

    int b = blockIdx.y, tile = blockIdx.x, tid = threadIdx.x;
    int lane = tid & 31, warp = tid >> 5;
    int warpM = warp & 1, warpN = warp >> 1;

    const half* xn = (const half*)(g_scratch + xn_o);
    const half* w3h = (const half*)(g_scratch + w3_o);

    // precompute gather tables for all 9 taps
    for (int it = tid; it < 9 * PX; it += 256) {
        int k = it >> 6, p = it & 63;
        int pg = tile * PX + p;
        int h = pg / Wo, w = pg - h * Wo;
        size_t ob = off_o + ((size_t)(b * offH + h * offmul) * offW + w * offmul) * 27;
        float oy = g_scratch[ob + 2 * k];
        float ox = g_scratch[ob + 2 * k + 1];
        float m  = g_scratch[ob + 18 + k];
        float py  = (float)(h * stride - 1 + k / 3) + oy;
        float pxx = (float)(w * stride - 1 + k % 3) + ox;
        float fy = floorf(py), fx = floorf(pxx);
        int y0 = (int)fy, x0 = (int)fx;
        float wy = py - fy, wx = pxx - fx;
        int y1 = y0 + 1, x1 = x0 + 1;
        float vy0 = (y0 >= 0 && y0 < Hi) ? 1.f : 0.f;
        float vy1 = (y1 >= 0 && y1 < Hi) ? 1.f : 0.f;
        float vx0 = (x0 >= 0 && x0 < Wi) ? 1.f : 0.f;
        float vx1 = (x1 >= 0 && x1 < Wi) ? 1.f : 0.f;
        int y0c = min(max(y0, 0), Hi - 1), y1c = min(max(y1, 0), Hi - 1);
        int x0c = min(max(x0, 0), Wi - 1), x1c = min(max(x1, 0), Wi - 1);
        int kb = k * 4 * PX + p;
        swt9[kb]          = (1.f - wy) * (1.f - wx) * m * vy0 * vx0;
        swt9[kb + PX]     = (1.f - wy) * wx * m * vy0 * vx1;
        swt9[kb + 2 * PX] = wy * (1.f - wx) * m * vy1 * vx0;
        swt9[kb + 3 * PX] = wy * wx * m * vy1 * vx1;
        sb9[kb]          = ((b * Hi + y0c) * Wi + x0c) * 256;
        sb9[kb + PX]     = ((b * Hi + y0c) * Wi + x1c) * 256;
        sb9[kb + 2 * PX] = ((b * Hi + y1c) * Wi + x0c) * 256;
        sb9[kb + 3 * PX] = ((b * Hi + y1c) * Wi + x1c) * 256;
    }
    __syncthreads();

    float acc[2][8][4];
    #pragma unroll
    for (int mt = 0; mt < 2; ++mt)
        #pragma unroll
        for (int nt = 0; nt < 8; ++nt)
            #pragma unroll
            for (int r = 0; r < 4; ++r) acc[mt][nt][r] = 0.f;

    // coalesced gather mapping: 4 consecutive lanes = 4 segments of one px
    int gpx = tid >> 2;   // 0..63
    int gcq = tid & 3;    // 16B segment

    uint32_t bs_saddr = (uint32_t)__cvta_generic_to_shared(Bsh);

    // per-k register-resident table (reloaded every 8 chunks)
    float gw0, gw1, gw2, gw3;
    int b00, b01, b10, b11;
    uint4 gv[4];

    auto load_table = [&](int kk) {
        int kb = kk * 4 * PX + gpx;
        gw0 = swt9[kb]; gw1 = swt9[kb + PX]; gw2 = swt9[kb + 2 * PX]; gw3 = swt9[kb + 3 * PX];
        b00 = sb9[kb];  b01 = sb9[kb + PX];  b10 = sb9[kb + 2 * PX]; b11 = sb9[kb + 3 * PX];
    };
    auto gather_ldg = [&](int s) {
        int cofs = ((s & 7) << 5) + gcq * 8;
        gv[0] = *(const uint4*)(xn + b00 + cofs);
        gv[1] = *(const uint4*)(xn + b01 + cofs);
        gv[2] = *(const uint4*)(xn + b10 + cofs);
        gv[3] = *(const uint4*)(xn + b11 + cofs);
    };
    auto combine_sts = [&](int buf) {
        uint4 outv;
        half2* po = (half2*)&outv;
        #pragma unroll
        for (int j = 0; j < 4; ++j) {
            float2 f00 = __half22float2(((const half2*)&gv[0])[j]);
            float2 f01 = __half22float2(((const half2*)&gv[1])[j]);
            float2 f10 = __half22float2(((const half2*)&gv[2])[j]);
            float2 f11 = __half22float2(((const half2*)&gv[3])[j]);
            float rx = gw0 * f00.x + gw1 * f01.x + gw2 * f10.x + gw3 * f11.x;
            float ry = gw0 * f00.y + gw1 * f01.y + gw2 * f10.y + gw3 * f11.y;
            po[j] = __floats2half2_rn(rx, ry);
        }
        *(uint4*)&Ash[buf * ASH_HALF + gpx * 40 + gcq * 8] = outv;
    };
    auto cpasync_b = [&](int s, int buf) {
        int kk = s >> 3, c0n = (s & 7) << 5;
        const half* wsrc = w3h + ((size_t)kk << 16) + c0n;   // [k][o][c], row = 256 halves
        #pragma unroll
        for (int it = 0; it < 4; ++it) {
            int e = it * 256 + tid;
            int o = e >> 2, seg = e & 3;
            cp_async16(bs_saddr + (uint32_t)(buf * 20480 + o * 80 + seg * 16),
                       wsrc + o * 256 + seg * 8);
        }
        asm volatile("cp.async.commit_group;\n");
    };

    load_table(0);
    gather_ldg(0);
    cpasync_b(0, 0);

    int lg = lane >> 3, lr = lane & 7;

    for (int s = 0; s < 72; ++s) {
        int cb = s & 1;
        combine_sts(cb);            // uses table+gv of chunk s
        if (s < 71) {
            if (((s + 1) & 7) == 0) load_table((s + 1) >> 3);
            gather_ldg(s + 1);
        }
        asm volatile("cp.async.wait_group 0;\n");
        __syncthreads();
        if (s < 71) cpasync_b(s + 1, cb ^ 1);

        const half* Ab = Ash + cb * ASH_HALF;
        const half* Bb = Bsh + cb * 10240;
        #pragma unroll
        for (int ks = 0; ks < 2; ++ks) {
            int kb = ks * 16 + (lg >> 1) * 8;
            uint32_t a[2][4];
            #pragma unroll
            for (int mt = 0; mt < 2; ++mt)
                ldsm_x4(a[mt], Ab + (warpM * 32 + mt * 16 + (lg & 1) * 8 + lr) * 40 + kb);
            #pragma unroll
            for (int j = 0; j < 4; ++j) {
                uint32_t bf[4];
                ldsm_x4(bf, Bb + (warpN * 64 + j * 16 + (lg & 1) * 8 + lr) * 40 + kb);
                mma_f16(acc[0][2 * j],     a[0], bf[0], bf[2]);
                mma_f16(acc[1][2 * j],     a[1], bf[0], bf[2]);
                mma_f16(acc[0][2 * j + 1], a[0], bf[1], bf[3]);
                mma_f16(acc[1][2 * j + 1], a[1], bf[1], bf[3]);
            }
        }
        __syncthreads();
    }

    // epilogue: Y [b][o][HWo] + fused stats
    float* yp = g_scratch + y_o + (size_t)b * 256 * HWo;
    float* st_sum = g_scratch + stat_o + b * 256;
    float* st_sq  = g_scratch + stat_o + 512 + b * 256;
    int px0 = tile * PX + warpM * 32 + (lane >> 2);
    #pragma unroll
    for (int nt = 0; nt < 8; ++nt) {
        int o = warpN * 64 + nt * 8 + 2 * (lane & 3);
        float s0 = 0.f, s1 = 0.f, q0 = 0.f, q1 = 0.f;
        #pragma unroll
        for (int mt = 0; mt < 2; ++mt) {
            int px = px0 + mt * 16;
            float v0 = acc[mt][nt][0], v1 = acc[mt][nt][1];
            float v2 = acc[mt][nt][2], v3 = acc[mt][nt][3];
            yp[(size_t)o * HWo + px]           = v0;
            yp[(size_t)(o + 1) * HWo + px]     = v1;
            yp[(size_t)o * HWo + px + 8]       = v2;
            yp[(size_t)(o + 1) * HWo + px + 8] = v3;
            s0 += v0 + v2; s1 += v1 + v3;
            q0 += v0 * v0 + v2 * v2; q1 += v1 * v1 + v3 * v3;
        }
        #pragma unroll
        for (int off = 16; off >= 4; off >>= 1) {
            s0 += __shfl_down_sync(0xffffffffu, s0, off);
            s1 += __shfl_down_sync(0xffffffffu, s1, off);
            q0 += __shfl_down_sync(0xffffffffu, q0, off);
            q1 += __shfl_down_sync(0xffffffffu, q1, off);
        }
        if (lane < 4) {
            atomicAdd(&st_sum[o], s0);
            atomicAdd(&st_sum[o + 1], s1);
            atomicAdd(&st_sq[o], q0);
            atomicAdd(&st_sq[o + 1], q1);
        }
    }
}

// ---------------------------------------------------------------------------
// GN finalize + scale-attn scalar. Zeroes its stat slot after reading
// (self-recycling); mid-branch instance also zeroes P2 for the level.
// ---------------------------------------------------------------------------
__global__ void gn_finalize_kernel(
    size_t sum_o, size_t sq_o,
    const float* __restrict__ gamma, const float* __restrict__ beta,
    const float* __restrict__ w_sa, const float* __restrict__ b_sa,
    float inv_hw, float inv_cnt,
    size_t gnm_o, size_t gnr_o, size_t sv_o, int zero_p2)
{
    int b = blockIdx.x, t = threadIdx.x;  // 256
    __shared__ float ss[256], qq[256], gm[16], gr[16], red[256];
    ss[t] = g_scratch[sum_o + b * 256 + t];
    qq[t] = g_scratch[sq_o + b * 256 + t];
    g_scratch[sum_o + b * 256 + t] = 0.f;
    g_scratch[sq_o + b * 256 + t] = 0.f;
    if (zero_p2) g_scratch[OFF_P2 + b * 256 + t] = 0.f;
    __syncthreads();
    if (t < 16) {
        float S = 0.f, Q = 0.f;
        #pragma unroll
        for (int j = 0; j < 16; ++j) { S += ss[t * 16 + j]; Q += qq[t * 16 + j]; }
        float mean = S * inv_cnt;
        float var = Q * inv_cnt - mean * mean;
        float r = rsqrtf(var + 1e-5f);
        gm[t] = mean; gr[t] = r;
        g_scratch[gnm_o + b * 16 + t] = mean;
        g_scratch[gnr_o + b * 16 + t] = r;
    }
    __syncthreads();
    int g = t >> 4;
    float p = gamma[t] * (ss[t] * inv_hw - gm[g]) * gr[g] + beta[t];
    red[t] = p * w_sa[t];
    __syncthreads();
    for (int off = 128; off; off >>= 1) {
        if (t < off) red[t] += red[t + off];
        __syncthreads();
    }
    if (t == 0) {
        float x = fmaxf(red[0] + b_sa[0], 0.f);
        g_scratch[sv_o + b] = fminf(x + 3.f, 6.f) * (1.f / 6.f);
    }
}

// ---------------------------------------------------------------------------
// Combine branches + pooled sums.
// ---------------------------------------------------------------------------
__global__ void combine_kernel(
    size_t ymid_o, size_t ylow_o, size_t yhigh_o,
    int hasLow, int hasHigh, int W, int HW, int Hh, int Wh, float ry, float rx,
    size_t gnm_o, size_t gnr_o, size_t sv_o,
    const float* __restrict__ gw_mid, const float* __restrict__ gb_mid,
    const float* __restrict__ gw_low, const float* __restrict__ gb_low,
    const float* __restrict__ gw_high, const float* __restrict__ gb_high,
    float inv_n, size_t sumf_o, size_t p2_o)
{
    int b = blockIdx.z, c = blockIdx.y;
    int px = blockIdx.x * 256 + threadIdx.x;
    int g = c >> 4;
    int gi = b * 16 + g;
    size_t base = ((size_t)(b * 256 + c)) * HW;

    float v = g_scratch[sv_o + b] *
              (gw_mid[c] * (g_scratch[ymid_o + base + px] - g_scratch[gnm_o + gi]) * g_scratch[gnr_o + gi] + gb_mid[c]);
    if (hasLow)
        v += g_scratch[sv_o + 2 + b] *
             (gw_low[c] * (g_scratch[ylow_o + base + px] - g_scratch[gnm_o + 32 + gi]) * g_scratch[gnr_o + 32 + gi] + gb_low[c]);
    if (hasHigh) {
        int h = px / W, w = px - h * W;
        float sy = h * ry, sx = w * rx;
        int yl = (int)sy; int yh2 = min(yl + 1, Hh - 1);
        int xl = (int)sx; int xh = min(xl + 1, Wh - 1);
        float wy = sy - (float)yl, wx = sx - (float)xl;
        const float* hp = g_scratch + yhigh_o + ((size_t)(b * 256 + c)) * Hh * Wh;
        float t0 = hp[yl * Wh + xl] * (1.f - wx) + hp[yl * Wh + xh] * wx;
        float t1 = hp[yh2 * Wh + xl] * (1.f - wx) + hp[yh2 * Wh + xh] * wx;
        float raw = t0 * (1.f - wy) + t1 * wy;
        v += g_scratch[sv_o + 4 + b] *
             (gw_high[c] * (raw - g_scratch[gnm_o + 64 + gi]) * g_scratch[gnr_o + 64 + gi] + gb_high[c]);
    }
    v *= inv_n;
    g_scratch[sumf_o + base + px] = v;

    float r = v;
    #pragma unroll
    for (int o = 16; o; o >>= 1) r += __shfl_down_sync(0xffffffffu, r, o);
    __shared__ float wsum[8];
    if ((threadIdx.x & 31) == 0) wsum[threadIdx.x >> 5] = r;
    __syncthreads();
    if (threadIdx.x == 0) {
        float tt = 0.f;
        #pragma unroll
        for (int i = 0; i < 8; ++i) tt += wsum[i];
        atomicAdd(&g_scratch[p2_o + b * 256 + c], tt);
    }
}

// ---------------------------------------------------------------------------
// DyReLU coefficients.
// ---------------------------------------------------------------------------
__global__ void dycoef_kernel(size_t p2_o, float inv_hw,
    const float* __restrict__ w1, const float* __restrict__ b1,
    const float* __restrict__ w2, const float* __restrict__ b2,
    size_t coef_o)
{
    int b = blockIdx.x, t = threadIdx.x;  // 1024
    __shared__ float pm[256], hb[64];
    if (t < 256) pm[t] = g_scratch[p2_o + b * 256 + t] * inv_hw;
    __syncthreads();
    if (t < 64) {
        float a = b1[t];
        for (int cx = 0; cx < 256; ++cx) a += pm[cx] * w1[t * 256 + cx];
        hb[t] = fmaxf(a, 0.f);
    }
    __syncthreads();
    float a = b2[t];
    #pragma unroll
    for (int i = 0; i < 64; ++i) a += hb[i] * w2[t * 64 + i];
    float hs = fminf(fmaxf(a + 3.f, 0.f), 6.f) * (1.f / 6.f);
    g_scratch[coef_o + b * 1024 + t] = hs - 0.5f;
}

// ---------------------------------------------------------------------------
// Apply DyReLU, write final output.
// ---------------------------------------------------------------------------
__global__ void dyrelu_kernel(size_t sumf_o, size_t coef_o, int HW, float* __restrict__ outp, int CHW) {
    int idx = blockIdx.x * 256 + threadIdx.x;
    int b = idx / CHW;
    int c = (idx - b * CHW) / HW;
    const float* cf = g_scratch + coef_o + b * 1024;
    float x = g_scratch[sumf_o + idx];
    float a1 = cf[c] * 2.f + 1.f, bb1 = cf[256 + c];
    float a2 = cf[512 + c] * 2.f, bb2 = cf[768 + c];
    outp[idx] = fmaxf(x * a1 + bb1, x * a2 + bb2);
}

// ---------------------------------------------------------------------------
// Host orchestration
// ---------------------------------------------------------------------------
extern "C" void kernel_launch(void* const* d_in, const int* in_sizes, int n_in,
                              void* d_out, int out_size) {
    (void)in_sizes; (void)n_in; (void)out_size;
    const float* x0     = (const float*)d_in[0];
    const float* x1     = (const float*)d_in[1];
    const float* x2     = (const float*)d_in[2];
    const float* w_off  = (const float*)d_in[3];
    const float* b_off  = (const float*)d_in[4];
    const float* w_mid  = (const float*)d_in[5];
    const float* g_mid  = (const float*)d_in[6];
    const float* be_mid = (const float*)d_in[7];
    const float* w_low  = (const float*)d_in[8];
    const float* g_low  = (const float*)d_in[9];
    const float* be_low = (const float*)d_in[10];
    const float* w_high = (const float*)d_in[11];
    const float* g_high = (const float*)d_in[12];
    const float* be_high= (const float*)d_in[13];
    const float* w_sa   = (const float*)d_in[14];
    const float* b_sa   = (const float*)d_in[15];
    const float* w_dy1  = (const float*)d_in[16];
    const float* b_dy1  = (const float*)d_in[17];
    const float* w_dy2  = (const float*)d_in[18];
    const float* b_dy2  = (const float*)d_in[19];
    float* out = (float*)d_out;

    static bool attr_set = false;
    if (!attr_set) {
        cudaFuncSetAttribute(mdconv_mma_kernel,
                             cudaFuncAttributeMaxDynamicSharedMemorySize, MD_SMEM_BYTES);
        attr_set = true;
    }

    dim3 tblk(32, 8);
    const int Hs[3] = {128, 64, 32};
    const size_t xn_offs[3] = {OFF_X0N, OFF_X1N, OFF_X2N};

    // Launch order: slot 4 = mdconv mid L0 for the ncu window.
    transpose_kernel<<<dim3(128 * 128 / 32, 8, 2), tblk>>>(x0, OFF_X0N, 128 * 128);   // 1
    prep_kernel<<<2606, 256>>>(w_mid, w_off);                                          // 2
    offconv_mma_kernel<<<dim3(128 * 128 / 128, 2), 256>>>(OFF_X0N, 128, 128, b_off, OFF_OFFB); // 3
    mdconv_mma_kernel<<<dim3(128 * 128 / 64, 2), 256, MD_SMEM_BYTES>>>(                // 4
        OFF_X0N, 128, 128, OFF_OFFB, 128, 128, 1, 1, OFF_W3MID, OFF_YMID, 128 * 128, 128, OFF_STAT);
    reorder_w_half_kernel<<<2304, 256>>>(w_low,  OFF_W3LOW);                           // 5
    reorder_w_half_kernel<<<2304, 256>>>(w_high, OFF_W3HIGH);                          // 6
    transpose_kernel<<<dim3(64 * 64 / 32, 8, 2), tblk>>>(x1, OFF_X1N, 64 * 64);        // 7
    transpose_kernel<<<dim3(32 * 32 / 32, 8, 2), tblk>>>(x2, OFF_X2N, 32 * 32);        // 8

    size_t outoff = 0;
    for (int l = 0; l < 3; ++l) {
        int H = Hs[l], HW = H * H;
        int hasLow = (l > 0), hasHigh = (l < 2);
        int nbr = 1 + hasLow + hasHigh;
        int Hh = H / 2, HWh = Hh * Hh;

        if (l > 0) {
            offconv_mma_kernel<<<dim3(HW / 128, 2), 256>>>(xn_offs[l], H, H, b_off, OFF_OFFB);
            mdconv_mma_kernel<<<dim3(HW / 64, 2), 256, MD_SMEM_BYTES>>>(
                xn_offs[l], H, H, OFF_OFFB, H, H, 1, 1, OFF_W3MID, OFF_YMID, HW, H, OFF_STAT);
        }
        gn_finalize_kernel<<<2, 256>>>(OFF_STAT, OFF_STAT + 512, g_mid, be_mid, w_sa, b_sa,
                                       1.f / HW, 1.f / (16.f * HW),
                                       OFF_GNM, OFF_GNR, OFF_SV, 1);
        if (hasLow) {
            int Hi = Hs[l - 1];
            mdconv_mma_kernel<<<dim3(HW / 64, 2), 256, MD_SMEM_BYTES>>>(
                xn_offs[l - 1], Hi, Hi, OFF_OFFB, H, H, 1, 2, OFF_W3LOW, OFF_YLOW, HW, H,
                OFF_STAT + 1024);
            gn_finalize_kernel<<<2, 256>>>(OFF_STAT + 1024, OFF_STAT + 1536, g_low, be_low, w_sa, b_sa,
                                           1.f / HW, 1.f / (16.f * HW),
                                           OFF_GNM + 32, OFF_GNR + 32, OFF_SV + 2, 0);
        }
        if (hasHigh) {
            mdconv_mma_kernel<<<dim3(HWh / 64, 2), 256, MD_SMEM_BYTES>>>(
                xn_offs[l + 1], Hh, Hh, OFF_OFFB, H, H, 2, 1, OFF_W3HIGH, OFF_YHIGH, HWh, Hh,
                OFF_STAT + 2048);
            gn_finalize_kernel<<<2, 256>>>(OFF_STAT + 2048, OFF_STAT + 2560, g_high, be_high, w_sa, b_sa,
                                           1.f / HWh, 1.f / (16.f * HWh),
                                           OFF_GNM + 64, OFF_GNR + 64, OFF_SV + 4, 0);
        }

        float ry = (float)(Hh - 1) / (float)(H - 1);
        combine_kernel<<<dim3(HW / 256, 256, 2), 256>>>(
            OFF_YMID, OFF_YLOW, OFF_YHIGH, hasLow, hasHigh,
            H, HW, Hh, Hh, ry, ry,
            OFF_GNM, OFF_GNR, OFF_SV,
            g_mid, be_mid, g_low, be_low, g_high, be_high,
            1.f / (float)nbr, OFF_SUMF, OFF_P2);

        dycoef_kernel<<<2, 1024>>>(OFF_P2, 1.f / HW, w_dy1, b_dy1, w_dy2, b_dy2, OFF_COEF);

        int total = 2 * 256 * HW;
        dyrelu_kernel<<<total / 256, 256>>>(OFF_SUMF, OFF_COEF, HW, out + outoff, 256 * HW);
        outoff += (size_t)total;
    }
}

// round 10
// speedup vs baseline: 1.3721x; 1.0804x over previous
#include <cuda_runtime.h>
#include <cuda_fp16.h>
#include <math.h>
#include <stdint.h>

// ---------------------------------------------------------------------------
// DyHead-style MultiAttentionBlock. FP16 tensor-core mdconv + offconv,
// ldmatrix fragments, fp16 NHWC inputs, coalesced gather, triple-buffered
// cp.async B pipeline (distance 2), multi-stream branch overlap.
// B=2, C=256, levels H = {128, 64, 32}, GN groups = 16.
// ---------------------------------------------------------------------------

constexpr int BN = 2;
constexpr int C  = 256;

// ---- scratch layout (float units; X buffers are half, occupy half the slot) ----
constexpr size_t OFF_X0N   = 0;
constexpr size_t OFF_X1N   = OFF_X0N  + (size_t)BN*128*128*C;
constexpr size_t OFF_X2N   = OFF_X1N  + (size_t)BN*64*64*C;
constexpr size_t OFF_OFFB  = OFF_X2N  + (size_t)BN*32*32*C;
constexpr size_t OFF_YMID  = OFF_OFFB + (size_t)BN*128*128*27;
constexpr size_t OFF_YLOW  = OFF_YMID + (size_t)BN*C*128*128;
constexpr size_t OFF_YHIGH = OFF_YLOW + (size_t)BN*C*64*64;
constexpr size_t OFF_SUMF  = OFF_YHIGH+ (size_t)BN*C*64*64;
constexpr size_t OFF_W3MID = OFF_SUMF + (size_t)BN*C*128*128;   // half[9*256*256]
constexpr size_t OFF_W3LOW = OFF_W3MID + (size_t)9*256*256;
constexpr size_t OFF_W3HIGH= OFF_W3LOW + (size_t)9*256*256;
constexpr size_t OFF_W3OFF = OFF_W3HIGH+ (size_t)9*256*256;     // half[9*32*256]
constexpr size_t OFF_STAT  = OFF_W3OFF + (size_t)9*256*32;      // 3 sets x (512 sum + 512 sq)
constexpr size_t OFF_GNM   = OFF_STAT  + 3072;
constexpr size_t OFF_GNR   = OFF_GNM   + 96;
constexpr size_t OFF_SV    = OFF_GNR   + 96;
constexpr size_t OFF_P2    = OFF_SV    + 8;
constexpr size_t OFF_COEF  = OFF_P2    + 512;
constexpr size_t SCRATCH_TOTAL = OFF_COEF + 2048;

__device__ __align__(256) float g_scratch[SCRATCH_TOTAL];

// mdconv (PX=64) dynamic smem layout (bytes):
//   Ash : half [2][64*40]   at 0      (10240)
//   Bsh : half [3][256*40]  at 10240  (61440)
//   swt9: float[9][256]     at 71680  (9216)
//   sb9 : int  [9][256]     at 80896  (9216)
constexpr int MD_SMEM_BYTES = 90112;

__device__ __forceinline__ void mma_f16(float* d, const uint32_t* a, uint32_t b0, uint32_t b1) {
    asm volatile(
        "mma.sync.aligned.m16n8k16.row.col.f32.f16.f16.f32 "
        "{%0,%1,%2,%3},{%4,%5,%6,%7},{%8,%9},{%0,%1,%2,%3};\n"
        : "+f"(d[0]), "+f"(d[1]), "+f"(d[2]), "+f"(d[3])
        : "r"(a[0]), "r"(a[1]), "r"(a[2]), "r"(a[3]), "r"(b0), "r"(b1));
}

__device__ __forceinline__ void ldsm_x4(uint32_t* r, const half* p) {
    uint32_t a = (uint32_t)__cvta_generic_to_shared(p);
    asm volatile("ldmatrix.sync.aligned.m8n8.x4.shared.b16 {%0,%1,%2,%3}, [%4];"
        : "=r"(r[0]), "=r"(r[1]), "=r"(r[2]), "=r"(r[3]) : "r"(a));
}

__device__ __forceinline__ void cp_async16(uint32_t daddr, const void* src) {
    asm volatile("cp.async.cg.shared.global [%0], [%1], 16;\n" :: "r"(daddr), "l"(src));
}

// ---------------------------------------------------------------------------
// prep: w_mid -> half [k][o][c], w_off -> half [k][o32][c], zero stat+P2.
// ---------------------------------------------------------------------------
__global__ void prep_kernel(const float* __restrict__ w_mid, const float* __restrict__ w_off) {
    int bidx = blockIdx.x;
    if (bidx < 2304) {
        int idx = bidx * 256 + threadIdx.x;           // < 9*256*256
        int k = idx >> 16, o = (idx >> 8) & 255, c = idx & 255;
        ((half*)(g_scratch + OFF_W3MID))[idx] = __float2half(w_mid[(o * 256 + c) * 9 + k]);
    } else if (bidx < 2592) {
        int idx = (bidx - 2304) * 256 + threadIdx.x;  // < 9*32*256
        int k = idx >> 13, o = (idx >> 8) & 31, c = idx & 255;
        ((half*)(g_scratch + OFF_W3OFF))[idx] =
            __float2half(o < 27 ? w_off[(o * 256 + c) * 9 + k] : 0.f);
    } else {
        int idx = (bidx - 2592) * 256 + threadIdx.x;
        if (idx < 3584) g_scratch[OFF_STAT + idx] = 0.f;   // stats + P2
    }
}

__global__ void reorder_w_half_kernel(const float* __restrict__ w, size_t out_o) {
    int idx = blockIdx.x * 256 + threadIdx.x;         // < 9*256*256
    int k = idx >> 16, o = (idx >> 8) & 255, c = idx & 255;
    ((half*)(g_scratch + out_o))[idx] = __float2half(w[(o * 256 + c) * 9 + k]);
}

// ---------------------------------------------------------------------------
// NCHW fp32 -> NHWC fp16 transpose.
// ---------------------------------------------------------------------------
__global__ void transpose_kernel(const float* __restrict__ in, size_t out_o, int HW) {
    __shared__ float t[32][33];
    int b = blockIdx.z;
    int hw0 = blockIdx.x * 32, c0 = blockIdx.y * 32;
    int tx = threadIdx.x, ty = threadIdx.y;  // 32 x 8
    #pragma unroll
    for (int i = 0; i < 32; i += 8)
        t[ty + i][tx] = in[((size_t)b * C + c0 + ty + i) * HW + hw0 + tx];
    __syncthreads();
    half* xh = (half*)(g_scratch + out_o);
    #pragma unroll
    for (int i = 0; i < 32; i += 8)
        xh[((size_t)b * HW + hw0 + ty + i) * C + c0 + tx] = __float2half(t[tx][ty + i]);
}

// ---------------------------------------------------------------------------
// Offset conv via fp16 MMA + ldmatrix. 3x3, 256 -> 27 (padded 32).
// Block: 128 px x 32 o, 256 threads (8 warps = 4M x 2N). B triple-buffered.
// ---------------------------------------------------------------------------
__global__ __launch_bounds__(256) void offconv_mma_kernel(
    size_t xn_o, int H, int W,
    const float* __restrict__ bias, size_t out_o)
{
    __shared__ half Ash[2][128 * 40];
    __shared__ half Bsh[3][32 * 40];

    int b = blockIdx.y, tile = blockIdx.x, tid = threadIdx.x;
    int lane = tid & 31, warp = tid >> 5;
    int warpM = warp >> 1, warpN = warp & 1;
    const half* xn = (const half*)(g_scratch + xn_o);
    const half* wh = (const half*)(g_scratch + OFF_W3OFF);

    float acc[2][2][4];
    #pragma unroll
    for (int mt = 0; mt < 2; ++mt)
        #pragma unroll
        for (int nt = 0; nt < 2; ++nt)
            #pragma unroll
            for (int r = 0; r < 4; ++r) acc[mt][nt][r] = 0.f;

    int tpx = tid >> 1, tseg = tid & 1;
    int p = tile * 128 + tpx;
    int ph = p / W, pw = p - ph * W;

    uint32_t bs_saddr = (uint32_t)__cvta_generic_to_shared(&Bsh[0][0]);

    uint4 gr[2];
    auto gather_ldg = [&](int s) {
        int k = s >> 3, c0 = (s & 7) << 5;
        int dy = k / 3 - 1, dx = k % 3 - 1;
        int y = ph + dy, x = pw + dx;
        bool valid = (y >= 0 && y < H && x >= 0 && x < W);
        const half* src = xn + ((size_t)(b * H + y) * W + x) * 256 + c0 + tseg * 16;
        #pragma unroll
        for (int i = 0; i < 2; ++i)
            gr[i] = valid ? *(const uint4*)(src + i * 8) : make_uint4(0, 0, 0, 0);
    };
    auto sts_a = [&](int buf) {
        half* dst = &Ash[buf][tpx * 40 + tseg * 16];
        *(uint4*)&dst[0] = gr[0];
        *(uint4*)&dst[8] = gr[1];
    };
    auto cpasync_b = [&](int s, int buf) {
        int k = s >> 3, c0 = (s & 7) << 5;
        if (tid < 128) {
            int o = tid >> 2, seg = tid & 3;
            cp_async16(bs_saddr + (uint32_t)(buf * 2560 + o * 80 + seg * 16),
                       wh + ((size_t)(k * 32 + o) << 8) + c0 + seg * 8);
        }
        asm volatile("cp.async.commit_group;\n");
    };

    gather_ldg(0);
    cpasync_b(0, 0);
    cpasync_b(1, 1);

    int lg = lane >> 3, lr = lane & 7;
    int bufB = 0, slot2 = 2;

    for (int s = 0; s < 72; ++s) {
        int cb = s & 1;
        sts_a(cb);
        if (s < 71) gather_ldg(s + 1);
        if (s < 71) asm volatile("cp.async.wait_group 1;\n");
        else        asm volatile("cp.async.wait_group 0;\n");
        __syncthreads();
        if (s < 70) cpasync_b(s + 2, slot2);

        const half* Ab = Ash[cb];
        const half* Bb = Bsh[bufB];
        #pragma unroll
        for (int ks = 0; ks < 2; ++ks) {
            int kb = ks * 16 + (lg >> 1) * 8;
            uint32_t a[2][4];
            #pragma unroll
            for (int mt = 0; mt < 2; ++mt)
                ldsm_x4(a[mt], Ab + (warpM * 32 + mt * 16 + (lg & 1) * 8 + lr) * 40 + kb);
            uint32_t bf[4];
            ldsm_x4(bf, Bb + (warpN * 16 + (lg & 1) * 8 + lr) * 40 + kb);
            mma_f16(acc[0][0], a[0], bf[0], bf[2]);
            mma_f16(acc[1][0], a[1], bf[0], bf[2]);
            mma_f16(acc[0][1], a[0], bf[1], bf[3]);
            mma_f16(acc[1][1], a[1], bf[1], bf[3]);
        }
        __syncthreads();
        bufB = (bufB == 2) ? 0 : bufB + 1;
        slot2 = (slot2 == 2) ? 0 : slot2 + 1;
    }

    // epilogue: [b][px][27]
    int HWl = H * W;
    int pxb = tile * 128 + warpM * 32 + (lane >> 2);
    #pragma unroll
    for (int nt = 0; nt < 2; ++nt) {
        int o = warpN * 16 + nt * 8 + 2 * (lane & 3);
        float bv0 = (o < 27) ? bias[o] : 0.f;
        float bv1 = (o + 1 < 27) ? bias[o + 1] : 0.f;
        #pragma unroll
        for (int mt = 0; mt < 2; ++mt) {
            #pragma unroll
            for (int rr = 0; rr < 2; ++rr) {
                int px = pxb + mt * 16 + rr * 8;
                float v0 = acc[mt][nt][rr * 2 + 0] + bv0;
                float v1 = acc[mt][nt][rr * 2 + 1] + bv1;
                size_t ob = out_o + ((size_t)b * HWl + px) * 27;
                if (o < 27) {
                    if (o >= 18) v0 = 1.f / (1.f + expf(-v0));
                    g_scratch[ob + o] = v0;
                }
                if (o + 1 < 27) {
                    if (o + 1 >= 18) v1 = 1.f / (1.f + expf(-v1));
                    g_scratch[ob + o + 1] = v1;
                }
            }
        }
    }
}

// ---------------------------------------------------------------------------
// Modulated deformable conv: fused bilinear gather + FP16 MMA, triple-buffered
// cp.async B (distance 2), per-k register gather table, fused stats.
// Block: 64 px x 256 o, 256 threads (8 warps = 2M x 4N), 2 blocks/SM.
// ---------------------------------------------------------------------------
__global__ __launch_bounds__(256, 2) void mdconv_mma_kernel(
    size_t xn_o, int Hi, int Wi,
    size_t off_o, int offH, int offW, int offmul,
    int stride, size_t w3_o,
    size_t y_o, int HWo, int Wo, size_t stat_o)
{
    constexpr int PX = 64;
    constexpr int ASH_HALF = PX * 40;

    extern __shared__ char smraw[];
    half*  Ash  = (half*)smraw;               // [2][64*40]
    half*  Bsh  = (half*)(smraw + 10240);     // [3][256*40]
    float* swt9 = (float*)(smraw + 71680);    // [9][4*64]
    int*   sb9  = (int*)(smraw + 80896);      // [9][4*64]

    int b = blockIdx.y, tile = blockIdx.x, tid = threadIdx.x;
    int lane = tid & 31, warp = tid >> 5;
    int warpM = warp & 1, warpN = warp >> 1;

    const half* xn = (const half*)(g_scratch + xn_o);
    const half* w3h = (const half*)(g_scratch + w3_o);

    // precompute gather tables for all 9 taps
    for (int it = tid; it < 9 * PX; it += 256) {
        int k = it >> 6, p = it & 63;
        int pg = tile * PX + p;
        int h = pg / Wo, w = pg - h * Wo;
        size_t ob = off_o + ((size_t)(b * offH + h * offmul) * offW + w * offmul) * 27;
        float oy = g_scratch[ob + 2 * k];
        float ox = g_scratch[ob + 2 * k + 1];
        float m  = g_scratch[ob + 18 + k];
        float py  = (float)(h * stride - 1 + k / 3) + oy;
        float pxx = (float)(w * stride - 1 + k % 3) + ox;
        float fy = floorf(py), fx = floorf(pxx);
        int y0 = (int)fy, x0 = (int)fx;
        float wy = py - fy, wx = pxx - fx;
        int y1 = y0 + 1, x1 = x0 + 1;
        float vy0 = (y0 >= 0 && y0 < Hi) ? 1.f : 0.f;
        float vy1 = (y1 >= 0 && y1 < Hi) ? 1.f : 0.f;
        float vx0 = (x0 >= 0 && x0 < Wi) ? 1.f : 0.f;
        float vx1 = (x1 >= 0 && x1 < Wi) ? 1.f : 0.f;
        int y0c = min(max(y0, 0), Hi - 1), y1c = min(max(y1, 0), Hi - 1);
        int x0c = min(max(x0, 0), Wi - 1), x1c = min(max(x1, 0), Wi - 1);
        int kb = k * 4 * PX + p;
        swt9[kb]          = (1.f - wy) * (1.f - wx) * m * vy0 * vx0;
        swt9[kb + PX]     = (1.f - wy) * wx * m * vy0 * vx1;
        swt9[kb + 2 * PX] = wy * (1.f - wx) * m * vy1 * vx0;
        swt9[kb + 3 * PX] = wy * wx * m * vy1 * vx1;
        sb9[kb]          = ((b * Hi + y0c) * Wi + x0c) * 256;
        sb9[kb + PX]     = ((b * Hi + y0c) * Wi + x1c) * 256;
        sb9[kb + 2 * PX] = ((b * Hi + y1c) * Wi + x0c) * 256;
        sb9[kb + 3 * PX] = ((b * Hi + y1c) * Wi + x1c) * 256;
    }
    __syncthreads();

    float acc[2][8][4];
    #pragma unroll
    for (int mt = 0; mt < 2; ++mt)
        #pragma unroll
        for (int nt = 0; nt < 8; ++nt)
            #pragma unroll
            for (int r = 0; r < 4; ++r) acc[mt][nt][r] = 0.f;

    // coalesced gather mapping: 4 consecutive lanes = 4 segments of one px
    int gpx = tid >> 2;   // 0..63
    int gcq = tid & 3;    // 16B segment

    uint32_t bs_saddr = (uint32_t)__cvta_generic_to_shared(Bsh);

    // per-k register-resident table (reloaded every 8 chunks)
    float gw0, gw1, gw2, gw3;
    int b00, b01, b10, b11;
    uint4 gv[4];

    auto load_table = [&](int kk) {
        int kb = kk * 4 * PX + gpx;
        gw0 = swt9[kb]; gw1 = swt9[kb + PX]; gw2 = swt9[kb + 2 * PX]; gw3 = swt9[kb + 3 * PX];
        b00 = sb9[kb];  b01 = sb9[kb + PX];  b10 = sb9[kb + 2 * PX]; b11 = sb9[kb + 3 * PX];
    };
    auto gather_ldg = [&](int s) {
        int cofs = ((s & 7) << 5) + gcq * 8;
        gv[0] = *(const uint4*)(xn + b00 + cofs);
        gv[1] = *(const uint4*)(xn + b01 + cofs);
        gv[2] = *(const uint4*)(xn + b10 + cofs);
        gv[3] = *(const uint4*)(xn + b11 + cofs);
    };
    auto combine_sts = [&](int buf) {
        uint4 outv;
        half2* po = (half2*)&outv;
        #pragma unroll
        for (int j = 0; j < 4; ++j) {
            float2 f00 = __half22float2(((const half2*)&gv[0])[j]);
            float2 f01 = __half22float2(((const half2*)&gv[1])[j]);
            float2 f10 = __half22float2(((const half2*)&gv[2])[j]);
            float2 f11 = __half22float2(((const half2*)&gv[3])[j]);
            float rx = gw0 * f00.x + gw1 * f01.x + gw2 * f10.x + gw3 * f11.x;
            float ry = gw0 * f00.y + gw1 * f01.y + gw2 * f10.y + gw3 * f11.y;
            po[j] = __floats2half2_rn(rx, ry);
        }
        *(uint4*)&Ash[buf * ASH_HALF + gpx * 40 + gcq * 8] = outv;
    };
    auto cpasync_b = [&](int s, int buf) {
        int kk = s >> 3, c0n = (s & 7) << 5;
        const half* wsrc = w3h + ((size_t)kk << 16) + c0n;   // [k][o][c], row = 256 halves
        #pragma unroll
        for (int it = 0; it < 4; ++it) {
            int e = it * 256 + tid;
            int o = e >> 2, seg = e & 3;
            cp_async16(bs_saddr + (uint32_t)(buf * 20480 + o * 80 + seg * 16),
                       wsrc + o * 256 + seg * 8);
        }
        asm volatile("cp.async.commit_group;\n");
    };

    load_table(0);
    gather_ldg(0);
    cpasync_b(0, 0);
    cpasync_b(1, 1);

    int lg = lane >> 3, lr = lane & 7;
    int bufB = 0, slot2 = 2;

    for (int s = 0; s < 72; ++s) {
        int cb = s & 1;
        combine_sts(cb);            // uses table+gv of chunk s
        if (s < 71) {
            if (((s + 1) & 7) == 0) load_table((s + 1) >> 3);
            gather_ldg(s + 1);
        }
        if (s < 71) asm volatile("cp.async.wait_group 1;\n");
        else        asm volatile("cp.async.wait_group 0;\n");
        __syncthreads();
        if (s < 70) cpasync_b(s + 2, slot2);

        const half* Ab = Ash + cb * ASH_HALF;
        const half* Bb = Bsh + bufB * 10240;
        #pragma unroll
        for (int ks = 0; ks < 2; ++ks) {
            int kb = ks * 16 + (lg >> 1) * 8;
            uint32_t a[2][4];
            #pragma unroll
            for (int mt = 0; mt < 2; ++mt)
                ldsm_x4(a[mt], Ab + (warpM * 32 + mt * 16 + (lg & 1) * 8 + lr) * 40 + kb);
            #pragma unroll
            for (int j = 0; j < 4; ++j) {
                uint32_t bf[4];
                ldsm_x4(bf, Bb + (warpN * 64 + j * 16 + (lg & 1) * 8 + lr) * 40 + kb);
                mma_f16(acc[0][2 * j],     a[0], bf[0], bf[2]);
                mma_f16(acc[1][2 * j],     a[1], bf[0], bf[2]);
                mma_f16(acc[0][2 * j + 1], a[0], bf[1], bf[3]);
                mma_f16(acc[1][2 * j + 1], a[1], bf[1], bf[3]);
            }
        }
        bufB = (bufB == 2) ? 0 : bufB + 1;
        slot2 = (slot2 == 2) ? 0 : slot2 + 1;
    }

    // epilogue: Y [b][o][HWo] + fused stats
    float* yp = g_scratch + y_o + (size_t)b * 256 * HWo;
    float* st_sum = g_scratch + stat_o + b * 256;
    float* st_sq  = g_scratch + stat_o + 512 + b * 256;
    int px0 = tile * PX + warpM * 32 + (lane >> 2);
    #pragma unroll
    for (int nt = 0; nt < 8; ++nt) {
        int o = warpN * 64 + nt * 8 + 2 * (lane & 3);
        float s0 = 0.f, s1 = 0.f, q0 = 0.f, q1 = 0.f;
        #pragma unroll
        for (int mt = 0; mt < 2; ++mt) {
            int px = px0 + mt * 16;
            float v0 = acc[mt][nt][0], v1 = acc[mt][nt][1];
            float v2 = acc[mt][nt][2], v3 = acc[mt][nt][3];
            yp[(size_t)o * HWo + px]           = v0;
            yp[(size_t)(o + 1) * HWo + px]     = v1;
            yp[(size_t)o * HWo + px + 8]       = v2;
            yp[(size_t)(o + 1) * HWo + px + 8] = v3;
            s0 += v0 + v2; s1 += v1 + v3;
            q0 += v0 * v0 + v2 * v2; q1 += v1 * v1 + v3 * v3;
        }
        #pragma unroll
        for (int off = 16; off >= 4; off >>= 1) {
            s0 += __shfl_down_sync(0xffffffffu, s0, off);
            s1 += __shfl_down_sync(0xffffffffu, s1, off);
            q0 += __shfl_down_sync(0xffffffffu, q0, off);
            q1 += __shfl_down_sync(0xffffffffu, q1, off);
        }
        if (lane < 4) {
            atomicAdd(&st_sum[o], s0);
            atomicAdd(&st_sum[o + 1], s1);
            atomicAdd(&st_sq[o], q0);
            atomicAdd(&st_sq[o + 1], q1);
        }
    }
}

// ---------------------------------------------------------------------------
// GN finalize + scale-attn scalar. Zeroes its stat slot after reading;
// mid-branch instance also zeroes P2 for the level.
// ---------------------------------------------------------------------------
__global__ void gn_finalize_kernel(
    size_t sum_o, size_t sq_o,
    const float* __restrict__ gamma, const float* __restrict__ beta,
    const float* __restrict__ w_sa, const float* __restrict__ b_sa,
    float inv_hw, float inv_cnt,
    size_t gnm_o, size_t gnr_o, size_t sv_o, int zero_p2)
{
    int b = blockIdx.x, t = threadIdx.x;  // 256
    __shared__ float ss[256], qq[256], gm[16], gr[16], red[256];
    ss[t] = g_scratch[sum_o + b * 256 + t];
    qq[t] = g_scratch[sq_o + b * 256 + t];
    g_scratch[sum_o + b * 256 + t] = 0.f;
    g_scratch[sq_o + b * 256 + t] = 0.f;
    if (zero_p2) g_scratch[OFF_P2 + b * 256 + t] = 0.f;
    __syncthreads();
    if (t < 16) {
        float S = 0.f, Q = 0.f;
        #pragma unroll
        for (int j = 0; j < 16; ++j) { S += ss[t * 16 + j]; Q += qq[t * 16 + j]; }
        float mean = S * inv_cnt;
        float var = Q * inv_cnt - mean * mean;
        float r = rsqrtf(var + 1e-5f);
        gm[t] = mean; gr[t] = r;
        g_scratch[gnm_o + b * 16 + t] = mean;
        g_scratch[gnr_o + b * 16 + t] = r;
    }
    __syncthreads();
    int g = t >> 4;
    float p = gamma[t] * (ss[t] * inv_hw - gm[g]) * gr[g] + beta[t];
    red[t] = p * w_sa[t];
    __syncthreads();
    for (int off = 128; off; off >>= 1) {
        if (t < off) red[t] += red[t + off];
        __syncthreads();
    }
    if (t == 0) {
        float x = fmaxf(red[0] + b_sa[0], 0.f);
        g_scratch[sv_o + b] = fminf(x + 3.f, 6.f) * (1.f / 6.f);
    }
}

// ---------------------------------------------------------------------------
// Combine branches + pooled sums.
// ---------------------------------------------------------------------------
__global__ void combine_kernel(
    size_t ymid_o, size_t ylow_o, size_t yhigh_o,
    int hasLow, int hasHigh, int W, int HW, int Hh, int Wh, float ry, float rx,
    size_t gnm_o, size_t gnr_o, size_t sv_o,
    const float* __restrict__ gw_mid, const float* __restrict__ gb_mid,
    const float* __restrict__ gw_low, const float* __restrict__ gb_low,
    const float* __restrict__ gw_high, const float* __restrict__ gb_high,
    float inv_n, size_t sumf_o, size_t p2_o)
{
    int b = blockIdx.z, c = blockIdx.y;
    int px = blockIdx.x * 256 + threadIdx.x;
    int g = c >> 4;
    int gi = b * 16 + g;
    size_t base = ((size_t)(b * 256 + c)) * HW;

    float v = g_scratch[sv_o + b] *
              (gw_mid[c] * (g_scratch[ymid_o + base + px] - g_scratch[gnm_o + gi]) * g_scratch[gnr_o + gi] + gb_mid[c]);
    if (hasLow)
        v += g_scratch[sv_o + 2 + b] *
             (gw_low[c] * (g_scratch[ylow_o + base + px] - g_scratch[gnm_o + 32 + gi]) * g_scratch[gnr_o + 32 + gi] + gb_low[c]);
    if (hasHigh) {
        int h = px / W, w = px - h * W;
        float sy = h * ry, sx = w * rx;
        int yl = (int)sy; int yh2 = min(yl + 1, Hh - 1);
        int xl = (int)sx; int xh = min(xl + 1, Wh - 1);
        float wy = sy - (float)yl, wx = sx - (float)xl;
        const float* hp = g_scratch + yhigh_o + ((size_t)(b * 256 + c)) * Hh * Wh;
        float t0 = hp[yl * Wh + xl] * (1.f - wx) + hp[yl * Wh + xh] * wx;
        float t1 = hp[yh2 * Wh + xl] * (1.f - wx) + hp[yh2 * Wh + xh] * wx;
        float raw = t0 * (1.f - wy) + t1 * wy;
        v += g_scratch[sv_o + 4 + b] *
             (gw_high[c] * (raw - g_scratch[gnm_o + 64 + gi]) * g_scratch[gnr_o + 64 + gi] + gb_high[c]);
    }
    v *= inv_n;
    g_scratch[sumf_o + base + px] = v;

    float r = v;
    #pragma unroll
    for (int o = 16; o; o >>= 1) r += __shfl_down_sync(0xffffffffu, r, o);
    __shared__ float wsum[8];
    if ((threadIdx.x & 31) == 0) wsum[threadIdx.x >> 5] = r;
    __syncthreads();
    if (threadIdx.x == 0) {
        float tt = 0.f;
        #pragma unroll
        for (int i = 0; i < 8; ++i) tt += wsum[i];
        atomicAdd(&g_scratch[p2_o + b * 256 + c], tt);
    }
}

// ---------------------------------------------------------------------------
// DyReLU coefficients.
// ---------------------------------------------------------------------------
__global__ void dycoef_kernel(size_t p2_o, float inv_hw,
    const float* __restrict__ w1, const float* __restrict__ b1,
    const float* __restrict__ w2, const float* __restrict__ b2,
    size_t coef_o)
{
    int b = blockIdx.x, t = threadIdx.x;  // 1024
    __shared__ float pm[256], hb[64];
    if (t < 256) pm[t] = g_scratch[p2_o + b * 256 + t] * inv_hw;
    __syncthreads();
    if (t < 64) {
        float a = b1[t];
        for (int cx = 0; cx < 256; ++cx) a += pm[cx] * w1[t * 256 + cx];
        hb[t] = fmaxf(a, 0.f);
    }
    __syncthreads();
    float a = b2[t];
    #pragma unroll
    for (int i = 0; i < 64; ++i) a += hb[i] * w2[t * 64 + i];
    float hs = fminf(fmaxf(a + 3.f, 0.f), 6.f) * (1.f / 6.f);
    g_scratch[coef_o + b * 1024 + t] = hs - 0.5f;
}

// ---------------------------------------------------------------------------
// Apply DyReLU, write final output.
// ---------------------------------------------------------------------------
__global__ void dyrelu_kernel(size_t sumf_o, size_t coef_o, int HW, float* __restrict__ outp, int CHW) {
    int idx = blockIdx.x * 256 + threadIdx.x;
    int b = idx / CHW;
    int c = (idx - b * CHW) / HW;
    const float* cf = g_scratch + coef_o + b * 1024;
    float x = g_scratch[sumf_o + idx];
    float a1 = cf[c] * 2.f + 1.f, bb1 = cf[256 + c];
    float a2 = cf[512 + c] * 2.f, bb2 = cf[768 + c];
    outp[idx] = fmaxf(x * a1 + bb1, x * a2 + bb2);
}

// ---------------------------------------------------------------------------
// Host orchestration (multi-stream fork/join, graph-capture compatible)
// ---------------------------------------------------------------------------
extern "C" void kernel_launch(void* const* d_in, const int* in_sizes, int n_in,
                              void* d_out, int out_size) {
    (void)in_sizes; (void)n_in; (void)out_size;
    const float* x0     = (const float*)d_in[0];
    const float* x1     = (const float*)d_in[1];
    const float* x2     = (const float*)d_in[2];
    const float* w_off  = (const float*)d_in[3];
    const float* b_off  = (const float*)d_in[4];
    const float* w_mid  = (const float*)d_in[5];
    const float* g_mid  = (const float*)d_in[6];
    const float* be_mid = (const float*)d_in[7];
    const float* w_low  = (const float*)d_in[8];
    const float* g_low  = (const float*)d_in[9];
    const float* be_low = (const float*)d_in[10];
    const float* w_high = (const float*)d_in[11];
    const float* g_high = (const float*)d_in[12];
    const float* be_high= (const float*)d_in[13];
    const float* w_sa   = (const float*)d_in[14];
    const float* b_sa   = (const float*)d_in[15];
    const float* w_dy1  = (const float*)d_in[16];
    const float* b_dy1  = (const float*)d_in[17];
    const float* w_dy2  = (const float*)d_in[18];
    const float* b_dy2  = (const float*)d_in[19];
    float* out = (float*)d_out;

    static cudaStream_t sA = nullptr, sB = nullptr;
    static cudaEvent_t evFork[3], evLow[3], evHigh[3];
    static bool inited = false;
    if (!inited) {
        cudaFuncSetAttribute(mdconv_mma_kernel,
                             cudaFuncAttributeMaxDynamicSharedMemorySize, MD_SMEM_BYTES);
        cudaStreamCreateWithFlags(&sA, cudaStreamNonBlocking);
        cudaStreamCreateWithFlags(&sB, cudaStreamNonBlocking);
        for (int i = 0; i < 3; ++i) {
            cudaEventCreateWithFlags(&evFork[i], cudaEventDisableTiming);
            cudaEventCreateWithFlags(&evLow[i],  cudaEventDisableTiming);
            cudaEventCreateWithFlags(&evHigh[i], cudaEventDisableTiming);
        }
        inited = true;
    }

    dim3 tblk(32, 8);
    const int Hs[3] = {128, 64, 32};
    const size_t xn_offs[3] = {OFF_X0N, OFF_X1N, OFF_X2N};
    const size_t stat_offs[3] = {OFF_STAT, OFF_STAT + 1024, OFF_STAT + 2048};

    // Front matter (main stream; slot 4 = mdconv mid L0 for the ncu window).
    transpose_kernel<<<dim3(128 * 128 / 32, 8, 2), tblk>>>(x0, OFF_X0N, 128 * 128);   // 1
    prep_kernel<<<2606, 256>>>(w_mid, w_off);                                          // 2
    offconv_mma_kernel<<<dim3(128 * 128 / 128, 2), 256>>>(OFF_X0N, 128, 128, b_off, OFF_OFFB); // 3
    mdconv_mma_kernel<<<dim3(128 * 128 / 64, 2), 256, MD_SMEM_BYTES>>>(                // 4
        OFF_X0N, 128, 128, OFF_OFFB, 128, 128, 1, 1, OFF_W3MID, OFF_YMID, 128 * 128, 128, OFF_STAT);
    reorder_w_half_kernel<<<2304, 256>>>(w_low,  OFF_W3LOW);                           // 5
    reorder_w_half_kernel<<<2304, 256>>>(w_high, OFF_W3HIGH);                          // 6
    transpose_kernel<<<dim3(64 * 64 / 32, 8, 2), tblk>>>(x1, OFF_X1N, 64 * 64);        // 7
    transpose_kernel<<<dim3(32 * 32 / 32, 8, 2), tblk>>>(x2, OFF_X2N, 32 * 32);        // 8

    size_t outoff = 0;
    for (int l = 0; l < 3; ++l) {
        int H = Hs[l], HW = H * H;
        int hasLow = (l > 0), hasHigh = (l < 2);
        int nbr = 1 + hasLow + hasHigh;
        int Hh = H / 2, HWh = Hh * Hh;

        if (l > 0) {
            offconv_mma_kernel<<<dim3(HW / 128, 2), 256>>>(xn_offs[l], H, H, b_off, OFF_OFFB);
            mdconv_mma_kernel<<<dim3(HW / 64, 2), 256, MD_SMEM_BYTES>>>(
                xn_offs[l], H, H, OFF_OFFB, H, H, 1, 1, OFF_W3MID, OFF_YMID, HW, H, OFF_STAT);
        }

        // Fork: low on sA, high on sB (both depend only on offconv + transposes).
        cudaEventRecord(evFork[l], 0);
        if (hasLow) {
            int Hi = Hs[l - 1];
            cudaStreamWaitEvent(sA, evFork[l], 0);
            mdconv_mma_kernel<<<dim3(HW / 64, 2), 256, MD_SMEM_BYTES, sA>>>(
                xn_offs[l - 1], Hi, Hi, OFF_OFFB, H, H, 1, 2, OFF_W3LOW, OFF_YLOW, HW, H,
                stat_offs[1]);
            gn_finalize_kernel<<<2, 256, 0, sA>>>(stat_offs[1], stat_offs[1] + 512,
                                                  g_low, be_low, w_sa, b_sa,
                                                  1.f / HW, 1.f / (16.f * HW),
                                                  OFF_GNM + 32, OFF_GNR + 32, OFF_SV + 2, 0);
            cudaEventRecord(evLow[l], sA);
        }
        if (hasHigh) {
            cudaStreamWaitEvent(sB, evFork[l], 0);
            mdconv_mma_kernel<<<dim3(HWh / 64, 2), 256, MD_SMEM_BYTES, sB>>>(
                xn_offs[l + 1], Hh, Hh, OFF_OFFB, H, H, 2, 1, OFF_W3HIGH, OFF_YHIGH, HWh, Hh,
                stat_offs[2]);
            gn_finalize_kernel<<<2, 256, 0, sB>>>(stat_offs[2], stat_offs[2] + 512,
                                                  g_high, be_high, w_sa, b_sa,
                                                  1.f / HWh, 1.f / (16.f * HWh),
                                                  OFF_GNM + 64, OFF_GNR + 64, OFF_SV + 4, 0);
            cudaEventRecord(evHigh[l], sB);
        }

        gn_finalize_kernel<<<2, 256>>>(stat_offs[0], stat_offs[0] + 512,
                                       g_mid, be_mid, w_sa, b_sa,
                                       1.f / HW, 1.f / (16.f * HW),
                                       OFF_GNM, OFF_GNR, OFF_SV, 1);

        // Join
        if (hasLow)  cudaStreamWaitEvent(0, evLow[l], 0);
        if (hasHigh) cudaStreamWaitEvent(0, evHigh[l], 0);

        float ry = (float)(Hh - 1) / (float)(H - 1);
        combine_kernel<<<dim3(HW / 256, 256, 2), 256>>>(
            OFF_YMID, OFF_YLOW, OFF_YHIGH, hasLow, hasHigh,
            H, HW, Hh, Hh, ry, ry,
            OFF_GNM, OFF_GNR, OFF_SV,
            g_mid, be_mid, g_low, be_low, g_high, be_high,
            1.f / (float)nbr, OFF_SUMF, OFF_P2);

        dycoef_kernel<<<2, 1024>>>(OFF_P2, 1.f / HW, w_dy1, b_dy1, w_dy2, b_dy2, OFF_COEF);

        int total = 2 * 256 * HW;
        dyrelu_kernel<<<total / 256, 256>>>(OFF_SUMF, OFF_COEF, HW, out + outoff, 256 * HW);
        outoff += (size_t)total;
    }
}

// round 14
// speedup vs baseline: 2.0104x; 1.4652x over previous
#include <cuda_runtime.h>
#include <cuda_fp16.h>
#include <math.h>
#include <stdint.h>

// ---------------------------------------------------------------------------
// DyHead-style MultiAttentionBlock. FP16 tensor-core mdconv + offconv,
// ldmatrix fragments, fp16 NHWC inputs, coalesced gather, triple-buffered
// cp.async B (distance 2), level-pipelined schedule on 3 streams.
// Fix vs R13: prep zeroes the FULL accumulator range (stats..P2 inclusive,
// 11352 floats) so graph replays don't accumulate atomicAdds in P2.
// B=2, C=256, levels H = {128, 64, 32}, GN groups = 16.
// ---------------------------------------------------------------------------

constexpr int BN = 2;
constexpr int C  = 256;

// ---- scratch layout (float units; X/W3 buffers hold halves in float slots) ----
constexpr size_t OFF_X0N   = 0;                         // 2*128*128*256
constexpr size_t OFF_X1N   = OFF_X0N   + 8388608;
constexpr size_t OFF_X2N   = OFF_X1N   + 2097152;
constexpr size_t OFF_OFFB0 = OFF_X2N   + 524288;        // 2*128*128*27
constexpr size_t OFF_OFFB1 = OFF_OFFB0 + 884736;
constexpr size_t OFF_OFFB2 = OFF_OFFB1 + 221184;
constexpr size_t OFF_Y0M   = OFF_OFFB2 + 55296;
constexpr size_t OFF_Y0H   = OFF_Y0M   + 8388608;
constexpr size_t OFF_Y1M   = OFF_Y0H   + 2097152;
constexpr size_t OFF_Y1L   = OFF_Y1M   + 2097152;
constexpr size_t OFF_Y1H   = OFF_Y1L   + 2097152;
constexpr size_t OFF_Y2M   = OFF_Y1H   + 524288;
constexpr size_t OFF_Y2L   = OFF_Y2M   + 524288;
constexpr size_t OFF_SUMF0 = OFF_Y2L   + 524288;
constexpr size_t OFF_SUMF1 = OFF_SUMF0 + 8388608;
constexpr size_t OFF_SUMF2 = OFF_SUMF1 + 2097152;
constexpr size_t OFF_W3MID = OFF_SUMF2 + 524288;        // half[9*256*256]
constexpr size_t OFF_W3LOW = OFF_W3MID + 589824;
constexpr size_t OFF_W3HIGH= OFF_W3LOW + 589824;
constexpr size_t OFF_W3OFF = OFF_W3HIGH+ 589824;        // half[9*32*256]
constexpr size_t OFF_STAT  = OFF_W3OFF + 73728;         // 3 lvl x 3 br x 1024
constexpr size_t OFF_GNM   = OFF_STAT  + 9216;          // 3 lvl x 96
constexpr size_t OFF_GNR   = OFF_GNM   + 288;
constexpr size_t OFF_SV    = OFF_GNR   + 288;           // 3 lvl x 8
constexpr size_t OFF_P2    = OFF_SV    + 24;            // 3 lvl x 512
constexpr size_t OFF_COEF  = OFF_P2    + 1536;          // 3 lvl x 2048
constexpr size_t SCRATCH_TOTAL = OFF_COEF + 6144;

// floats to zero each replay: STAT(9216)+GNM(288)+GNR(288)+SV(24)+P2(1536)
constexpr int ZERO_SPAN = 11352;

__device__ __align__(256) float g_scratch[SCRATCH_TOTAL];

// mdconv (PX=64) dynamic smem layout (bytes):
//   Ash : half [2][64*40]   at 0      (10240)
//   Bsh : half [3][256*40]  at 10240  (61440)
//   swt9: float[9][256]     at 71680  (9216)
//   sb9 : int  [9][256]     at 80896  (9216)
constexpr int MD_SMEM_BYTES = 90112;

__device__ __forceinline__ void mma_f16(float* d, const uint32_t* a, uint32_t b0, uint32_t b1) {
    asm volatile(
        "mma.sync.aligned.m16n8k16.row.col.f32.f16.f16.f32 "
        "{%0,%1,%2,%3},{%4,%5,%6,%7},{%8,%9},{%0,%1,%2,%3};\n"
        : "+f"(d[0]), "+f"(d[1]), "+f"(d[2]), "+f"(d[3])
        : "r"(a[0]), "r"(a[1]), "r"(a[2]), "r"(a[3]), "r"(b0), "r"(b1));
}

__device__ __forceinline__ void ldsm_x4(uint32_t* r, const half* p) {
    uint32_t a = (uint32_t)__cvta_generic_to_shared(p);
    asm volatile("ldmatrix.sync.aligned.m8n8.x4.shared.b16 {%0,%1,%2,%3}, [%4];"
        : "=r"(r[0]), "=r"(r[1]), "=r"(r[2]), "=r"(r[3]) : "r"(a));
}

__device__ __forceinline__ void cp_async16(uint32_t daddr, const void* src) {
    asm volatile("cp.async.cg.shared.global [%0], [%1], 16;\n" :: "r"(daddr), "l"(src));
}

// ---------------------------------------------------------------------------
// prep: w_mid -> half [k][o][c], w_off -> half [k][o32][c], zero accumulators.
// ---------------------------------------------------------------------------
__global__ void prep_kernel(const float* __restrict__ w_mid, const float* __restrict__ w_off) {
    int bidx = blockIdx.x;
    if (bidx < 2304) {
        int idx = bidx * 256 + threadIdx.x;           // < 9*256*256
        int k = idx >> 16, o = (idx >> 8) & 255, c = idx & 255;
        ((half*)(g_scratch + OFF_W3MID))[idx] = __float2half(w_mid[(o * 256 + c) * 9 + k]);
    } else if (bidx < 2592) {
        int idx = (bidx - 2304) * 256 + threadIdx.x;  // < 9*32*256
        int k = idx >> 13, o = (idx >> 8) & 31, c = idx & 255;
        ((half*)(g_scratch + OFF_W3OFF))[idx] =
            __float2half(o < 27 ? w_off[(o * 256 + c) * 9 + k] : 0.f);
    } else {
        int idx = (bidx - 2592) * 256 + threadIdx.x;
        if (idx < ZERO_SPAN) g_scratch[OFF_STAT + idx] = 0.f;  // stats..P2 inclusive
    }
}

__global__ void reorder_w_half_kernel(const float* __restrict__ w, size_t out_o) {
    int idx = blockIdx.x * 256 + threadIdx.x;         // < 9*256*256
    int k = idx >> 16, o = (idx >> 8) & 255, c = idx & 255;
    ((half*)(g_scratch + out_o))[idx] = __float2half(w[(o * 256 + c) * 9 + k]);
}

// ---------------------------------------------------------------------------
// NCHW fp32 -> NHWC fp16 transpose.
// ---------------------------------------------------------------------------
__global__ void transpose_kernel(const float* __restrict__ in, size_t out_o, int HW) {
    __shared__ float t[32][33];
    int b = blockIdx.z;
    int hw0 = blockIdx.x * 32, c0 = blockIdx.y * 32;
    int tx = threadIdx.x, ty = threadIdx.y;  // 32 x 8
    #pragma unroll
    for (int i = 0; i < 32; i += 8)
        t[ty + i][tx] = in[((size_t)b * C + c0 + ty + i) * HW + hw0 + tx];
    __syncthreads();
    half* xh = (half*)(g_scratch + out_o);
    #pragma unroll
    for (int i = 0; i < 32; i += 8)
        xh[((size_t)b * HW + hw0 + ty + i) * C + c0 + tx] = __float2half(t[tx][ty + i]);
}

// ---------------------------------------------------------------------------
// Offset conv via fp16 MMA + ldmatrix. 3x3, 256 -> 27 (padded 32).
// Block: 128 px x 32 o, 256 threads (8 warps = 4M x 2N). B triple-buffered.
// ---------------------------------------------------------------------------
__global__ __launch_bounds__(256) void offconv_mma_kernel(
    size_t xn_o, int H, int W,
    const float* __restrict__ bias, size_t out_o)
{
    __shared__ half Ash[2][128 * 40];
    __shared__ half Bsh[3][32 * 40];

    int b = blockIdx.y, tile = blockIdx.x, tid = threadIdx.x;
    int lane = tid & 31, warp = tid >> 5;
    int warpM = warp >> 1, warpN = warp & 1;
    const half* xn = (const half*)(g_scratch + xn_o);
    const half* wh = (const half*)(g_scratch + OFF_W3OFF);

    float acc[2][2][4];
    #pragma unroll
    for (int mt = 0; mt < 2; ++mt)
        #pragma unroll
        for (int nt = 0; nt < 2; ++nt)
            #pragma unroll
            for (int r = 0; r < 4; ++r) acc[mt][nt][r] = 0.f;

    int tpx = tid >> 1, tseg = tid & 1;
    int p = tile * 128 + tpx;
    int ph = p / W, pw = p - ph * W;

    uint32_t bs_saddr = (uint32_t)__cvta_generic_to_shared(&Bsh[0][0]);

    uint4 gr[2];
    auto gather_ldg = [&](int s) {
        int k = s >> 3, c0 = (s & 7) << 5;
        int dy = k / 3 - 1, dx = k % 3 - 1;
        int y = ph + dy, x = pw + dx;
        bool valid = (y >= 0 && y < H && x >= 0 && x < W);
        const half* src = xn + ((size_t)(b * H + y) * W + x) * 256 + c0 + tseg * 16;
        #pragma unroll
        for (int i = 0; i < 2; ++i)
            gr[i] = valid ? *(const uint4*)(src + i * 8) : make_uint4(0, 0, 0, 0);
    };
    auto sts_a = [&](int buf) {
        half* dst = &Ash[buf][tpx * 40 + tseg * 16];
        *(uint4*)&dst[0] = gr[0];
        *(uint4*)&dst[8] = gr[1];
    };
    auto cpasync_b = [&](int s, int buf) {
        int k = s >> 3, c0 = (s & 7) << 5;
        if (tid < 128) {
            int o = tid >> 2, seg = tid & 3;
            cp_async16(bs_saddr + (uint32_t)(buf * 2560 + o * 80 + seg * 16),
                       wh + ((size_t)(k * 32 + o) << 8) + c0 + seg * 8);
        }
        asm volatile("cp.async.commit_group;\n");
    };

    gather_ldg(0);
    cpasync_b(0, 0);
    cpasync_b(1, 1);

    int lg = lane >> 3, lr = lane & 7;
    int bufB = 0, slot2 = 2;

    for (int s = 0; s < 72; ++s) {
        int cb = s & 1;
        sts_a(cb);
        if (s < 71) gather_ldg(s + 1);
        if (s < 71) asm volatile("cp.async.wait_group 1;\n");
        else        asm volatile("cp.async.wait_group 0;\n");
        __syncthreads();
        if (s < 70) cpasync_b(s + 2, slot2);

        const half* Ab = Ash[cb];
        const half* Bb = Bsh[bufB];
        #pragma unroll
        for (int ks = 0; ks < 2; ++ks) {
            int kb = ks * 16 + (lg >> 1) * 8;
            uint32_t a[2][4];
            #pragma unroll
            for (int mt = 0; mt < 2; ++mt)
                ldsm_x4(a[mt], Ab + (warpM * 32 + mt * 16 + (lg & 1) * 8 + lr) * 40 + kb);
            uint32_t bf[4];
            ldsm_x4(bf, Bb + (warpN * 16 + (lg & 1) * 8 + lr) * 40 + kb);
            mma_f16(acc[0][0], a[0], bf[0], bf[2]);
            mma_f16(acc[1][0], a[1], bf[0], bf[2]);
            mma_f16(acc[0][1], a[0], bf[1], bf[3]);
            mma_f16(acc[1][1], a[1], bf[1], bf[3]);
        }
        __syncthreads();
        bufB = (bufB == 2) ? 0 : bufB + 1;
        slot2 = (slot2 == 2) ? 0 : slot2 + 1;
    }

    // epilogue: [b][px][27]
    int HWl = H * W;
    int pxb = tile * 128 + warpM * 32 + (lane >> 2);
    #pragma unroll
    for (int nt = 0; nt < 2; ++nt) {
        int o = warpN * 16 + nt * 8 + 2 * (lane & 3);
        float bv0 = (o < 27) ? bias[o] : 0.f;
        float bv1 = (o + 1 < 27) ? bias[o + 1] : 0.f;
        #pragma unroll
        for (int mt = 0; mt < 2; ++mt) {
            #pragma unroll
            for (int rr = 0; rr < 2; ++rr) {
                int px = pxb + mt * 16 + rr * 8;
                float v0 = acc[mt][nt][rr * 2 + 0] + bv0;
                float v1 = acc[mt][nt][rr * 2 + 1] + bv1;
                size_t ob = out_o + ((size_t)b * HWl + px) * 27;
                if (o < 27) {
                    if (o >= 18) v0 = 1.f / (1.f + expf(-v0));
                    g_scratch[ob + o] = v0;
                }
                if (o + 1 < 27) {
                    if (o + 1 >= 18) v1 = 1.f / (1.f + expf(-v1));
                    g_scratch[ob + o + 1] = v1;
                }
            }
        }
    }
}

// ---------------------------------------------------------------------------
// Modulated deformable conv: fused bilinear gather + FP16 MMA, triple-buffered
// cp.async B (distance 2), per-k register gather table, fused stats.
// Block: 64 px x 256 o, 256 threads (8 warps = 2M x 4N), 2 blocks/SM.
// ---------------------------------------------------------------------------
__global__ __launch_bounds__(256, 2) void mdconv_mma_kernel(
    size_t xn_o, int Hi, int Wi,
    size_t off_o, int offH, int offW, int offmul,
    int stride, size_t w3_o,
    size_t y_o, int HWo, int Wo, size_t stat_o)
{
    constexpr int PX = 64;
    constexpr int ASH_HALF = PX * 40;

    extern __shared__ char smraw[];
    half*  Ash  = (half*)smraw;               // [2][64*40]
    half*  Bsh  = (half*)(smraw + 10240);     // [3][256*40]
    float* swt9 = (float*)(smraw + 71680);    // [9][4*64]
    int*   sb9  = (int*)(smraw + 80896);      // [9][4*64]

    int b = blockIdx.y, tile = blockIdx.x, tid = threadIdx.x;
    int lane = tid & 31, warp = tid >> 5;
    int warpM = warp & 1, warpN = warp >> 1;

    const half* xn = (const half*)(g_scratch + xn_o);
    const half* w3h = (const half*)(g_scratch + w3_o);

    // precompute gather tables for all 9 taps
    for (int it = tid; it < 9 * PX; it += 256) {
        int k = it >> 6, p = it & 63;
        int pg = tile * PX + p;
        int h = pg / Wo, w = pg - h * Wo;
        size_t ob = off_o + ((size_t)(b * offH + h * offmul) * offW + w * offmul) * 27;
        float oy = g_scratch[ob + 2 * k];
        float ox = g_scratch[ob + 2 * k + 1];
        float m  = g_scratch[ob + 18 + k];
        float py  = (float)(h * stride - 1 + k / 3) + oy;
        float pxx = (float)(w * stride - 1 + k % 3) + ox;
        float fy = floorf(py), fx = floorf(pxx);
        int y0 = (int)fy, x0 = (int)fx;
        float wy = py - fy, wx = pxx - fx;
        int y1 = y0 + 1, x1 = x0 + 1;
        float vy0 = (y0 >= 0 && y0 < Hi) ? 1.f : 0.f;
        float vy1 = (y1 >= 0 && y1 < Hi) ? 1.f : 0.f;
        float vx0 = (x0 >= 0 && x0 < Wi) ? 1.f : 0.f;
        float vx1 = (x1 >= 0 && x1 < Wi) ? 1.f : 0.f;
        int y0c = min(max(y0, 0), Hi - 1), y1c = min(max(y1, 0), Hi - 1);
        int x0c = min(max(x0, 0), Wi - 1), x1c = min(max(x1, 0), Wi - 1);
        int kb = k * 4 * PX + p;
        swt9[kb]          = (1.f - wy) * (1.f - wx) * m * vy0 * vx0;
        swt9[kb + PX]     = (1.f - wy) * wx * m * vy0 * vx1;
        swt9[kb + 2 * PX] = wy * (1.f - wx) * m * vy1 * vx0;
        swt9[kb + 3 * PX] = wy * wx * m * vy1 * vx1;
        sb9[kb]          = ((b * Hi + y0c) * Wi + x0c) * 256;
        sb9[kb + PX]     = ((b * Hi + y0c) * Wi + x1c) * 256;
        sb9[kb + 2 * PX] = ((b * Hi + y1c) * Wi + x0c) * 256;
        sb9[kb + 3 * PX] = ((b * Hi + y1c) * Wi + x1c) * 256;
    }
    __syncthreads();

    float acc[2][8][4];
    #pragma unroll
    for (int mt = 0; mt < 2; ++mt)
        #pragma unroll
        for (int nt = 0; nt < 8; ++nt)
            #pragma unroll
            for (int r = 0; r < 4; ++r) acc[mt][nt][r] = 0.f;

    // coalesced gather mapping: 4 consecutive lanes = 4 segments of one px
    int gpx = tid >> 2;   // 0..63
    int gcq = tid & 3;    // 16B segment

    uint32_t bs_saddr = (uint32_t)__cvta_generic_to_shared(Bsh);

    // per-k register-resident table (reloaded every 8 chunks)
    float gw0, gw1, gw2, gw3;
    int b00, b01, b10, b11;
    uint4 gv[4];

    auto load_table = [&](int kk) {
        int kb = kk * 4 * PX + gpx;
        gw0 = swt9[kb]; gw1 = swt9[kb + PX]; gw2 = swt9[kb + 2 * PX]; gw3 = swt9[kb + 3 * PX];
        b00 = sb9[kb];  b01 = sb9[kb + PX];  b10 = sb9[kb + 2 * PX]; b11 = sb9[kb + 3 * PX];
    };
    auto gather_ldg = [&](int s) {
        int cofs = ((s & 7) << 5) + gcq * 8;
        gv[0] = *(const uint4*)(xn + b00 + cofs);
        gv[1] = *(const uint4*)(xn + b01 + cofs);
        gv[2] = *(const uint4*)(xn + b10 + cofs);
        gv[3] = *(const uint4*)(xn + b11 + cofs);
    };
    auto combine_sts = [&](int buf) {
        uint4 outv;
        half2* po = (half2*)&outv;
        #pragma unroll
        for (int j = 0; j < 4; ++j) {
            float2 f00 = __half22float2(((const half2*)&gv[0])[j]);
            float2 f01 = __half22float2(((const half2*)&gv[1])[j]);
            float2 f10 = __half22float2(((const half2*)&gv[2])[j]);
            float2 f11 = __half22float2(((const half2*)&gv[3])[j]);
            float rx = gw0 * f00.x + gw1 * f01.x + gw2 * f10.x + gw3 * f11.x;
            float ry = gw0 * f00.y + gw1 * f01.y + gw2 * f10.y + gw3 * f11.y;
            po[j] = __floats2half2_rn(rx, ry);
        }
        *(uint4*)&Ash[buf * ASH_HALF + gpx * 40 + gcq * 8] = outv;
    };
    auto cpasync_b = [&](int s, int buf) {
        int kk = s >> 3, c0n = (s & 7) << 5;
        const half* wsrc = w3h + ((size_t)kk << 16) + c0n;   // [k][o][c], row = 256 halves
        #pragma unroll
        for (int it = 0; it < 4; ++it) {
            int e = it * 256 + tid;
            int o = e >> 2, seg = e & 3;
            cp_async16(bs_saddr + (uint32_t)(buf * 20480 + o * 80 + seg * 16),
                       wsrc + o * 256 + seg * 8);
        }
        asm volatile("cp.async.commit_group;\n");
    };

    load_table(0);
    gather_ldg(0);
    cpasync_b(0, 0);
    cpasync_b(1, 1);

    int lg = lane >> 3, lr = lane & 7;
    int bufB = 0, slot2 = 2;

    for (int s = 0; s < 72; ++s) {
        int cb = s & 1;
        combine_sts(cb);            // uses table+gv of chunk s
        if (s < 71) {
            if (((s + 1) & 7) == 0) load_table((s + 1) >> 3);
            gather_ldg(s + 1);
        }
        if (s < 71) asm volatile("cp.async.wait_group 1;\n");
        else        asm volatile("cp.async.wait_group 0;\n");
        __syncthreads();
        if (s < 70) cpasync_b(s + 2, slot2);

        const half* Ab = Ash + cb * ASH_HALF;
        const half* Bb = Bsh + bufB * 10240;
        #pragma unroll
        for (int ks = 0; ks < 2; ++ks) {
            int kb = ks * 16 + (lg >> 1) * 8;
            uint32_t a[2][4];
            #pragma unroll
            for (int mt = 0; mt < 2; ++mt)
                ldsm_x4(a[mt], Ab + (warpM * 32 + mt * 16 + (lg & 1) * 8 + lr) * 40 + kb);
            #pragma unroll
            for (int j = 0; j < 4; ++j) {
                uint32_t bf[4];
                ldsm_x4(bf, Bb + (warpN * 64 + j * 16 + (lg & 1) * 8 + lr) * 40 + kb);
                mma_f16(acc[0][2 * j],     a[0], bf[0], bf[2]);
                mma_f16(acc[1][2 * j],     a[1], bf[0], bf[2]);
                mma_f16(acc[0][2 * j + 1], a[0], bf[1], bf[3]);
                mma_f16(acc[1][2 * j + 1], a[1], bf[1], bf[3]);
            }
        }
        bufB = (bufB == 2) ? 0 : bufB + 1;
        slot2 = (slot2 == 2) ? 0 : slot2 + 1;
    }

    // epilogue: Y [b][o][HWo] + fused stats
    float* yp = g_scratch + y_o + (size_t)b * 256 * HWo;
    float* st_sum = g_scratch + stat_o + b * 256;
    float* st_sq  = g_scratch + stat_o + 512 + b * 256;
    int px0 = tile * PX + warpM * 32 + (lane >> 2);
    #pragma unroll
    for (int nt = 0; nt < 8; ++nt) {
        int o = warpN * 64 + nt * 8 + 2 * (lane & 3);
        float s0 = 0.f, s1 = 0.f, q0 = 0.f, q1 = 0.f;
        #pragma unroll
        for (int mt = 0; mt < 2; ++mt) {
            int px = px0 + mt * 16;
            float v0 = acc[mt][nt][0], v1 = acc[mt][nt][1];
            float v2 = acc[mt][nt][2], v3 = acc[mt][nt][3];
            yp[(size_t)o * HWo + px]           = v0;
            yp[(size_t)(o + 1) * HWo + px]     = v1;
            yp[(size_t)o * HWo + px + 8]       = v2;
            yp[(size_t)(o + 1) * HWo + px + 8] = v3;
            s0 += v0 + v2; s1 += v1 + v3;
            q0 += v0 * v0 + v2 * v2; q1 += v1 * v1 + v3 * v3;
        }
        #pragma unroll
        for (int off = 16; off >= 4; off >>= 1) {
            s0 += __shfl_down_sync(0xffffffffu, s0, off);
            s1 += __shfl_down_sync(0xffffffffu, s1, off);
            q0 += __shfl_down_sync(0xffffffffu, q0, off);
            q1 += __shfl_down_sync(0xffffffffu, q1, off);
        }
        if (lane < 4) {
            atomicAdd(&st_sum[o], s0);
            atomicAdd(&st_sum[o + 1], s1);
            atomicAdd(&st_sq[o], q0);
            atomicAdd(&st_sq[o + 1], q1);
        }
    }
}

// ---------------------------------------------------------------------------
// GN finalize + scale-attn scalar (stats pre-zeroed by prep each replay).
// ---------------------------------------------------------------------------
__global__ void gn_finalize_kernel(
    size_t sum_o, size_t sq_o,
    const float* __restrict__ gamma, const float* __restrict__ beta,
    const float* __restrict__ w_sa, const float* __restrict__ b_sa,
    float inv_hw, float inv_cnt,
    size_t gnm_o, size_t gnr_o, size_t sv_o)
{
    int b = blockIdx.x, t = threadIdx.x;  // 256
    __shared__ float ss[256], qq[256], gm[16], gr[16], red[256];
    ss[t] = g_scratch[sum_o + b * 256 + t];
    qq[t] = g_scratch[sq_o + b * 256 + t];
    __syncthreads();
    if (t < 16) {
        float S = 0.f, Q = 0.f;
        #pragma unroll
        for (int j = 0; j < 16; ++j) { S += ss[t * 16 + j]; Q += qq[t * 16 + j]; }
        float mean = S * inv_cnt;
        float var = Q * inv_cnt - mean * mean;
        float r = rsqrtf(var + 1e-5f);
        gm[t] = mean; gr[t] = r;
        g_scratch[gnm_o + b * 16 + t] = mean;
        g_scratch[gnr_o + b * 16 + t] = r;
    }
    __syncthreads();
    int g = t >> 4;
    float p = gamma[t] * (ss[t] * inv_hw - gm[g]) * gr[g] + beta[t];
    red[t] = p * w_sa[t];
    __syncthreads();
    for (int off = 128; off; off >>= 1) {
        if (t < off) red[t] += red[t + off];
        __syncthreads();
    }
    if (t == 0) {
        float x = fmaxf(red[0] + b_sa[0], 0.f);
        g_scratch[sv_o + b] = fminf(x + 3.f, 6.f) * (1.f / 6.f);
    }
}

// ---------------------------------------------------------------------------
// Combine branches + pooled sums.
// ---------------------------------------------------------------------------
__global__ void combine_kernel(
    size_t ymid_o, size_t ylow_o, size_t yhigh_o,
    int hasLow, int hasHigh, int W, int HW, int Hh, int Wh, float ry, float rx,
    size_t gnm_o, size_t gnr_o, size_t sv_o,
    const float* __restrict__ gw_mid, const float* __restrict__ gb_mid,
    const float* __restrict__ gw_low, const float* __restrict__ gb_low,
    const float* __restrict__ gw_high, const float* __restrict__ gb_high,
    float inv_n, size_t sumf_o, size_t p2_o)
{
    int b = blockIdx.z, c = blockIdx.y;
    int px = blockIdx.x * 256 + threadIdx.x;
    int g = c >> 4;
    int gi = b * 16 + g;
    size_t base = ((size_t)(b * 256 + c)) * HW;

    float v = g_scratch[sv_o + b] *
              (gw_mid[c] * (g_scratch[ymid_o + base + px] - g_scratch[gnm_o + gi]) * g_scratch[gnr_o + gi] + gb_mid[c]);
    if (hasLow)
        v += g_scratch[sv_o + 2 + b] *
             (gw_low[c] * (g_scratch[ylow_o + base + px] - g_scratch[gnm_o + 32 + gi]) * g_scratch[gnr_o + 32 + gi] + gb_low[c]);
    if (hasHigh) {
        int h = px / W, w = px - h * W;
        float sy = h * ry, sx = w * rx;
        int yl = (int)sy; int yh2 = min(yl + 1, Hh - 1);
        int xl = (int)sx; int xh = min(xl + 1, Wh - 1);
        float wy = sy - (float)yl, wx = sx - (float)xl;
        const float* hp = g_scratch + yhigh_o + ((size_t)(b * 256 + c)) * Hh * Wh;
        float t0 = hp[yl * Wh + xl] * (1.f - wx) + hp[yl * Wh + xh] * wx;
        float t1 = hp[yh2 * Wh + xl] * (1.f - wx) + hp[yh2 * Wh + xh] * wx;
        float raw = t0 * (1.f - wy) + t1 * wy;
        v += g_scratch[sv_o + 4 + b] *
             (gw_high[c] * (raw - g_scratch[gnm_o + 64 + gi]) * g_scratch[gnr_o + 64 + gi] + gb_high[c]);
    }
    v *= inv_n;
    g_scratch[sumf_o + base + px] = v;

    float r = v;
    #pragma unroll
    for (int o = 16; o; o >>= 1) r += __shfl_down_sync(0xffffffffu, r, o);
    __shared__ float wsum[8];
    if ((threadIdx.x & 31) == 0) wsum[threadIdx.x >> 5] = r;
    __syncthreads();
    if (threadIdx.x == 0) {
        float tt = 0.f;
        #pragma unroll
        for (int i = 0; i < 8; ++i) tt += wsum[i];
        atomicAdd(&g_scratch[p2_o + b * 256 + c], tt);
    }
}

// ---------------------------------------------------------------------------
// DyReLU coefficients.
// ---------------------------------------------------------------------------
__global__ void dycoef_kernel(size_t p2_o, float inv_hw,
    const float* __restrict__ w1, const float* __restrict__ b1,
    const float* __restrict__ w2, const float* __restrict__ b2,
    size_t coef_o)
{
    int b = blockIdx.x, t = threadIdx.x;  // 1024
    __shared__ float pm[256], hb[64];
    if (t < 256) pm[t] = g_scratch[p2_o + b * 256 + t] * inv_hw;
    __syncthreads();
    if (t < 64) {
        float a = b1[t];
        for (int cx = 0; cx < 256; ++cx) a += pm[cx] * w1[t * 256 + cx];
        hb[t] = fmaxf(a, 0.f);
    }
    __syncthreads();
    float a = b2[t];
    #pragma unroll
    for (int i = 0; i < 64; ++i) a += hb[i] * w2[t * 64 + i];
    float hs = fminf(fmaxf(a + 3.f, 0.f), 6.f) * (1.f / 6.f);
    g_scratch[coef_o + b * 1024 + t] = hs - 0.5f;
}

// ---------------------------------------------------------------------------
// Apply DyReLU, write final output.
// ---------------------------------------------------------------------------
__global__ void dyrelu_kernel(size_t sumf_o, size_t coef_o, int HW, float* __restrict__ outp, int CHW) {
    int idx = blockIdx.x * 256 + threadIdx.x;
    int b = idx / CHW;
    int c = (idx - b * CHW) / HW;
    const float* cf = g_scratch + coef_o + b * 1024;
    float x = g_scratch[sumf_o + idx];
    float a1 = cf[c] * 2.f + 1.f, bb1 = cf[256 + c];
    float a2 = cf[512 + c] * 2.f, bb2 = cf[768 + c];
    outp[idx] = fmaxf(x * a1 + bb1, x * a2 + bb2);
}

// ---------------------------------------------------------------------------
// Host orchestration: level-pipelined schedule on 3 streams (main + s1 + s2),
// side streams event-forked from the capture stream.
// ---------------------------------------------------------------------------
extern "C" void kernel_launch(void* const* d_in, const int* in_sizes, int n_in,
                              void* d_out, int out_size) {
    (void)in_sizes; (void)n_in; (void)out_size;
    const float* x0     = (const float*)d_in[0];
    const float* x1     = (const float*)d_in[1];
    const float* x2     = (const float*)d_in[2];
    const float* w_off  = (const float*)d_in[3];
    const float* b_off  = (const float*)d_in[4];
    const float* w_mid  = (const float*)d_in[5];
    const float* g_mid  = (const float*)d_in[6];
    const float* be_mid = (const float*)d_in[7];
    const float* w_low  = (const float*)d_in[8];
    const float* g_low  = (const float*)d_in[9];
    const float* be_low = (const float*)d_in[10];
    const float* w_high = (const float*)d_in[11];
    const float* g_high = (const float*)d_in[12];
    const float* be_high= (const float*)d_in[13];
    const float* w_sa   = (const float*)d_in[14];
    const float* b_sa   = (const float*)d_in[15];
    const float* w_dy1  = (const float*)d_in[16];
    const float* b_dy1  = (const float*)d_in[17];
    const float* w_dy2  = (const float*)d_in[18];
    const float* b_dy2  = (const float*)d_in[19];
    float* out = (float*)d_out;

    static cudaStream_t s1, s2;
    static cudaEvent_t evRoot, evT0, evT1, evPrep, evOff0, evOff1, evWL;
    static cudaEvent_t evHigh0, evHigh1, evL1, evL2;
    static bool inited = false;
    if (!inited) {
        cudaFuncSetAttribute(mdconv_mma_kernel,
                             cudaFuncAttributeMaxDynamicSharedMemorySize, MD_SMEM_BYTES);
        cudaStreamCreateWithFlags(&s1, cudaStreamNonBlocking);
        cudaStreamCreateWithFlags(&s2, cudaStreamNonBlocking);
        cudaEvent_t* evs[] = {&evRoot, &evT0, &evT1, &evPrep, &evOff0, &evOff1, &evWL,
                              &evHigh0, &evHigh1, &evL1, &evL2};
        for (auto e : evs) cudaEventCreateWithFlags(e, cudaEventDisableTiming);
        inited = true;
    }

    dim3 tblk(32, 8);
    const float inv16k = 1.f / 16384.f, inv4k = 1.f / 4096.f, inv1k = 1.f / 1024.f;

    // ---- main: L0 mid chain. Root event first so side streams fork legally.
    transpose_kernel<<<dim3(512, 8, 2), tblk>>>(x0, OFF_X0N, 16384);      // launch 1
    cudaEventRecord(evRoot, 0);
    cudaEventRecord(evT0, 0);
    cudaStreamWaitEvent(s1, evRoot, 0);
    cudaStreamWaitEvent(s2, evRoot, 0);

    prep_kernel<<<2637, 256>>>(w_mid, w_off);                              // launch 2
    cudaEventRecord(evPrep, 0);
    offconv_mma_kernel<<<dim3(128, 2), 256>>>(OFF_X0N, 128, 128, b_off, OFF_OFFB0); // 3
    cudaEventRecord(evOff0, 0);
    mdconv_mma_kernel<<<dim3(256, 2), 256, MD_SMEM_BYTES>>>(               // launch 4 (ncu)
        OFF_X0N, 128, 128, OFF_OFFB0, 128, 128, 1, 1, OFF_W3MID, OFF_Y0M, 16384, 128, OFF_STAT);

    // ---- s1: L1 chain + low1 + L1 tail
    transpose_kernel<<<dim3(128, 8, 2), tblk, 0, s1>>>(x1, OFF_X1N, 4096);
    cudaEventRecord(evT1, s1);
    reorder_w_half_kernel<<<2304, 256, 0, s1>>>(w_low, OFF_W3LOW);
    cudaEventRecord(evWL, s1);
    cudaStreamWaitEvent(s1, evPrep, 0);
    offconv_mma_kernel<<<dim3(32, 2), 256, 0, s1>>>(OFF_X1N, 64, 64, b_off, OFF_OFFB1);
    cudaEventRecord(evOff1, s1);
    mdconv_mma_kernel<<<dim3(64, 2), 256, MD_SMEM_BYTES, s1>>>(
        OFF_X1N, 64, 64, OFF_OFFB1, 64, 64, 1, 1, OFF_W3MID, OFF_Y1M, 4096, 64, OFF_STAT + 3072);
    gn_finalize_kernel<<<2, 256, 0, s1>>>(OFF_STAT + 3072, OFF_STAT + 3584,
        g_mid, be_mid, w_sa, b_sa, inv4k, inv4k / 16.f,
        OFF_GNM + 96, OFF_GNR + 96, OFF_SV + 8);
    cudaStreamWaitEvent(s1, evT0, 0);
    mdconv_mma_kernel<<<dim3(64, 2), 256, MD_SMEM_BYTES, s1>>>(
        OFF_X0N, 128, 128, OFF_OFFB1, 64, 64, 1, 2, OFF_W3LOW, OFF_Y1L, 4096, 64, OFF_STAT + 4096);
    gn_finalize_kernel<<<2, 256, 0, s1>>>(OFF_STAT + 4096, OFF_STAT + 4608,
        g_low, be_low, w_sa, b_sa, inv4k, inv4k / 16.f,
        OFF_GNM + 96 + 32, OFF_GNR + 96 + 32, OFF_SV + 8 + 2);

    // ---- s2: L2 chain + high0 + high1 + low2 + L2 tail
    transpose_kernel<<<dim3(32, 8, 2), tblk, 0, s2>>>(x2, OFF_X2N, 1024);
    reorder_w_half_kernel<<<2304, 256, 0, s2>>>(w_high, OFF_W3HIGH);
    cudaStreamWaitEvent(s2, evPrep, 0);
    offconv_mma_kernel<<<dim3(8, 2), 256, 0, s2>>>(OFF_X2N, 32, 32, b_off, OFF_OFFB2);
    mdconv_mma_kernel<<<dim3(16, 2), 256, MD_SMEM_BYTES, s2>>>(
        OFF_X2N, 32, 32, OFF_OFFB2, 32, 32, 1, 1, OFF_W3MID, OFF_Y2M, 1024, 32, OFF_STAT + 6144);
    gn_finalize_kernel<<<2, 256, 0, s2>>>(OFF_STAT + 6144, OFF_STAT + 6656,
        g_mid, be_mid, w_sa, b_sa, inv1k, inv1k / 16.f,
        OFF_GNM + 192, OFF_GNR + 192, OFF_SV + 16);
    cudaStreamWaitEvent(s2, evOff0, 0);
    cudaStreamWaitEvent(s2, evT1, 0);
    mdconv_mma_kernel<<<dim3(64, 2), 256, MD_SMEM_BYTES, s2>>>(
        OFF_X1N, 64, 64, OFF_OFFB0, 128, 128, 2, 1, OFF_W3HIGH, OFF_Y0H, 4096, 64, OFF_STAT + 2048);
    gn_finalize_kernel<<<2, 256, 0, s2>>>(OFF_STAT + 2048, OFF_STAT + 2560,
        g_high, be_high, w_sa, b_sa, inv4k, inv4k / 16.f,
        OFF_GNM + 64, OFF_GNR + 64, OFF_SV + 4);
    cudaEventRecord(evHigh0, s2);
    cudaStreamWaitEvent(s2, evOff1, 0);
    mdconv_mma_kernel<<<dim3(16, 2), 256, MD_SMEM_BYTES, s2>>>(
        OFF_X2N, 32, 32, OFF_OFFB1, 64, 64, 2, 1, OFF_W3HIGH, OFF_Y1H, 1024, 32, OFF_STAT + 5120);
    gn_finalize_kernel<<<2, 256, 0, s2>>>(OFF_STAT + 5120, OFF_STAT + 5632,
        g_high, be_high, w_sa, b_sa, inv1k, inv1k / 16.f,
        OFF_GNM + 96 + 64, OFF_GNR + 96 + 64, OFF_SV + 8 + 4);
    cudaEventRecord(evHigh1, s2);
    cudaStreamWaitEvent(s2, evWL, 0);
    mdconv_mma_kernel<<<dim3(16, 2), 256, MD_SMEM_BYTES, s2>>>(
        OFF_X1N, 64, 64, OFF_OFFB2, 32, 32, 1, 2, OFF_W3LOW, OFF_Y2L, 1024, 32, OFF_STAT + 7168);
    gn_finalize_kernel<<<2, 256, 0, s2>>>(OFF_STAT + 7168, OFF_STAT + 7680,
        g_low, be_low, w_sa, b_sa, inv1k, inv1k / 16.f,
        OFF_GNM + 192 + 32, OFF_GNR + 192 + 32, OFF_SV + 16 + 2);
    // L2 tail (mid2, low2 both on s2)
    combine_kernel<<<dim3(4, 256, 2), 256, 0, s2>>>(
        OFF_Y2M, OFF_Y2L, 0, 1, 0, 32, 1024, 16, 16, 0.f, 0.f,
        OFF_GNM + 192, OFF_GNR + 192, OFF_SV + 16,
        g_mid, be_mid, g_low, be_low, g_high, be_high,
        0.5f, OFF_SUMF2, OFF_P2 + 1024);
    dycoef_kernel<<<2, 1024, 0, s2>>>(OFF_P2 + 1024, inv1k, w_dy1, b_dy1, w_dy2, b_dy2,
                                      OFF_COEF + 4096);
    dyrelu_kernel<<<2 * 256 * 1024 / 256, 256, 0, s2>>>(OFF_SUMF2, OFF_COEF + 4096, 1024,
                                                        out + 2 * 256 * (16384 + 4096), 256 * 1024);
    cudaEventRecord(evL2, s2);

    // ---- s1: L1 tail (needs high1 from s2)
    cudaStreamWaitEvent(s1, evHigh1, 0);
    {
        float ry = 31.f / 63.f;
        combine_kernel<<<dim3(16, 256, 2), 256, 0, s1>>>(
            OFF_Y1M, OFF_Y1L, OFF_Y1H, 1, 1, 64, 4096, 32, 32, ry, ry,
            OFF_GNM + 96, OFF_GNR + 96, OFF_SV + 8,
            g_mid, be_mid, g_low, be_low, g_high, be_high,
            1.f / 3.f, OFF_SUMF1, OFF_P2 + 512);
        dycoef_kernel<<<2, 1024, 0, s1>>>(OFF_P2 + 512, inv4k, w_dy1, b_dy1, w_dy2, b_dy2,
                                          OFF_COEF + 2048);
        dyrelu_kernel<<<2 * 256 * 4096 / 256, 256, 0, s1>>>(OFF_SUMF1, OFF_COEF + 2048, 4096,
                                                            out + 2 * 256 * 16384, 256 * 4096);
    }
    cudaEventRecord(evL1, s1);

    // ---- main: L0 GN + tail (needs high0 from s2), then join everything.
    gn_finalize_kernel<<<2, 256>>>(OFF_STAT, OFF_STAT + 512,
        g_mid, be_mid, w_sa, b_sa, inv16k, inv16k / 16.f,
        OFF_GNM, OFF_GNR, OFF_SV);
    cudaStreamWaitEvent(0, evHigh0, 0);
    {
        float ry = 63.f / 127.f;
        combine_kernel<<<dim3(64, 256, 2), 256>>>(
            OFF_Y0M, 0, OFF_Y0H, 0, 1, 128, 16384, 64, 64, ry, ry,
            OFF_GNM, OFF_GNR, OFF_SV,
            g_mid, be_mid, g_low, be_low, g_high, be_high,
            0.5f, OFF_SUMF0, OFF_P2);
        dycoef_kernel<<<2, 1024>>>(OFF_P2, inv16k, w_dy1, b_dy1, w_dy2, b_dy2, OFF_COEF);
    }
    cudaStreamWaitEvent(0, evL1, 0);
    cudaStreamWaitEvent(0, evL2, 0);
    dyrelu_kernel<<<2 * 256 * 16384 / 256, 256>>>(OFF_SUMF0, OFF_COEF, 16384, out, 256 * 16384);
}

// round 15
// speedup vs baseline: 2.0544x; 1.0219x over previous
#include <cuda_runtime.h>
#include <cuda_fp16.h>
#include <math.h>
#include <stdint.h>

// ---------------------------------------------------------------------------
// DyHead-style MultiAttentionBlock. FP16 tensor-core mdconv + offconv,
// ldmatrix fragments, fp16 NHWC inputs, coalesced gather, triple-buffered
// cp.async B (distance 2), level-pipelined schedule on 3 streams.
// R15: offconv retiled to PX=64 (2x grid parallelism), prep moved off the
// main critical path (runs concurrently with the L0 transpose).
// B=2, C=256, levels H = {128, 64, 32}, GN groups = 16.
// ---------------------------------------------------------------------------

constexpr int BN = 2;
constexpr int C  = 256;

// ---- scratch layout (float units; X/W3 buffers hold halves in float slots) ----
constexpr size_t OFF_X0N   = 0;                         // 2*128*128*256
constexpr size_t OFF_X1N   = OFF_X0N   + 8388608;
constexpr size_t OFF_X2N   = OFF_X1N   + 2097152;
constexpr size_t OFF_OFFB0 = OFF_X2N   + 524288;        // 2*128*128*27
constexpr size_t OFF_OFFB1 = OFF_OFFB0 + 884736;
constexpr size_t OFF_OFFB2 = OFF_OFFB1 + 221184;
constexpr size_t OFF_Y0M   = OFF_OFFB2 + 55296;
constexpr size_t OFF_Y0H   = OFF_Y0M   + 8388608;
constexpr size_t OFF_Y1M   = OFF_Y0H   + 2097152;
constexpr size_t OFF_Y1L   = OFF_Y1M   + 2097152;
constexpr size_t OFF_Y1H   = OFF_Y1L   + 2097152;
constexpr size_t OFF_Y2M   = OFF_Y1H   + 524288;
constexpr size_t OFF_Y2L   = OFF_Y2M   + 524288;
constexpr size_t OFF_SUMF0 = OFF_Y2L   + 524288;
constexpr size_t OFF_SUMF1 = OFF_SUMF0 + 8388608;
constexpr size_t OFF_SUMF2 = OFF_SUMF1 + 2097152;
constexpr size_t OFF_W3MID = OFF_SUMF2 + 524288;        // half[9*256*256]
constexpr size_t OFF_W3LOW = OFF_W3MID + 589824;
constexpr size_t OFF_W3HIGH= OFF_W3LOW + 589824;
constexpr size_t OFF_W3OFF = OFF_W3HIGH+ 589824;        // half[9*32*256]
constexpr size_t OFF_STAT  = OFF_W3OFF + 73728;         // 3 lvl x 3 br x 1024
constexpr size_t OFF_GNM   = OFF_STAT  + 9216;          // 3 lvl x 96
constexpr size_t OFF_GNR   = OFF_GNM   + 288;
constexpr size_t OFF_SV    = OFF_GNR   + 288;           // 3 lvl x 8
constexpr size_t OFF_P2    = OFF_SV    + 24;            // 3 lvl x 512
constexpr size_t OFF_COEF  = OFF_P2    + 1536;          // 3 lvl x 2048
constexpr size_t SCRATCH_TOTAL = OFF_COEF + 6144;

// floats to zero each replay: STAT(9216)+GNM(288)+GNR(288)+SV(24)+P2(1536)
constexpr int ZERO_SPAN = 11352;

__device__ __align__(256) float g_scratch[SCRATCH_TOTAL];

// mdconv (PX=64) dynamic smem layout (bytes):
//   Ash : half [2][64*40]   at 0      (10240)
//   Bsh : half [3][256*40]  at 10240  (61440)
//   swt9: float[9][256]     at 71680  (9216)
//   sb9 : int  [9][256]     at 80896  (9216)
constexpr int MD_SMEM_BYTES = 90112;

__device__ __forceinline__ void mma_f16(float* d, const uint32_t* a, uint32_t b0, uint32_t b1) {
    asm volatile(
        "mma.sync.aligned.m16n8k16.row.col.f32.f16.f16.f32 "
        "{%0,%1,%2,%3},{%4,%5,%6,%7},{%8,%9},{%0,%1,%2,%3};\n"
        : "+f"(d[0]), "+f"(d[1]), "+f"(d[2]), "+f"(d[3])
        : "r"(a[0]), "r"(a[1]), "r"(a[2]), "r"(a[3]), "r"(b0), "r"(b1));
}

__device__ __forceinline__ void ldsm_x4(uint32_t* r, const half* p) {
    uint32_t a = (uint32_t)__cvta_generic_to_shared(p);
    asm volatile("ldmatrix.sync.aligned.m8n8.x4.shared.b16 {%0,%1,%2,%3}, [%4];"
        : "=r"(r[0]), "=r"(r[1]), "=r"(r[2]), "=r"(r[3]) : "r"(a));
}

__device__ __forceinline__ void cp_async16(uint32_t daddr, const void* src) {
    asm volatile("cp.async.cg.shared.global [%0], [%1], 16;\n" :: "r"(daddr), "l"(src));
}

// ---------------------------------------------------------------------------
// root: tiny first node so side streams can fork before any heavy work.
// ---------------------------------------------------------------------------
__global__ void root_kernel() {
    if (threadIdx.x == 0) g_scratch[OFF_SV] = 0.f;   // overwritten by prep/gn later
}

// ---------------------------------------------------------------------------
// prep: w_mid -> half [k][o][c], w_off -> half [k][o32][c], zero accumulators.
// ---------------------------------------------------------------------------
__global__ void prep_kernel(const float* __restrict__ w_mid, const float* __restrict__ w_off) {
    int bidx = blockIdx.x;
    if (bidx < 2304) {
        int idx = bidx * 256 + threadIdx.x;           // < 9*256*256
        int k = idx >> 16, o = (idx >> 8) & 255, c = idx & 255;
        ((half*)(g_scratch + OFF_W3MID))[idx] = __float2half(w_mid[(o * 256 + c) * 9 + k]);
    } else if (bidx < 2592) {
        int idx = (bidx - 2304) * 256 + threadIdx.x;  // < 9*32*256
        int k = idx >> 13, o = (idx >> 8) & 31, c = idx & 255;
        ((half*)(g_scratch + OFF_W3OFF))[idx] =
            __float2half(o < 27 ? w_off[(o * 256 + c) * 9 + k] : 0.f);
    } else {
        int idx = (bidx - 2592) * 256 + threadIdx.x;
        if (idx < ZERO_SPAN) g_scratch[OFF_STAT + idx] = 0.f;  // stats..P2 inclusive
    }
}

__global__ void reorder_w_half_kernel(const float* __restrict__ w, size_t out_o) {
    int idx = blockIdx.x * 256 + threadIdx.x;         // < 9*256*256
    int k = idx >> 16, o = (idx >> 8) & 255, c = idx & 255;
    ((half*)(g_scratch + out_o))[idx] = __float2half(w[(o * 256 + c) * 9 + k]);
}

// ---------------------------------------------------------------------------
// NCHW fp32 -> NHWC fp16 transpose.
// ---------------------------------------------------------------------------
__global__ void transpose_kernel(const float* __restrict__ in, size_t out_o, int HW) {
    __shared__ float t[32][33];
    int b = blockIdx.z;
    int hw0 = blockIdx.x * 32, c0 = blockIdx.y * 32;
    int tx = threadIdx.x, ty = threadIdx.y;  // 32 x 8
    #pragma unroll
    for (int i = 0; i < 32; i += 8)
        t[ty + i][tx] = in[((size_t)b * C + c0 + ty + i) * HW + hw0 + tx];
    __syncthreads();
    half* xh = (half*)(g_scratch + out_o);
    #pragma unroll
    for (int i = 0; i < 32; i += 8)
        xh[((size_t)b * HW + hw0 + ty + i) * C + c0 + tx] = __float2half(t[tx][ty + i]);
}

// ---------------------------------------------------------------------------
// Offset conv via fp16 MMA + ldmatrix. 3x3, 256 -> 27 (padded 32).
// Block: 64 px x 32 o, 256 threads (4M warps x 2N warps). B triple-buffered.
// PX=64 doubles grid parallelism vs the old 128-px tile (latency-bound kernel).
// ---------------------------------------------------------------------------
__global__ __launch_bounds__(256) void offconv_mma_kernel(
    size_t xn_o, int H, int W,
    const float* __restrict__ bias, size_t out_o)
{
    __shared__ half Ash[2][64 * 40];
    __shared__ half Bsh[3][32 * 40];

    int b = blockIdx.y, tile = blockIdx.x, tid = threadIdx.x;
    int lane = tid & 31, warp = tid >> 5;
    int warpM = warp >> 1, warpN = warp & 1;   // 4 x 16px, 2 x 16o
    const half* xn = (const half*)(g_scratch + xn_o);
    const half* wh = (const half*)(g_scratch + OFF_W3OFF);

    float acc[2][4];
    #pragma unroll
    for (int nt = 0; nt < 2; ++nt)
        #pragma unroll
        for (int r = 0; r < 4; ++r) acc[nt][r] = 0.f;

    int tpx = tid >> 2, tseg = tid & 3;
    int p = tile * 64 + tpx;
    int ph = p / W, pw = p - ph * W;

    uint32_t bs_saddr = (uint32_t)__cvta_generic_to_shared(&Bsh[0][0]);

    uint4 gr;
    auto gather_ldg = [&](int s) {
        int k = s >> 3, c0 = (s & 7) << 5;
        int dy = k / 3 - 1, dx = k % 3 - 1;
        int y = ph + dy, x = pw + dx;
        bool valid = (y >= 0 && y < H && x >= 0 && x < W);
        const half* src = xn + ((size_t)(b * H + y) * W + x) * 256 + c0 + tseg * 8;
        gr = valid ? *(const uint4*)src : make_uint4(0, 0, 0, 0);
    };
    auto sts_a = [&](int buf) {
        *(uint4*)&Ash[buf][tpx * 40 + tseg * 8] = gr;
    };
    auto cpasync_b = [&](int s, int buf) {
        int k = s >> 3, c0 = (s & 7) << 5;
        if (tid < 128) {
            int o = tid >> 2, seg = tid & 3;
            cp_async16(bs_saddr + (uint32_t)(buf * 2560 + o * 80 + seg * 16),
                       wh + ((size_t)(k * 32 + o) << 8) + c0 + seg * 8);
        }
        asm volatile("cp.async.commit_group;\n");
    };

    gather_ldg(0);
    cpasync_b(0, 0);
    cpasync_b(1, 1);

    int lg = lane >> 3, lr = lane & 7;
    int bufB = 0, slot2 = 2;

    for (int s = 0; s < 72; ++s) {
        int cb = s & 1;
        sts_a(cb);
        if (s < 71) gather_ldg(s + 1);
        if (s < 71) asm volatile("cp.async.wait_group 1;\n");
        else        asm volatile("cp.async.wait_group 0;\n");
        __syncthreads();
        if (s < 70) cpasync_b(s + 2, slot2);

        const half* Ab = Ash[cb];
        const half* Bb = Bsh[bufB];
        #pragma unroll
        for (int ks = 0; ks < 2; ++ks) {
            int kb = ks * 16 + (lg >> 1) * 8;
            uint32_t a[4];
            ldsm_x4(a, Ab + (warpM * 16 + (lg & 1) * 8 + lr) * 40 + kb);
            uint32_t bf[4];
            ldsm_x4(bf, Bb + (warpN * 16 + (lg & 1) * 8 + lr) * 40 + kb);
            mma_f16(acc[0], a, bf[0], bf[2]);
            mma_f16(acc[1], a, bf[1], bf[3]);
        }
        __syncthreads();
        bufB = (bufB == 2) ? 0 : bufB + 1;
        slot2 = (slot2 == 2) ? 0 : slot2 + 1;
    }

    // epilogue: [b][px][27]
    int HWl = H * W;
    int pxb = tile * 64 + warpM * 16 + (lane >> 2);
    #pragma unroll
    for (int nt = 0; nt < 2; ++nt) {
        int o = warpN * 16 + nt * 8 + 2 * (lane & 3);
        float bv0 = (o < 27) ? bias[o] : 0.f;
        float bv1 = (o + 1 < 27) ? bias[o + 1] : 0.f;
        #pragma unroll
        for (int rr = 0; rr < 2; ++rr) {
            int px = pxb + rr * 8;
            float v0 = acc[nt][rr * 2 + 0] + bv0;
            float v1 = acc[nt][rr * 2 + 1] + bv1;
            size_t ob = out_o + ((size_t)b * HWl + px) * 27;
            if (o < 27) {
                if (o >= 18) v0 = 1.f / (1.f + expf(-v0));
                g_scratch[ob + o] = v0;
            }
            if (o + 1 < 27) {
                if (o + 1 >= 18) v1 = 1.f / (1.f + expf(-v1));
                g_scratch[ob + o + 1] = v1;
            }
        }
    }
}

// ---------------------------------------------------------------------------
// Modulated deformable conv: fused bilinear gather + FP16 MMA, triple-buffered
// cp.async B (distance 2), per-k register gather table, fused stats.
// Block: 64 px x 256 o, 256 threads (8 warps = 2M x 4N), 2 blocks/SM.
// ---------------------------------------------------------------------------
__global__ __launch_bounds__(256, 2) void mdconv_mma_kernel(
    size_t xn_o, int Hi, int Wi,
    size_t off_o, int offH, int offW, int offmul,
    int stride, size_t w3_o,
    size_t y_o, int HWo, int Wo, size_t stat_o)
{
    constexpr int PX = 64;
    constexpr int ASH_HALF = PX * 40;

    extern __shared__ char smraw[];
    half*  Ash  = (half*)smraw;               // [2][64*40]
    half*  Bsh  = (half*)(smraw + 10240);     // [3][256*40]
    float* swt9 = (float*)(smraw + 71680);    // [9][4*64]
    int*   sb9  = (int*)(smraw + 80896);      // [9][4*64]

    int b = blockIdx.y, tile = blockIdx.x, tid = threadIdx.x;
    int lane = tid & 31, warp = tid >> 5;
    int warpM = warp & 1, warpN = warp >> 1;

    const half* xn = (const half*)(g_scratch + xn_o);
    const half* w3h = (const half*)(g_scratch + w3_o);

    // precompute gather tables for all 9 taps
    for (int it = tid; it < 9 * PX; it += 256) {
        int k = it >> 6, p = it & 63;
        int pg = tile * PX + p;
        int h = pg / Wo, w = pg - h * Wo;
        size_t ob = off_o + ((size_t)(b * offH + h * offmul) * offW + w * offmul) * 27;
        float oy = g_scratch[ob + 2 * k];
        float ox = g_scratch[ob + 2 * k + 1];
        float m  = g_scratch[ob + 18 + k];
        float py  = (float)(h * stride - 1 + k / 3) + oy;
        float pxx = (float)(w * stride - 1 + k % 3) + ox;
        float fy = floorf(py), fx = floorf(pxx);
        int y0 = (int)fy, x0 = (int)fx;
        float wy = py - fy, wx = pxx - fx;
        int y1 = y0 + 1, x1 = x0 + 1;
        float vy0 = (y0 >= 0 && y0 < Hi) ? 1.f : 0.f;
        float vy1 = (y1 >= 0 && y1 < Hi) ? 1.f : 0.f;
        float vx0 = (x0 >= 0 && x0 < Wi) ? 1.f : 0.f;
        float vx1 = (x1 >= 0 && x1 < Wi) ? 1.f : 0.f;
        int y0c = min(max(y0, 0), Hi - 1), y1c = min(max(y1, 0), Hi - 1);
        int x0c = min(max(x0, 0), Wi - 1), x1c = min(max(x1, 0), Wi - 1);
        int kb = k * 4 * PX + p;
        swt9[kb]          = (1.f - wy) * (1.f - wx) * m * vy0 * vx0;
        swt9[kb + PX]     = (1.f - wy) * wx * m * vy0 * vx1;
        swt9[kb + 2 * PX] = wy * (1.f - wx) * m * vy1 * vx0;
        swt9[kb + 3 * PX] = wy * wx * m * vy1 * vx1;
        sb9[kb]          = ((b * Hi + y0c) * Wi + x0c) * 256;
        sb9[kb + PX]     = ((b * Hi + y0c) * Wi + x1c) * 256;
        sb9[kb + 2 * PX] = ((b * Hi + y1c) * Wi + x0c) * 256;
        sb9[kb + 3 * PX] = ((b * Hi + y1c) * Wi + x1c) * 256;
    }
    __syncthreads();

    float acc[2][8][4];
    #pragma unroll
    for (int mt = 0; mt < 2; ++mt)
        #pragma unroll
        for (int nt = 0; nt < 8; ++nt)
            #pragma unroll
            for (int r = 0; r < 4; ++r) acc[mt][nt][r] = 0.f;

    // coalesced gather mapping: 4 consecutive lanes = 4 segments of one px
    int gpx = tid >> 2;   // 0..63
    int gcq = tid & 3;    // 16B segment

    uint32_t bs_saddr = (uint32_t)__cvta_generic_to_shared(Bsh);

    // per-k register-resident table (reloaded every 8 chunks)
    float gw0, gw1, gw2, gw3;
    int b00, b01, b10, b11;
    uint4 gv[4];

    auto load_table = [&](int kk) {
        int kb = kk * 4 * PX + gpx;
        gw0 = swt9[kb]; gw1 = swt9[kb + PX]; gw2 = swt9[kb + 2 * PX]; gw3 = swt9[kb + 3 * PX];
        b00 = sb9[kb];  b01 = sb9[kb + PX];  b10 = sb9[kb + 2 * PX]; b11 = sb9[kb + 3 * PX];
    };
    auto gather_ldg = [&](int s) {
        int cofs = ((s & 7) << 5) + gcq * 8;
        gv[0] = *(const uint4*)(xn + b00 + cofs);
        gv[1] = *(const uint4*)(xn + b01 + cofs);
        gv[2] = *(const uint4*)(xn + b10 + cofs);
        gv[3] = *(const uint4*)(xn + b11 + cofs);
    };
    auto combine_sts = [&](int buf) {
        uint4 outv;
        half2* po = (half2*)&outv;
        #pragma unroll
        for (int j = 0; j < 4; ++j) {
            float2 f00 = __half22float2(((const half2*)&gv[0])[j]);
            float2 f01 = __half22float2(((const half2*)&gv[1])[j]);
            float2 f10 = __half22float2(((const half2*)&gv[2])[j]);
            float2 f11 = __half22float2(((const half2*)&gv[3])[j]);
            float rx = gw0 * f00.x + gw1 * f01.x + gw2 * f10.x + gw3 * f11.x;
            float ry = gw0 * f00.y + gw1 * f01.y + gw2 * f10.y + gw3 * f11.y;
            po[j] = __floats2half2_rn(rx, ry);
        }
        *(uint4*)&Ash[buf * ASH_HALF + gpx * 40 + gcq * 8] = outv;
    };
    auto cpasync_b = [&](int s, int buf) {
        int kk = s >> 3, c0n = (s & 7) << 5;
        const half* wsrc = w3h + ((size_t)kk << 16) + c0n;   // [k][o][c], row = 256 halves
        #pragma unroll
        for (int it = 0; it < 4; ++it) {
            int e = it * 256 + tid;
            int o = e >> 2, seg = e & 3;
            cp_async16(bs_saddr + (uint32_t)(buf * 20480 + o * 80 + seg * 16),
                       wsrc + o * 256 + seg * 8);
        }
        asm volatile("cp.async.commit_group;\n");
    };

    load_table(0);
    gather_ldg(0);
    cpasync_b(0, 0);
    cpasync_b(1, 1);

    int lg = lane >> 3, lr = lane & 7;
    int bufB = 0, slot2 = 2;

    for (int s = 0; s < 72; ++s) {
        int cb = s & 1;
        combine_sts(cb);            // uses table+gv of chunk s
        if (s < 71) {
            if (((s + 1) & 7) == 0) load_table((s + 1) >> 3);
            gather_ldg(s + 1);
        }
        if (s < 71) asm volatile("cp.async.wait_group 1;\n");
        else        asm volatile("cp.async.wait_group 0;\n");
        __syncthreads();
        if (s < 70) cpasync_b(s + 2, slot2);

        const half* Ab = Ash + cb * ASH_HALF;
        const half* Bb = Bsh + bufB * 10240;
        #pragma unroll
        for (int ks = 0; ks < 2; ++ks) {
            int kb = ks * 16 + (lg >> 1) * 8;
            uint32_t a[2][4];
            #pragma unroll
            for (int mt = 0; mt < 2; ++mt)
                ldsm_x4(a[mt], Ab + (warpM * 32 + mt * 16 + (lg & 1) * 8 + lr) * 40 + kb);
            #pragma unroll
            for (int j = 0; j < 4; ++j) {
                uint32_t bf[4];
                ldsm_x4(bf, Bb + (warpN * 64 + j * 16 + (lg & 1) * 8 + lr) * 40 + kb);
                mma_f16(acc[0][2 * j],     a[0], bf[0], bf[2]);
                mma_f16(acc[1][2 * j],     a[1], bf[0], bf[2]);
                mma_f16(acc[0][2 * j + 1], a[0], bf[1], bf[3]);
                mma_f16(acc[1][2 * j + 1], a[1], bf[1], bf[3]);
            }
        }
        bufB = (bufB == 2) ? 0 : bufB + 1;
        slot2 = (slot2 == 2) ? 0 : slot2 + 1;
    }

    // epilogue: Y [b][o][HWo] + fused stats
    float* yp = g_scratch + y_o + (size_t)b * 256 * HWo;
    float* st_sum = g_scratch + stat_o + b * 256;
    float* st_sq  = g_scratch + stat_o + 512 + b * 256;
    int px0 = tile * PX + warpM * 32 + (lane >> 2);
    #pragma unroll
    for (int nt = 0; nt < 8; ++nt) {
        int o = warpN * 64 + nt * 8 + 2 * (lane & 3);
        float s0 = 0.f, s1 = 0.f, q0 = 0.f, q1 = 0.f;
        #pragma unroll
        for (int mt = 0; mt < 2; ++mt) {
            int px = px0 + mt * 16;
            float v0 = acc[mt][nt][0], v1 = acc[mt][nt][1];
            float v2 = acc[mt][nt][2], v3 = acc[mt][nt][3];
            yp[(size_t)o * HWo + px]           = v0;
            yp[(size_t)(o + 1) * HWo + px]     = v1;
            yp[(size_t)o * HWo + px + 8]       = v2;
            yp[(size_t)(o + 1) * HWo + px + 8] = v3;
            s0 += v0 + v2; s1 += v1 + v3;
            q0 += v0 * v0 + v2 * v2; q1 += v1 * v1 + v3 * v3;
        }
        #pragma unroll
        for (int off = 16; off >= 4; off >>= 1) {
            s0 += __shfl_down_sync(0xffffffffu, s0, off);
            s1 += __shfl_down_sync(0xffffffffu, s1, off);
            q0 += __shfl_down_sync(0xffffffffu, q0, off);
            q1 += __shfl_down_sync(0xffffffffu, q1, off);
        }
        if (lane < 4) {
            atomicAdd(&st_sum[o], s0);
            atomicAdd(&st_sum[o + 1], s1);
            atomicAdd(&st_sq[o], q0);
            atomicAdd(&st_sq[o + 1], q1);
        }
    }
}

// ---------------------------------------------------------------------------
// GN finalize + scale-attn scalar (stats pre-zeroed by prep each replay).
// ---------------------------------------------------------------------------
__global__ void gn_finalize_kernel(
    size_t sum_o, size_t sq_o,
    const float* __restrict__ gamma, const float* __restrict__ beta,
    const float* __restrict__ w_sa, const float* __restrict__ b_sa,
    float inv_hw, float inv_cnt,
    size_t gnm_o, size_t gnr_o, size_t sv_o)
{
    int b = blockIdx.x, t = threadIdx.x;  // 256
    __shared__ float ss[256], qq[256], gm[16], gr[16], red[256];
    ss[t] = g_scratch[sum_o + b * 256 + t];
    qq[t] = g_scratch[sq_o + b * 256 + t];
    __syncthreads();
    if (t < 16) {
        float S = 0.f, Q = 0.f;
        #pragma unroll
        for (int j = 0; j < 16; ++j) { S += ss[t * 16 + j]; Q += qq[t * 16 + j]; }
        float mean = S * inv_cnt;
        float var = Q * inv_cnt - mean * mean;
        float r = rsqrtf(var + 1e-5f);
        gm[t] = mean; gr[t] = r;
        g_scratch[gnm_o + b * 16 + t] = mean;
        g_scratch[gnr_o + b * 16 + t] = r;
    }
    __syncthreads();
    int g = t >> 4;
    float p = gamma[t] * (ss[t] * inv_hw - gm[g]) * gr[g] + beta[t];
    red[t] = p * w_sa[t];
    __syncthreads();
    for (int off = 128; off; off >>= 1) {
        if (t < off) red[t] += red[t + off];
        __syncthreads();
    }
    if (t == 0) {
        float x = fmaxf(red[0] + b_sa[0], 0.f);
        g_scratch[sv_o + b] = fminf(x + 3.f, 6.f) * (1.f / 6.f);
    }
}

// ---------------------------------------------------------------------------
// Combine branches + pooled sums.
// ---------------------------------------------------------------------------
__global__ void combine_kernel(
    size_t ymid_o, size_t ylow_o, size_t yhigh_o,
    int hasLow, int hasHigh, int W, int HW, int Hh, int Wh, float ry, float rx,
    size_t gnm_o, size_t gnr_o, size_t sv_o,
    const float* __restrict__ gw_mid, const float* __restrict__ gb_mid,
    const float* __restrict__ gw_low, const float* __restrict__ gb_low,
    const float* __restrict__ gw_high, const float* __restrict__ gb_high,
    float inv_n, size_t sumf_o, size_t p2_o)
{
    int b = blockIdx.z, c = blockIdx.y;
    int px = blockIdx.x * 256 + threadIdx.x;
    int g = c >> 4;
    int gi = b * 16 + g;
    size_t base = ((size_t)(b * 256 + c)) * HW;

    float v = g_scratch[sv_o + b] *
              (gw_mid[c] * (g_scratch[ymid_o + base + px] - g_scratch[gnm_o + gi]) * g_scratch[gnr_o + gi] + gb_mid[c]);
    if (hasLow)
        v += g_scratch[sv_o + 2 + b] *
             (gw_low[c] * (g_scratch[ylow_o + base + px] - g_scratch[gnm_o + 32 + gi]) * g_scratch[gnr_o + 32 + gi] + gb_low[c]);
    if (hasHigh) {
        int h = px / W, w = px - h * W;
        float sy = h * ry, sx = w * rx;
        int yl = (int)sy; int yh2 = min(yl + 1, Hh - 1);
        int xl = (int)sx; int xh = min(xl + 1, Wh - 1);
        float wy = sy - (float)yl, wx = sx - (float)xl;
        const float* hp = g_scratch + yhigh_o + ((size_t)(b * 256 + c)) * Hh * Wh;
        float t0 = hp[yl * Wh + xl] * (1.f - wx) + hp[yl * Wh + xh] * wx;
        float t1 = hp[yh2 * Wh + xl] * (1.f - wx) + hp[yh2 * Wh + xh] * wx;
        float raw = t0 * (1.f - wy) + t1 * wy;
        v += g_scratch[sv_o + 4 + b] *
             (gw_high[c] * (raw - g_scratch[gnm_o + 64 + gi]) * g_scratch[gnr_o + 64 + gi] + gb_high[c]);
    }
    v *= inv_n;
    g_scratch[sumf_o + base + px] = v;

    float r = v;
    #pragma unroll
    for (int o = 16; o; o >>= 1) r += __shfl_down_sync(0xffffffffu, r, o);
    __shared__ float wsum[8];
    if ((threadIdx.x & 31) == 0) wsum[threadIdx.x >> 5] = r;
    __syncthreads();
    if (threadIdx.x == 0) {
        float tt = 0.f;
        #pragma unroll
        for (int i = 0; i < 8; ++i) tt += wsum[i];
        atomicAdd(&g_scratch[p2_o + b * 256 + c], tt);
    }
}

// ---------------------------------------------------------------------------
// DyReLU coefficients.
// ---------------------------------------------------------------------------
__global__ void dycoef_kernel(size_t p2_o, float inv_hw,
    const float* __restrict__ w1, const float* __restrict__ b1,
    const float* __restrict__ w2, const float* __restrict__ b2,
    size_t coef_o)
{
    int b = blockIdx.x, t = threadIdx.x;  // 1024
    __shared__ float pm[256], hb[64];
    if (t < 256) pm[t] = g_scratch[p2_o + b * 256 + t] * inv_hw;
    __syncthreads();
    if (t < 64) {
        float a = b1[t];
        for (int cx = 0; cx < 256; ++cx) a += pm[cx] * w1[t * 256 + cx];
        hb[t] = fmaxf(a, 0.f);
    }
    __syncthreads();
    float a = b2[t];
    #pragma unroll
    for (int i = 0; i < 64; ++i) a += hb[i] * w2[t * 64 + i];
    float hs = fminf(fmaxf(a + 3.f, 0.f), 6.f) * (1.f / 6.f);
    g_scratch[coef_o + b * 1024 + t] = hs - 0.5f;
}

// ---------------------------------------------------------------------------
// Apply DyReLU, write final output.
// ---------------------------------------------------------------------------
__global__ void dyrelu_kernel(size_t sumf_o, size_t coef_o, int HW, float* __restrict__ outp, int CHW) {
    int idx = blockIdx.x * 256 + threadIdx.x;
    int b = idx / CHW;
    int c = (idx - b * CHW) / HW;
    const float* cf = g_scratch + coef_o + b * 1024;
    float x = g_scratch[sumf_o + idx];
    float a1 = cf[c] * 2.f + 1.f, bb1 = cf[256 + c];
    float a2 = cf[512 + c] * 2.f, bb2 = cf[768 + c];
    outp[idx] = fmaxf(x * a1 + bb1, x * a2 + bb2);
}

// ---------------------------------------------------------------------------
// Host orchestration: level-pipelined schedule on 3 streams (main + s1 + s2),
// side streams event-forked from the capture stream; prep runs concurrently
// with the L0 transpose.
// ---------------------------------------------------------------------------
extern "C" void kernel_launch(void* const* d_in, const int* in_sizes, int n_in,
                              void* d_out, int out_size) {
    (void)in_sizes; (void)n_in; (void)out_size;
    const float* x0     = (const float*)d_in[0];
    const float* x1     = (const float*)d_in[1];
    const float* x2     = (const float*)d_in[2];
    const float* w_off  = (const float*)d_in[3];
    const float* b_off  = (const float*)d_in[4];
    const float* w_mid  = (const float*)d_in[5];
    const float* g_mid  = (const float*)d_in[6];
    const float* be_mid = (const float*)d_in[7];
    const float* w_low  = (const float*)d_in[8];
    const float* g_low  = (const float*)d_in[9];
    const float* be_low = (const float*)d_in[10];
    const float* w_high = (const float*)d_in[11];
    const float* g_high = (const float*)d_in[12];
    const float* be_high= (const float*)d_in[13];
    const float* w_sa   = (const float*)d_in[14];
    const float* b_sa   = (const float*)d_in[15];
    const float* w_dy1  = (const float*)d_in[16];
    const float* b_dy1  = (const float*)d_in[17];
    const float* w_dy2  = (const float*)d_in[18];
    const float* b_dy2  = (const float*)d_in[19];
    float* out = (float*)d_out;

    static cudaStream_t s1, s2;
    static cudaEvent_t evRoot, evT0, evT1, evPrep, evOff0, evOff1, evWL;
    static cudaEvent_t evHigh0, evHigh1, evL1, evL2;
    static bool inited = false;
    if (!inited) {
        cudaFuncSetAttribute(mdconv_mma_kernel,
                             cudaFuncAttributeMaxDynamicSharedMemorySize, MD_SMEM_BYTES);
        cudaStreamCreateWithFlags(&s1, cudaStreamNonBlocking);
        cudaStreamCreateWithFlags(&s2, cudaStreamNonBlocking);
        cudaEvent_t* evs[] = {&evRoot, &evT0, &evT1, &evPrep, &evOff0, &evOff1, &evWL,
                              &evHigh0, &evHigh1, &evL1, &evL2};
        for (auto e : evs) cudaEventCreateWithFlags(e, cudaEventDisableTiming);
        inited = true;
    }

    dim3 tblk(32, 8);
    const float inv16k = 1.f / 16384.f, inv4k = 1.f / 4096.f, inv1k = 1.f / 1024.f;

    // ---- main: tiny root node, fork side streams, then L0 chain.
    root_kernel<<<1, 32>>>();                                              // launch 1
    cudaEventRecord(evRoot, 0);
    cudaStreamWaitEvent(s1, evRoot, 0);
    cudaStreamWaitEvent(s2, evRoot, 0);

    transpose_kernel<<<dim3(512, 8, 2), tblk>>>(x0, OFF_X0N, 16384);      // main
    cudaEventRecord(evT0, 0);

    // ---- s2: prep first (concurrent with T0), then its own chain.
    prep_kernel<<<2637, 256, 0, s2>>>(w_mid, w_off);
    cudaEventRecord(evPrep, s2);

    // ---- main: off0 needs T0 (same stream) + prep (event), then mid0.
    cudaStreamWaitEvent(0, evPrep, 0);
    offconv_mma_kernel<<<dim3(256, 2), 256>>>(OFF_X0N, 128, 128, b_off, OFF_OFFB0);
    cudaEventRecord(evOff0, 0);
    mdconv_mma_kernel<<<dim3(256, 2), 256, MD_SMEM_BYTES>>>(
        OFF_X0N, 128, 128, OFF_OFFB0, 128, 128, 1, 1, OFF_W3MID, OFF_Y0M, 16384, 128, OFF_STAT);

    // ---- s1: L1 chain + low1 + L1 tail
    transpose_kernel<<<dim3(128, 8, 2), tblk, 0, s1>>>(x1, OFF_X1N, 4096);
    cudaEventRecord(evT1, s1);
    reorder_w_half_kernel<<<2304, 256, 0, s1>>>(w_low, OFF_W3LOW);
    cudaEventRecord(evWL, s1);
    cudaStreamWaitEvent(s1, evPrep, 0);
    offconv_mma_kernel<<<dim3(64, 2), 256, 0, s1>>>(OFF_X1N, 64, 64, b_off, OFF_OFFB1);
    cudaEventRecord(evOff1, s1);
    mdconv_mma_kernel<<<dim3(64, 2), 256, MD_SMEM_BYTES, s1>>>(
        OFF_X1N, 64, 64, OFF_OFFB1, 64, 64, 1, 1, OFF_W3MID, OFF_Y1M, 4096, 64, OFF_STAT + 3072);
    gn_finalize_kernel<<<2, 256, 0, s1>>>(OFF_STAT + 3072, OFF_STAT + 3584,
        g_mid, be_mid, w_sa, b_sa, inv4k, inv4k / 16.f,
        OFF_GNM + 96, OFF_GNR + 96, OFF_SV + 8);
    cudaStreamWaitEvent(s1, evT0, 0);
    mdconv_mma_kernel<<<dim3(64, 2), 256, MD_SMEM_BYTES, s1>>>(
        OFF_X0N, 128, 128, OFF_OFFB1, 64, 64, 1, 2, OFF_W3LOW, OFF_Y1L, 4096, 64, OFF_STAT + 4096);
    gn_finalize_kernel<<<2, 256, 0, s1>>>(OFF_STAT + 4096, OFF_STAT + 4608,
        g_low, be_low, w_sa, b_sa, inv4k, inv4k / 16.f,
        OFF_GNM + 96 + 32, OFF_GNR + 96 + 32, OFF_SV + 8 + 2);

    // ---- s2: L2 chain + high0 + high1 + low2 + L2 tail (after prep)
    transpose_kernel<<<dim3(32, 8, 2), tblk, 0, s2>>>(x2, OFF_X2N, 1024);
    reorder_w_half_kernel<<<2304, 256, 0, s2>>>(w_high, OFF_W3HIGH);
    offconv_mma_kernel<<<dim3(16, 2), 256, 0, s2>>>(OFF_X2N, 32, 32, b_off, OFF_OFFB2);
    mdconv_mma_kernel<<<dim3(16, 2), 256, MD_SMEM_BYTES, s2>>>(
        OFF_X2N, 32, 32, OFF_OFFB2, 32, 32, 1, 1, OFF_W3MID, OFF_Y2M, 1024, 32, OFF_STAT + 6144);
    gn_finalize_kernel<<<2, 256, 0, s2>>>(OFF_STAT + 6144, OFF_STAT + 6656,
        g_mid, be_mid, w_sa, b_sa, inv1k, inv1k / 16.f,
        OFF_GNM + 192, OFF_GNR + 192, OFF_SV + 16);
    cudaStreamWaitEvent(s2, evOff0, 0);
    cudaStreamWaitEvent(s2, evT1, 0);
    mdconv_mma_kernel<<<dim3(64, 2), 256, MD_SMEM_BYTES, s2>>>(
        OFF_X1N, 64, 64, OFF_OFFB0, 128, 128, 2, 1, OFF_W3HIGH, OFF_Y0H, 4096, 64, OFF_STAT + 2048);
    gn_finalize_kernel<<<2, 256, 0, s2>>>(OFF_STAT + 2048, OFF_STAT + 2560,
        g_high, be_high, w_sa, b_sa, inv4k, inv4k / 16.f,
        OFF_GNM + 64, OFF_GNR + 64, OFF_SV + 4);
    cudaEventRecord(evHigh0, s2);
    cudaStreamWaitEvent(s2, evOff1, 0);
    mdconv_mma_kernel<<<dim3(16, 2), 256, MD_SMEM_BYTES, s2>>>(
        OFF_X2N, 32, 32, OFF_OFFB1, 64, 64, 2, 1, OFF_W3HIGH, OFF_Y1H, 1024, 32, OFF_STAT + 5120);
    gn_finalize_kernel<<<2, 256, 0, s2>>>(OFF_STAT + 5120, OFF_STAT + 5632,
        g_high, be_high, w_sa, b_sa, inv1k, inv1k / 16.f,
        OFF_GNM + 96 + 64, OFF_GNR + 96 + 64, OFF_SV + 8 + 4);
    cudaEventRecord(evHigh1, s2);
    cudaStreamWaitEvent(s2, evWL, 0);
    mdconv_mma_kernel<<<dim3(16, 2), 256, MD_SMEM_BYTES, s2>>>(
        OFF_X1N, 64, 64, OFF_OFFB2, 32, 32, 1, 2, OFF_W3LOW, OFF_Y2L, 1024, 32, OFF_STAT + 7168);
    gn_finalize_kernel<<<2, 256, 0, s2>>>(OFF_STAT + 7168, OFF_STAT + 7680,
        g_low, be_low, w_sa, b_sa, inv1k, inv1k / 16.f,
        OFF_GNM + 192 + 32, OFF_GNR + 192 + 32, OFF_SV + 16 + 2);
    // L2 tail (mid2, low2 both on s2)
    combine_kernel<<<dim3(4, 256, 2), 256, 0, s2>>>(
        OFF_Y2M, OFF_Y2L, 0, 1, 0, 32, 1024, 16, 16, 0.f, 0.f,
        OFF_GNM + 192, OFF_GNR + 192, OFF_SV + 16,
        g_mid, be_mid, g_low, be_low, g_high, be_high,
        0.5f, OFF_SUMF2, OFF_P2 + 1024);
    dycoef_kernel<<<2, 1024, 0, s2>>>(OFF_P2 + 1024, inv1k, w_dy1, b_dy1, w_dy2, b_dy2,
                                      OFF_COEF + 4096);
    dyrelu_kernel<<<2 * 256 * 1024 / 256, 256, 0, s2>>>(OFF_SUMF2, OFF_COEF + 4096, 1024,
                                                        out + 2 * 256 * (16384 + 4096), 256 * 1024);
    cudaEventRecord(evL2, s2);

    // ---- s1: L1 tail (needs high1 from s2)
    cudaStreamWaitEvent(s1, evHigh1, 0);
    {
        float ry = 31.f / 63.f;
        combine_kernel<<<dim3(16, 256, 2), 256, 0, s1>>>(
            OFF_Y1M, OFF_Y1L, OFF_Y1H, 1, 1, 64, 4096, 32, 32, ry, ry,
            OFF_GNM + 96, OFF_GNR + 96, OFF_SV + 8,
            g_mid, be_mid, g_low, be_low, g_high, be_high,
            1.f / 3.f, OFF_SUMF1, OFF_P2 + 512);
        dycoef_kernel<<<2, 1024, 0, s1>>>(OFF_P2 + 512, inv4k, w_dy1, b_dy1, w_dy2, b_dy2,
                                          OFF_COEF + 2048);
        dyrelu_kernel<<<2 * 256 * 4096 / 256, 256, 0, s1>>>(OFF_SUMF1, OFF_COEF + 2048, 4096,
                                                            out + 2 * 256 * 16384, 256 * 4096);
    }
    cudaEventRecord(evL1, s1);

    // ---- main: L0 GN + tail (needs high0 from s2), then join everything.
    gn_finalize_kernel<<<2, 256>>>(OFF_STAT, OFF_STAT + 512,
        g_mid, be_mid, w_sa, b_sa, inv16k, inv16k / 16.f,
        OFF_GNM, OFF_GNR, OFF_SV);
    cudaStreamWaitEvent(0, evHigh0, 0);
    {
        float ry = 63.f / 127.f;
        combine_kernel<<<dim3(64, 256, 2), 256>>>(
            OFF_Y0M, 0, OFF_Y0H, 0, 1, 128, 16384, 64, 64, ry, ry,
            OFF_GNM, OFF_GNR, OFF_SV,
            g_mid, be_mid, g_low, be_low, g_high, be_high,
            0.5f, OFF_SUMF0, OFF_P2);
        dycoef_kernel<<<2, 1024>>>(OFF_P2, inv16k, w_dy1, b_dy1, w_dy2, b_dy2, OFF_COEF);
    }
    cudaStreamWaitEvent(0, evL1, 0);
    cudaStreamWaitEvent(0, evL2, 0);
    dyrelu_kernel<<<2 * 256 * 16384 / 256, 256>>>(OFF_SUMF0, OFF_COEF, 16384, out, 256 * 16384);
}

// round 16
// speedup vs baseline: 2.2201x; 1.0806x over previous
#include <cuda_runtime.h>
#include <cuda_fp16.h>
#include <math.h>
#include <stdint.h>

// ---------------------------------------------------------------------------
// DyHead-style MultiAttentionBlock. FP16 tensor-core mdconv + offconv,
// ldmatrix fragments, fp16 NHWC inputs, coalesced gather, triple-buffered
// cp.async B (distance 2). R16: ALL seven deformable convs batched into ONE
// super-launch via a __constant__ descriptor table (full-wave packing);
// GN finalizes batched into one launch. 3-stream pre/tail schedule.
// B=2, C=256, levels H = {128, 64, 32}, GN groups = 16.
// ---------------------------------------------------------------------------

constexpr int BN = 2;
constexpr int C  = 256;

// ---- scratch layout (float units; X/W3 buffers hold halves in float slots) ----
constexpr size_t OFF_X0N   = 0;                         // 2*128*128*256
constexpr size_t OFF_X1N   = OFF_X0N   + 8388608;
constexpr size_t OFF_X2N   = OFF_X1N   + 2097152;
constexpr size_t OFF_OFFB0 = OFF_X2N   + 524288;        // 2*128*128*27
constexpr size_t OFF_OFFB1 = OFF_OFFB0 + 884736;
constexpr size_t OFF_OFFB2 = OFF_OFFB1 + 221184;
constexpr size_t OFF_Y0M   = OFF_OFFB2 + 55296;
constexpr size_t OFF_Y0H   = OFF_Y0M   + 8388608;
constexpr size_t OFF_Y1M   = OFF_Y0H   + 2097152;
constexpr size_t OFF_Y1L   = OFF_Y1M   + 2097152;
constexpr size_t OFF_Y1H   = OFF_Y1L   + 2097152;
constexpr size_t OFF_Y2M   = OFF_Y1H   + 524288;
constexpr size_t OFF_Y2L   = OFF_Y2M   + 524288;
constexpr size_t OFF_SUMF0 = OFF_Y2L   + 524288;
constexpr size_t OFF_SUMF1 = OFF_SUMF0 + 8388608;
constexpr size_t OFF_SUMF2 = OFF_SUMF1 + 2097152;
constexpr size_t OFF_W3MID = OFF_SUMF2 + 524288;        // half[9*256*256]
constexpr size_t OFF_W3LOW = OFF_W3MID + 589824;
constexpr size_t OFF_W3HIGH= OFF_W3LOW + 589824;
constexpr size_t OFF_W3OFF = OFF_W3HIGH+ 589824;        // half[9*32*256]
constexpr size_t OFF_STAT  = OFF_W3OFF + 73728;         // 3 lvl x 3 br x 1024
constexpr size_t OFF_GNM   = OFF_STAT  + 9216;          // 3 lvl x 96
constexpr size_t OFF_GNR   = OFF_GNM   + 288;
constexpr size_t OFF_SV    = OFF_GNR   + 288;           // 3 lvl x 8
constexpr size_t OFF_P2    = OFF_SV    + 24;            // 3 lvl x 512
constexpr size_t OFF_COEF  = OFF_P2    + 1536;          // 3 lvl x 2048
constexpr size_t SCRATCH_TOTAL = OFF_COEF + 6144;

// floats to zero each replay: STAT(9216)+GNM(288)+GNR(288)+SV(24)+P2(1536)
constexpr int ZERO_SPAN = 11352;

__device__ __align__(256) float g_scratch[SCRATCH_TOTAL];

// mdconv (PX=64) dynamic smem layout (bytes):
//   Ash : half [2][64*40]   at 0      (10240)
//   Bsh : half [3][256*40]  at 10240  (61440)
//   swt9: float[9][256]     at 71680  (9216)
//   sb9 : int  [9][256]     at 80896  (9216)
constexpr int MD_SMEM_BYTES = 90112;

// ---- descriptor table for the batched mdconv super-launch ----
struct MDDesc {
    unsigned long long xn_o, off_o, w3_o, y_o, stat_o;
    int Hi, Wi, offH, offW, offmul, stride, HWo, Wo, tile_end;
};
__constant__ MDDesc g_md[7] = {
    // mid0: 256 tiles
    {OFF_X0N, OFF_OFFB0, OFF_W3MID, OFF_Y0M, OFF_STAT,        128,128,128,128,1,1,16384,128, 256},
    // low1: 64 tiles (reads x0)
    {OFF_X0N, OFF_OFFB1, OFF_W3LOW, OFF_Y1L, OFF_STAT+4096,   128,128, 64, 64,1,2, 4096, 64, 320},
    // high0: 64 tiles (reads x1)
    {OFF_X1N, OFF_OFFB0, OFF_W3HIGH,OFF_Y0H, OFF_STAT+2048,    64, 64,128,128,2,1, 4096, 64, 384},
    // mid1: 64 tiles
    {OFF_X1N, OFF_OFFB1, OFF_W3MID, OFF_Y1M, OFF_STAT+3072,    64, 64, 64, 64,1,1, 4096, 64, 448},
    // mid2: 16 tiles
    {OFF_X2N, OFF_OFFB2, OFF_W3MID, OFF_Y2M, OFF_STAT+6144,    32, 32, 32, 32,1,1, 1024, 32, 464},
    // high1: 16 tiles (reads x2)
    {OFF_X2N, OFF_OFFB1, OFF_W3HIGH,OFF_Y1H, OFF_STAT+5120,    32, 32, 64, 64,2,1, 1024, 32, 480},
    // low2: 16 tiles (reads x1)
    {OFF_X1N, OFF_OFFB2, OFF_W3LOW, OFF_Y2L, OFF_STAT+7168,    64, 64, 32, 32,1,2, 1024, 32, 496},
};
constexpr int MD_TOTAL_TILES = 496;

// ---- descriptor table for the batched GN finalize (7 branches) ----
struct GNDesc {
    unsigned long long stat_o, gnm_o, gnr_o, sv_o;
    float inv_hw;
    int wsel;   // 0=mid, 1=low, 2=high
};
__constant__ GNDesc g_gn[7] = {
    {OFF_STAT,        OFF_GNM,       OFF_GNR,       OFF_SV,      1.f/16384.f, 0},  // L0 mid
    {OFF_STAT + 2048, OFF_GNM + 64,  OFF_GNR + 64,  OFF_SV + 4,  1.f/4096.f,  2},  // L0 high
    {OFF_STAT + 3072, OFF_GNM + 96,  OFF_GNR + 96,  OFF_SV + 8,  1.f/4096.f,  0},  // L1 mid
    {OFF_STAT + 4096, OFF_GNM + 128, OFF_GNR + 128, OFF_SV + 10, 1.f/4096.f,  1},  // L1 low
    {OFF_STAT + 5120, OFF_GNM + 160, OFF_GNR + 160, OFF_SV + 12, 1.f/1024.f,  2},  // L1 high
    {OFF_STAT + 6144, OFF_GNM + 192, OFF_GNR + 192, OFF_SV + 16, 1.f/1024.f,  0},  // L2 mid
    {OFF_STAT + 7168, OFF_GNM + 224, OFF_GNR + 224, OFF_SV + 18, 1.f/1024.f,  1},  // L2 low
};

__device__ __forceinline__ void mma_f16(float* d, const uint32_t* a, uint32_t b0, uint32_t b1) {
    asm volatile(
        "mma.sync.aligned.m16n8k16.row.col.f32.f16.f16.f32 "
        "{%0,%1,%2,%3},{%4,%5,%6,%7},{%8,%9},{%0,%1,%2,%3};\n"
        : "+f"(d[0]), "+f"(d[1]), "+f"(d[2]), "+f"(d[3])
        : "r"(a[0]), "r"(a[1]), "r"(a[2]), "r"(a[3]), "r"(b0), "r"(b1));
}

__device__ __forceinline__ void ldsm_x4(uint32_t* r, const half* p) {
    uint32_t a = (uint32_t)__cvta_generic_to_shared(p);
    asm volatile("ldmatrix.sync.aligned.m8n8.x4.shared.b16 {%0,%1,%2,%3}, [%4];"
        : "=r"(r[0]), "=r"(r[1]), "=r"(r[2]), "=r"(r[3]) : "r"(a));
}

__device__ __forceinline__ void cp_async16(uint32_t daddr, const void* src) {
    asm volatile("cp.async.cg.shared.global [%0], [%1], 16;\n" :: "r"(daddr), "l"(src));
}

// ---------------------------------------------------------------------------
// root: tiny first node so side streams can fork before any heavy work.
// ---------------------------------------------------------------------------
__global__ void root_kernel() {
    if (threadIdx.x == 0) g_scratch[OFF_SV] = 0.f;
}

// ---------------------------------------------------------------------------
// prep: w_mid -> half [k][o][c], w_off -> half [k][o32][c], zero accumulators.
// ---------------------------------------------------------------------------
__global__ void prep_kernel(const float* __restrict__ w_mid, const float* __restrict__ w_off) {
    int bidx = blockIdx.x;
    if (bidx < 2304) {
        int idx = bidx * 256 + threadIdx.x;           // < 9*256*256
        int k = idx >> 16, o = (idx >> 8) & 255, c = idx & 255;
        ((half*)(g_scratch + OFF_W3MID))[idx] = __float2half(w_mid[(o * 256 + c) * 9 + k]);
    } else if (bidx < 2592) {
        int idx = (bidx - 2304) * 256 + threadIdx.x;  // < 9*32*256
        int k = idx >> 13, o = (idx >> 8) & 31, c = idx & 255;
        ((half*)(g_scratch + OFF_W3OFF))[idx] =
            __float2half(o < 27 ? w_off[(o * 256 + c) * 9 + k] : 0.f);
    } else {
        int idx = (bidx - 2592) * 256 + threadIdx.x;
        if (idx < ZERO_SPAN) g_scratch[OFF_STAT + idx] = 0.f;  // stats..P2 inclusive
    }
}

__global__ void reorder_w_half_kernel(const float* __restrict__ w, size_t out_o) {
    int idx = blockIdx.x * 256 + threadIdx.x;         // < 9*256*256
    int k = idx >> 16, o = (idx >> 8) & 255, c = idx & 255;
    ((half*)(g_scratch + out_o))[idx] = __float2half(w[(o * 256 + c) * 9 + k]);
}

// ---------------------------------------------------------------------------
// NCHW fp32 -> NHWC fp16 transpose.
// ---------------------------------------------------------------------------
__global__ void transpose_kernel(const float* __restrict__ in, size_t out_o, int HW) {
    __shared__ float t[32][33];
    int b = blockIdx.z;
    int hw0 = blockIdx.x * 32, c0 = blockIdx.y * 32;
    int tx = threadIdx.x, ty = threadIdx.y;  // 32 x 8
    #pragma unroll
    for (int i = 0; i < 32; i += 8)
        t[ty + i][tx] = in[((size_t)b * C + c0 + ty + i) * HW + hw0 + tx];
    __syncthreads();
    half* xh = (half*)(g_scratch + out_o);
    #pragma unroll
    for (int i = 0; i < 32; i += 8)
        xh[((size_t)b * HW + hw0 + ty + i) * C + c0 + tx] = __float2half(t[tx][ty + i]);
}

// ---------------------------------------------------------------------------
// Offset conv via fp16 MMA + ldmatrix. 3x3, 256 -> 27 (padded 32).
// Block: 64 px x 32 o, 256 threads (4M x 2N warps). B triple-buffered.
// ---------------------------------------------------------------------------
__global__ __launch_bounds__(256) void offconv_mma_kernel(
    size_t xn_o, int H, int W,
    const float* __restrict__ bias, size_t out_o)
{
    __shared__ half Ash[2][64 * 40];
    __shared__ half Bsh[3][32 * 40];

    int b = blockIdx.y, tile = blockIdx.x, tid = threadIdx.x;
    int lane = tid & 31, warp = tid >> 5;
    int warpM = warp >> 1, warpN = warp & 1;
    const half* xn = (const half*)(g_scratch + xn_o);
    const half* wh = (const half*)(g_scratch + OFF_W3OFF);

    float acc[2][4];
    #pragma unroll
    for (int nt = 0; nt < 2; ++nt)
        #pragma unroll
        for (int r = 0; r < 4; ++r) acc[nt][r] = 0.f;

    int tpx = tid >> 2, tseg = tid & 3;
    int p = tile * 64 + tpx;
    int ph = p / W, pw = p - ph * W;

    uint32_t bs_saddr = (uint32_t)__cvta_generic_to_shared(&Bsh[0][0]);

    uint4 gr;
    auto gather_ldg = [&](int s) {
        int k = s >> 3, c0 = (s & 7) << 5;
        int dy = k / 3 - 1, dx = k % 3 - 1;
        int y = ph + dy, x = pw + dx;
        bool valid = (y >= 0 && y < H && x >= 0 && x < W);
        const half* src = xn + ((size_t)(b * H + y) * W + x) * 256 + c0 + tseg * 8;
        gr = valid ? *(const uint4*)src : make_uint4(0, 0, 0, 0);
    };
    auto sts_a = [&](int buf) {
        *(uint4*)&Ash[buf][tpx * 40 + tseg * 8] = gr;
    };
    auto cpasync_b = [&](int s, int buf) {
        int k = s >> 3, c0 = (s & 7) << 5;
        if (tid < 128) {
            int o = tid >> 2, seg = tid & 3;
            cp_async16(bs_saddr + (uint32_t)(buf * 2560 + o * 80 + seg * 16),
                       wh + ((size_t)(k * 32 + o) << 8) + c0 + seg * 8);
        }
        asm volatile("cp.async.commit_group;\n");
    };

    gather_ldg(0);
    cpasync_b(0, 0);
    cpasync_b(1, 1);

    int lg = lane >> 3, lr = lane & 7;
    int bufB = 0, slot2 = 2;

    for (int s = 0; s < 72; ++s) {
        int cb = s & 1;
        sts_a(cb);
        if (s < 71) gather_ldg(s + 1);
        if (s < 71) asm volatile("cp.async.wait_group 1;\n");
        else        asm volatile("cp.async.wait_group 0;\n");
        __syncthreads();
        if (s < 70) cpasync_b(s + 2, slot2);

        const half* Ab = Ash[cb];
        const half* Bb = Bsh[bufB];
        #pragma unroll
        for (int ks = 0; ks < 2; ++ks) {
            int kb = ks * 16 + (lg >> 1) * 8;
            uint32_t a[4];
            ldsm_x4(a, Ab + (warpM * 16 + (lg & 1) * 8 + lr) * 40 + kb);
            uint32_t bf[4];
            ldsm_x4(bf, Bb + (warpN * 16 + (lg & 1) * 8 + lr) * 40 + kb);
            mma_f16(acc[0], a, bf[0], bf[2]);
            mma_f16(acc[1], a, bf[1], bf[3]);
        }
        __syncthreads();
        bufB = (bufB == 2) ? 0 : bufB + 1;
        slot2 = (slot2 == 2) ? 0 : slot2 + 1;
    }

    // epilogue: [b][px][27]
    int HWl = H * W;
    int pxb = tile * 64 + warpM * 16 + (lane >> 2);
    #pragma unroll
    for (int nt = 0; nt < 2; ++nt) {
        int o = warpN * 16 + nt * 8 + 2 * (lane & 3);
        float bv0 = (o < 27) ? bias[o] : 0.f;
        float bv1 = (o + 1 < 27) ? bias[o + 1] : 0.f;
        #pragma unroll
        for (int rr = 0; rr < 2; ++rr) {
            int px = pxb + rr * 8;
            float v0 = acc[nt][rr * 2 + 0] + bv0;
            float v1 = acc[nt][rr * 2 + 1] + bv1;
            size_t ob = out_o + ((size_t)b * HWl + px) * 27;
            if (o < 27) {
                if (o >= 18) v0 = 1.f / (1.f + expf(-v0));
                g_scratch[ob + o] = v0;
            }
            if (o + 1 < 27) {
                if (o + 1 >= 18) v1 = 1.f / (1.f + expf(-v1));
                g_scratch[ob + o + 1] = v1;
            }
        }
    }
}

// ---------------------------------------------------------------------------
// Batched modulated deformable conv: one launch covers ALL seven convs via
// the __constant__ descriptor table. Block: 64 px x 256 o, 256 threads,
// 2 blocks/SM. Fused per-(b,c) stats.
// ---------------------------------------------------------------------------
__global__ __launch_bounds__(256, 2) void mdconv_super_kernel() {
    constexpr int PX = 64;
    constexpr int ASH_HALF = PX * 40;

    extern __shared__ char smraw[];
    half*  Ash  = (half*)smraw;               // [2][64*40]
    half*  Bsh  = (half*)(smraw + 10240);     // [3][256*40]
    float* swt9 = (float*)(smraw + 71680);    // [9][4*64]
    int*   sb9  = (int*)(smraw + 80896);      // [9][4*64]

    // descriptor lookup
    int ci = 0;
    {
        int t = blockIdx.x;
        while (t >= g_md[ci].tile_end) ci++;
    }
    const MDDesc d = g_md[ci];
    int tile = blockIdx.x - (ci ? g_md[ci - 1].tile_end : 0);
    int Hi = d.Hi, Wi = d.Wi, offH = d.offH, offW = d.offW;
    int offmul = d.offmul, stride = d.stride, HWo = d.HWo, Wo = d.Wo;

    int b = blockIdx.y, tid = threadIdx.x;
    int lane = tid & 31, warp = tid >> 5;
    int warpM = warp & 1, warpN = warp >> 1;

    const half* xn = (const half*)(g_scratch + d.xn_o);
    const half* w3h = (const half*)(g_scratch + d.w3_o);
    size_t off_o = d.off_o;

    // precompute gather tables for all 9 taps
    for (int it = tid; it < 9 * PX; it += 256) {
        int k = it >> 6, p = it & 63;
        int pg = tile * PX + p;
        int h = pg / Wo, w = pg - h * Wo;
        size_t ob = off_o + ((size_t)(b * offH + h * offmul) * offW + w * offmul) * 27;
        float oy = g_scratch[ob + 2 * k];
        float ox = g_scratch[ob + 2 * k + 1];
        float m  = g_scratch[ob + 18 + k];
        float py  = (float)(h * stride - 1 + k / 3) + oy;
        float pxx = (float)(w * stride - 1 + k % 3) + ox;
        float fy = floorf(py), fx = floorf(pxx);
        int y0 = (int)fy, x0 = (int)fx;
        float wy = py - fy, wx = pxx - fx;
        int y1 = y0 + 1, x1 = x0 + 1;
        float vy0 = (y0 >= 0 && y0 < Hi) ? 1.f : 0.f;
        float vy1 = (y1 >= 0 && y1 < Hi) ? 1.f : 0.f;
        float vx0 = (x0 >= 0 && x0 < Wi) ? 1.f : 0.f;
        float vx1 = (x1 >= 0 && x1 < Wi) ? 1.f : 0.f;
        int y0c = min(max(y0, 0), Hi - 1), y1c = min(max(y1, 0), Hi - 1);
        int x0c = min(max(x0, 0), Wi - 1), x1c = min(max(x1, 0), Wi - 1);
        int kb = k * 4 * PX + p;
        swt9[kb]          = (1.f - wy) * (1.f - wx) * m * vy0 * vx0;
        swt9[kb + PX]     = (1.f - wy) * wx * m * vy0 * vx1;
        swt9[kb + 2 * PX] = wy * (1.f - wx) * m * vy1 * vx0;
        swt9[kb + 3 * PX] = wy * wx * m * vy1 * vx1;
        sb9[kb]          = ((b * Hi + y0c) * Wi + x0c) * 256;
        sb9[kb + PX]     = ((b * Hi + y0c) * Wi + x1c) * 256;
        sb9[kb + 2 * PX] = ((b * Hi + y1c) * Wi + x0c) * 256;
        sb9[kb + 3 * PX] = ((b * Hi + y1c) * Wi + x1c) * 256;
    }
    __syncthreads();

    float acc[2][8][4];
    #pragma unroll
    for (int mt = 0; mt < 2; ++mt)
        #pragma unroll
        for (int nt = 0; nt < 8; ++nt)
            #pragma unroll
            for (int r = 0; r < 4; ++r) acc[mt][nt][r] = 0.f;

    int gpx = tid >> 2;   // 0..63
    int gcq = tid & 3;    // 16B segment

    uint32_t bs_saddr = (uint32_t)__cvta_generic_to_shared(Bsh);

    float gw0, gw1, gw2, gw3;
    int b00, b01, b10, b11;
    uint4 gv[4];

    auto load_table = [&](int kk) {
        int kb = kk * 4 * PX + gpx;
        gw0 = swt9[kb]; gw1 = swt9[kb + PX]; gw2 = swt9[kb + 2 * PX]; gw3 = swt9[kb + 3 * PX];
        b00 = sb9[kb];  b01 = sb9[kb + PX];  b10 = sb9[kb + 2 * PX]; b11 = sb9[kb + 3 * PX];
    };
    auto gather_ldg = [&](int s) {
        int cofs = ((s & 7) << 5) + gcq * 8;
        gv[0] = *(const uint4*)(xn + b00 + cofs);
        gv[1] = *(const uint4*)(xn + b01 + cofs);
        gv[2] = *(const uint4*)(xn + b10 + cofs);
        gv[3] = *(const uint4*)(xn + b11 + cofs);
    };
    auto combine_sts = [&](int buf) {
        uint4 outv;
        half2* po = (half2*)&outv;
        #pragma unroll
        for (int j = 0; j < 4; ++j) {
            float2 f00 = __half22float2(((const half2*)&gv[0])[j]);
            float2 f01 = __half22float2(((const half2*)&gv[1])[j]);
            float2 f10 = __half22float2(((const half2*)&gv[2])[j]);
            float2 f11 = __half22float2(((const half2*)&gv[3])[j]);
            float rx = gw0 * f00.x + gw1 * f01.x + gw2 * f10.x + gw3 * f11.x;
            float ry = gw0 * f00.y + gw1 * f01.y + gw2 * f10.y + gw3 * f11.y;
            po[j] = __floats2half2_rn(rx, ry);
        }
        *(uint4*)&Ash[buf * ASH_HALF + gpx * 40 + gcq * 8] = outv;
    };
    auto cpasync_b = [&](int s, int buf) {
        int kk = s >> 3, c0n = (s & 7) << 5;
        const half* wsrc = w3h + ((size_t)kk << 16) + c0n;   // [k][o][c], row = 256 halves
        #pragma unroll
        for (int it = 0; it < 4; ++it) {
            int e = it * 256 + tid;
            int o = e >> 2, seg = e & 3;
            cp_async16(bs_saddr + (uint32_t)(buf * 20480 + o * 80 + seg * 16),
                       wsrc + o * 256 + seg * 8);
        }
        asm volatile("cp.async.commit_group;\n");
    };

    load_table(0);
    gather_ldg(0);
    cpasync_b(0, 0);
    cpasync_b(1, 1);

    int lg = lane >> 3, lr = lane & 7;
    int bufB = 0, slot2 = 2;

    for (int s = 0; s < 72; ++s) {
        int cb = s & 1;
        combine_sts(cb);
        if (s < 71) {
            if (((s + 1) & 7) == 0) load_table((s + 1) >> 3);
            gather_ldg(s + 1);
        }
        if (s < 71) asm volatile("cp.async.wait_group 1;\n");
        else        asm volatile("cp.async.wait_group 0;\n");
        __syncthreads();
        if (s < 70) cpasync_b(s + 2, slot2);

        const half* Ab = Ash + cb * ASH_HALF;
        const half* Bb = Bsh + bufB * 10240;
        #pragma unroll
        for (int ks = 0; ks < 2; ++ks) {
            int kb = ks * 16 + (lg >> 1) * 8;
            uint32_t a[2][4];
            #pragma unroll
            for (int mt = 0; mt < 2; ++mt)
                ldsm_x4(a[mt], Ab + (warpM * 32 + mt * 16 + (lg & 1) * 8 + lr) * 40 + kb);
            #pragma unroll
            for (int j = 0; j < 4; ++j) {
                uint32_t bf[4];
                ldsm_x4(bf, Bb + (warpN * 64 + j * 16 + (lg & 1) * 8 + lr) * 40 + kb);
                mma_f16(acc[0][2 * j],     a[0], bf[0], bf[2]);
                mma_f16(acc[1][2 * j],     a[1], bf[0], bf[2]);
                mma_f16(acc[0][2 * j + 1], a[0], bf[1], bf[3]);
                mma_f16(acc[1][2 * j + 1], a[1], bf[1], bf[3]);
            }
        }
        bufB = (bufB == 2) ? 0 : bufB + 1;
        slot2 = (slot2 == 2) ? 0 : slot2 + 1;
    }

    // epilogue: Y [b][o][HWo] + fused stats
    float* yp = g_scratch + d.y_o + (size_t)b * 256 * HWo;
    float* st_sum = g_scratch + d.stat_o + b * 256;
    float* st_sq  = g_scratch + d.stat_o + 512 + b * 256;
    int px0 = tile * PX + warpM * 32 + (lane >> 2);
    #pragma unroll
    for (int nt = 0; nt < 8; ++nt) {
        int o = warpN * 64 + nt * 8 + 2 * (lane & 3);
        float s0 = 0.f, s1 = 0.f, q0 = 0.f, q1 = 0.f;
        #pragma unroll
        for (int mt = 0; mt < 2; ++mt) {
            int px = px0 + mt * 16;
            float v0 = acc[mt][nt][0], v1 = acc[mt][nt][1];
            float v2 = acc[mt][nt][2], v3 = acc[mt][nt][3];
            yp[(size_t)o * HWo + px]           = v0;
            yp[(size_t)(o + 1) * HWo + px]     = v1;
            yp[(size_t)o * HWo + px + 8]       = v2;
            yp[(size_t)(o + 1) * HWo + px + 8] = v3;
            s0 += v0 + v2; s1 += v1 + v3;
            q0 += v0 * v0 + v2 * v2; q1 += v1 * v1 + v3 * v3;
        }
        #pragma unroll
        for (int off = 16; off >= 4; off >>= 1) {
            s0 += __shfl_down_sync(0xffffffffu, s0, off);
            s1 += __shfl_down_sync(0xffffffffu, s1, off);
            q0 += __shfl_down_sync(0xffffffffu, q0, off);
            q1 += __shfl_down_sync(0xffffffffu, q1, off);
        }
        if (lane < 4) {
            atomicAdd(&st_sum[o], s0);
            atomicAdd(&st_sum[o + 1], s1);
            atomicAdd(&st_sq[o], q0);
            atomicAdd(&st_sq[o + 1], q1);
        }
    }
}

// ---------------------------------------------------------------------------
// Batched GN finalize: 7 branches x 2 batch = 14 blocks.
// ---------------------------------------------------------------------------
__global__ void gn_all_kernel(
    const float* __restrict__ g_mid, const float* __restrict__ be_mid,
    const float* __restrict__ g_low, const float* __restrict__ be_low,
    const float* __restrict__ g_high, const float* __restrict__ be_high,
    const float* __restrict__ w_sa, const float* __restrict__ b_sa)
{
    int br = blockIdx.x >> 1, b = blockIdx.x & 1, t = threadIdx.x;  // 256 thr
    const GNDesc d = g_gn[br];
    const float* gamma = (d.wsel == 0) ? g_mid : (d.wsel == 1) ? g_low : g_high;
    const float* beta  = (d.wsel == 0) ? be_mid : (d.wsel == 1) ? be_low : be_high;
    float inv_hw = d.inv_hw, inv_cnt = d.inv_hw / 16.f;

    __shared__ float ss[256], qq[256], gm[16], gr[16], red[256];
    ss[t] = g_scratch[d.stat_o + b * 256 + t];
    qq[t] = g_scratch[d.stat_o + 512 + b * 256 + t];
    __syncthreads();
    if (t < 16) {
        float S = 0.f, Q = 0.f;
        #pragma unroll
        for (int j = 0; j < 16; ++j) { S += ss[t * 16 + j]; Q += qq[t * 16 + j]; }
        float mean = S * inv_cnt;
        float var = Q * inv_cnt - mean * mean;
        float r = rsqrtf(var + 1e-5f);
        gm[t] = mean; gr[t] = r;
        g_scratch[d.gnm_o + b * 16 + t] = mean;
        g_scratch[d.gnr_o + b * 16 + t] = r;
    }
    __syncthreads();
    int g = t >> 4;
    float p = gamma[t] * (ss[t] * inv_hw - gm[g]) * gr[g] + beta[t];
    red[t] = p * w_sa[t];
    __syncthreads();
    for (int off = 128; off; off >>= 1) {
        if (t < off) red[t] += red[t + off];
        __syncthreads();
    }
    if (t == 0) {
        float x = fmaxf(red[0] + b_sa[0], 0.f);
        g_scratch[d.sv_o + b] = fminf(x + 3.f, 6.f) * (1.f / 6.f);
    }
}

// ---------------------------------------------------------------------------
// Combine branches + pooled sums.
// ---------------------------------------------------------------------------
__global__ void combine_kernel(
    size_t ymid_o, size_t ylow_o, size_t yhigh_o,
    int hasLow, int hasHigh, int W, int HW, int Hh, int Wh, float ry, float rx,
    size_t gnm_o, size_t gnr_o, size_t sv_o,
    const float* __restrict__ gw_mid, const float* __restrict__ gb_mid,
    const float* __restrict__ gw_low, const float* __restrict__ gb_low,
    const float* __restrict__ gw_high, const float* __restrict__ gb_high,
    float inv_n, size_t sumf_o, size_t p2_o)
{
    int b = blockIdx.z, c = blockIdx.y;
    int px = blockIdx.x * 256 + threadIdx.x;
    int g = c >> 4;
    int gi = b * 16 + g;
    size_t base = ((size_t)(b * 256 + c)) * HW;

    float v = g_scratch[sv_o + b] *
              (gw_mid[c] * (g_scratch[ymid_o + base + px] - g_scratch[gnm_o + gi]) * g_scratch[gnr_o + gi] + gb_mid[c]);
    if (hasLow)
        v += g_scratch[sv_o + 2 + b] *
             (gw_low[c] * (g_scratch[ylow_o + base + px] - g_scratch[gnm_o + 32 + gi]) * g_scratch[gnr_o + 32 + gi] + gb_low[c]);
    if (hasHigh) {
        int h = px / W, w = px - h * W;
        float sy = h * ry, sx = w * rx;
        int yl = (int)sy; int yh2 = min(yl + 1, Hh - 1);
        int xl = (int)sx; int xh = min(xl + 1, Wh - 1);
        float wy = sy - (float)yl, wx = sx - (float)xl;
        const float* hp = g_scratch + yhigh_o + ((size_t)(b * 256 + c)) * Hh * Wh;
        float t0 = hp[yl * Wh + xl] * (1.f - wx) + hp[yl * Wh + xh] * wx;
        float t1 = hp[yh2 * Wh + xl] * (1.f - wx) + hp[yh2 * Wh + xh] * wx;
        float raw = t0 * (1.f - wy) + t1 * wy;
        v += g_scratch[sv_o + 4 + b] *
             (gw_high[c] * (raw - g_scratch[gnm_o + 64 + gi]) * g_scratch[gnr_o + 64 + gi] + gb_high[c]);
    }
    v *= inv_n;
    g_scratch[sumf_o + base + px] = v;

    float r = v;
    #pragma unroll
    for (int o = 16; o; o >>= 1) r += __shfl_down_sync(0xffffffffu, r, o);
    __shared__ float wsum[8];
    if ((threadIdx.x & 31) == 0) wsum[threadIdx.x >> 5] = r;
    __syncthreads();
    if (threadIdx.x == 0) {
        float tt = 0.f;
        #pragma unroll
        for (int i = 0; i < 8; ++i) tt += wsum[i];
        atomicAdd(&g_scratch[p2_o + b * 256 + c], tt);
    }
}

// ---------------------------------------------------------------------------
// DyReLU coefficients.
// ---------------------------------------------------------------------------
__global__ void dycoef_kernel(size_t p2_o, float inv_hw,
    const float* __restrict__ w1, const float* __restrict__ b1,
    const float* __restrict__ w2, const float* __restrict__ b2,
    size_t coef_o)
{
    int b = blockIdx.x, t = threadIdx.x;  // 1024
    __shared__ float pm[256], hb[64];
    if (t < 256) pm[t] = g_scratch[p2_o + b * 256 + t] * inv_hw;
    __syncthreads();
    if (t < 64) {
        float a = b1[t];
        for (int cx = 0; cx < 256; ++cx) a += pm[cx] * w1[t * 256 + cx];
        hb[t] = fmaxf(a, 0.f);
    }
    __syncthreads();
    float a = b2[t];
    #pragma unroll
    for (int i = 0; i < 64; ++i) a += hb[i] * w2[t * 64 + i];
    float hs = fminf(fmaxf(a + 3.f, 0.f), 6.f) * (1.f / 6.f);
    g_scratch[coef_o + b * 1024 + t] = hs - 0.5f;
}

// ---------------------------------------------------------------------------
// Apply DyReLU, write final output.
// ---------------------------------------------------------------------------
__global__ void dyrelu_kernel(size_t sumf_o, size_t coef_o, int HW, float* __restrict__ outp, int CHW) {
    int idx = blockIdx.x * 256 + threadIdx.x;
    int b = idx / CHW;
    int c = (idx - b * CHW) / HW;
    const float* cf = g_scratch + coef_o + b * 1024;
    float x = g_scratch[sumf_o + idx];
    float a1 = cf[c] * 2.f + 1.f, bb1 = cf[256 + c];
    float a2 = cf[512 + c] * 2.f, bb2 = cf[768 + c];
    outp[idx] = fmaxf(x * a1 + bb1, x * a2 + bb2);
}

// ---------------------------------------------------------------------------
// Host orchestration: 3 streams. Pre-work fans out, joins into ONE batched
// mdconv super-launch, then batched GN, then per-level tails on 3 streams.
// ---------------------------------------------------------------------------
extern "C" void kernel_launch(void* const* d_in, const int* in_sizes, int n_in,
                              void* d_out, int out_size) {
    (void)in_sizes; (void)n_in; (void)out_size;
    const float* x0     = (const float*)d_in[0];
    const float* x1     = (const float*)d_in[1];
    const float* x2     = (const float*)d_in[2];
    const float* w_off  = (const float*)d_in[3];
    const float* b_off  = (const float*)d_in[4];
    const float* w_mid  = (const float*)d_in[5];
    const float* g_mid  = (const float*)d_in[6];
    const float* be_mid = (const float*)d_in[7];
    const float* w_low  = (const float*)d_in[8];
    const float* g_low  = (const float*)d_in[9];
    const float* be_low = (const float*)d_in[10];
    const float* w_high = (const float*)d_in[11];
    const float* g_high = (const float*)d_in[12];
    const float* be_high= (const float*)d_in[13];
    const float* w_sa   = (const float*)d_in[14];
    const float* b_sa   = (const float*)d_in[15];
    const float* w_dy1  = (const float*)d_in[16];
    const float* b_dy1  = (const float*)d_in[17];
    const float* w_dy2  = (const float*)d_in[18];
    const float* b_dy2  = (const float*)d_in[19];
    float* out = (float*)d_out;

    static cudaStream_t s1, s2;
    static cudaEvent_t evRoot, evPrep, evOff1, evOff2, evGN, evL1, evL2;
    static bool inited = false;
    if (!inited) {
        cudaFuncSetAttribute(mdconv_super_kernel,
                             cudaFuncAttributeMaxDynamicSharedMemorySize, MD_SMEM_BYTES);
        cudaStreamCreateWithFlags(&s1, cudaStreamNonBlocking);
        cudaStreamCreateWithFlags(&s2, cudaStreamNonBlocking);
        cudaEvent_t* evs[] = {&evRoot, &evPrep, &evOff1, &evOff2, &evGN, &evL1, &evL2};
        for (auto e : evs) cudaEventCreateWithFlags(e, cudaEventDisableTiming);
        inited = true;
    }

    dim3 tblk(32, 8);
    const float inv16k = 1.f / 16384.f, inv4k = 1.f / 4096.f, inv1k = 1.f / 1024.f;

    // ---- fork
    root_kernel<<<1, 32>>>();
    cudaEventRecord(evRoot, 0);
    cudaStreamWaitEvent(s1, evRoot, 0);
    cudaStreamWaitEvent(s2, evRoot, 0);

    // ---- main: T0 then off0
    transpose_kernel<<<dim3(512, 8, 2), tblk>>>(x0, OFF_X0N, 16384);
    // ---- s2: prep + T2 + reorder_whigh + off2
    prep_kernel<<<2637, 256, 0, s2>>>(w_mid, w_off);
    cudaEventRecord(evPrep, s2);
    transpose_kernel<<<dim3(32, 8, 2), tblk, 0, s2>>>(x2, OFF_X2N, 1024);
    reorder_w_half_kernel<<<2304, 256, 0, s2>>>(w_high, OFF_W3HIGH);
    offconv_mma_kernel<<<dim3(16, 2), 256, 0, s2>>>(OFF_X2N, 32, 32, b_off, OFF_OFFB2);
    cudaEventRecord(evOff2, s2);
    // ---- s1: T1 + reorder_wlow + off1
    transpose_kernel<<<dim3(128, 8, 2), tblk, 0, s1>>>(x1, OFF_X1N, 4096);
    reorder_w_half_kernel<<<2304, 256, 0, s1>>>(w_low, OFF_W3LOW);
    cudaStreamWaitEvent(s1, evPrep, 0);
    offconv_mma_kernel<<<dim3(64, 2), 256, 0, s1>>>(OFF_X1N, 64, 64, b_off, OFF_OFFB1);
    cudaEventRecord(evOff1, s1);
    // ---- main: off0 (needs prep), then join all and run the super-launch
    cudaStreamWaitEvent(0, evPrep, 0);
    offconv_mma_kernel<<<dim3(256, 2), 256>>>(OFF_X0N, 128, 128, b_off, OFF_OFFB0);
    cudaStreamWaitEvent(0, evOff1, 0);
    cudaStreamWaitEvent(0, evOff2, 0);
    mdconv_super_kernel<<<dim3(MD_TOTAL_TILES, 2), 256, MD_SMEM_BYTES>>>();
    gn_all_kernel<<<14, 256>>>(g_mid, be_mid, g_low, be_low, g_high, be_high, w_sa, b_sa);
    cudaEventRecord(evGN, 0);

    // ---- s1: L1 tail
    cudaStreamWaitEvent(s1, evGN, 0);
    {
        float ry = 31.f / 63.f;
        combine_kernel<<<dim3(16, 256, 2), 256, 0, s1>>>(
            OFF_Y1M, OFF_Y1L, OFF_Y1H, 1, 1, 64, 4096, 32, 32, ry, ry,
            OFF_GNM + 96, OFF_GNR + 96, OFF_SV + 8,
            g_mid, be_mid, g_low, be_low, g_high, be_high,
            1.f / 3.f, OFF_SUMF1, OFF_P2 + 512);
        dycoef_kernel<<<2, 1024, 0, s1>>>(OFF_P2 + 512, inv4k, w_dy1, b_dy1, w_dy2, b_dy2,
                                          OFF_COEF + 2048);
        dyrelu_kernel<<<2 * 256 * 4096 / 256, 256, 0, s1>>>(OFF_SUMF1, OFF_COEF + 2048, 4096,
                                                            out + 2 * 256 * 16384, 256 * 4096);
    }
    cudaEventRecord(evL1, s1);

    // ---- s2: L2 tail
    cudaStreamWaitEvent(s2, evGN, 0);
    {
        combine_kernel<<<dim3(4, 256, 2), 256, 0, s2>>>(
            OFF_Y2M, OFF_Y2L, 0, 1, 0, 32, 1024, 16, 16, 0.f, 0.f,
            OFF_GNM + 192, OFF_GNR + 192, OFF_SV + 16,
            g_mid, be_mid, g_low, be_low, g_high, be_high,
            0.5f, OFF_SUMF2, OFF_P2 + 1024);
        dycoef_kernel<<<2, 1024, 0, s2>>>(OFF_P2 + 1024, inv1k, w_dy1, b_dy1, w_dy2, b_dy2,
                                          OFF_COEF + 4096);
        dyrelu_kernel<<<2 * 256 * 1024 / 256, 256, 0, s2>>>(OFF_SUMF2, OFF_COEF + 4096, 1024,
                                                            out + 2 * 256 * (16384 + 4096), 256 * 1024);
    }
    cudaEventRecord(evL2, s2);

    // ---- main: L0 tail, join everything, final dyrelu0
    {
        float ry = 63.f / 127.f;
        combine_kernel<<<dim3(64, 256, 2), 256>>>(
            OFF_Y0M, 0, OFF_Y0H, 0, 1, 128, 16384, 64, 64, ry, ry,
            OFF_GNM, OFF_GNR, OFF_SV,
            g_mid, be_mid, g_low, be_low, g_high, be_high,
            0.5f, OFF_SUMF0, OFF_P2);
        dycoef_kernel<<<2, 1024>>>(OFF_P2, inv16k, w_dy1, b_dy1, w_dy2, b_dy2, OFF_COEF);
    }
    cudaStreamWaitEvent(0, evL1, 0);
    cudaStreamWaitEvent(0, evL2, 0);
    dyrelu_kernel<<<2 * 256 * 16384 / 256, 256>>>(OFF_SUMF0, OFF_COEF, 16384, out, 256 * 16384);
}